// round 1
// baseline (speedup 1.0000x reference)
#include <cuda_runtime.h>
#include <math.h>

#define BB 2
#define NTOK 4096
#define DM 768
#define NH 12
#define DHEAD 64
#define NBLK 64
#define BS 64
#define FFD 3072
#define NL 2
#define RR 3

// ---------------- scratch (device globals; no allocation) ----------------
__device__ float g_x[BB * NTOK * DM];
__device__ float g_q[BB * NTOK * DM];
__device__ float g_k[BB * NTOK * DM];
__device__ float g_v[BB * NTOK * DM];
__device__ float g_ctx[BB * NTOK * DM];
__device__ float g_t[BB * NTOK * DM];
__device__ float g_a[BB * NTOK * DM];
__device__ float g_h[BB * NTOK * FFD];
__device__ float g_part[BB * 32];

// ---------------- block reduce (sum of two values) ----------------
__device__ __forceinline__ void block_reduce2(float& s, float& s2) {
#pragma unroll
    for (int off = 16; off > 0; off >>= 1) {
        s  += __shfl_down_sync(0xffffffffu, s, off);
        s2 += __shfl_down_sync(0xffffffffu, s2, off);
    }
    __shared__ float sh[16];
    int w = threadIdx.x >> 5, lane = threadIdx.x & 31;
    if (lane == 0) { sh[w] = s; sh[8 + w] = s2; }
    __syncthreads();
    if (threadIdx.x == 0) {
        float a = 0.f, b = 0.f;
#pragma unroll
        for (int i = 0; i < 8; i++) { a += sh[i]; b += sh[8 + i]; }
        sh[0] = a; sh[8] = b;
    }
    __syncthreads();
    s = sh[0]; s2 = sh[8];
}

// ---------------- embedding + LayerNorm ----------------
__global__ __launch_bounds__(256) void embed_ln_kernel(
    const float* __restrict__ e, const float* __restrict__ pos,
    const float* __restrict__ tt, const float* __restrict__ g,
    const float* __restrict__ bta, float* __restrict__ out)
{
    int row = blockIdx.x;
    int n = row & (NTOK - 1);
    size_t base = (size_t)row * DM;
    float v[3]; float s = 0.f, s2 = 0.f;
#pragma unroll
    for (int i = 0; i < 3; i++) {
        int d = threadIdx.x + i * 256;
        float val = e[base + d] + pos[(size_t)n * DM + d] + tt[d];
        v[i] = val; s += val; s2 += val * val;
    }
    block_reduce2(s, s2);
    float mean = s * (1.f / DM);
    float var = s2 * (1.f / DM) - mean * mean;
    float rstd = rsqrtf(var + 1e-12f);
#pragma unroll
    for (int i = 0; i < 3; i++) {
        int d = threadIdx.x + i * 256;
        out[base + d] = (v[i] - mean) * rstd * g[d] + bta[d];
    }
}

// ---------------- residual add + LayerNorm ----------------
__global__ __launch_bounds__(256) void ln_add_kernel(
    const float* __restrict__ r, const float* __restrict__ y,
    const float* __restrict__ g, const float* __restrict__ bta,
    float* __restrict__ out)
{
    int row = blockIdx.x;
    size_t base = (size_t)row * DM;
    float v[3]; float s = 0.f, s2 = 0.f;
#pragma unroll
    for (int i = 0; i < 3; i++) {
        int d = threadIdx.x + i * 256;
        float val = r[base + d] + y[base + d];
        v[i] = val; s += val; s2 += val * val;
    }
    block_reduce2(s, s2);
    float mean = s * (1.f / DM);
    float var = s2 * (1.f / DM) - mean * mean;
    float rstd = rsqrtf(var + 1e-12f);
#pragma unroll
    for (int i = 0; i < 3; i++) {
        int d = threadIdx.x + i * 256;
        out[base + d] = (v[i] - mean) * rstd * g[d] + bta[d];
    }
}

// ---------------- SGEMM: C = A(MxK) @ W(KxN) + bias, optional GELU ----------------
// M,N,K all multiples of 128/128/16 in this problem (768, 3072, 8192).
template<int GELU>
__global__ __launch_bounds__(256) void sgemm_kernel(
    const float* __restrict__ A, const float* __restrict__ Bw,
    const float* __restrict__ bias, float* __restrict__ C,
    int M, int Nn, int K)
{
    __shared__ float As[16][132];
    __shared__ float Bs[16][128];
    int tid = threadIdx.x;
    int tr = tid >> 4, tc = tid & 15;
    const float* Ap = A + (size_t)blockIdx.y * 128 * K;
    const float* Bp = Bw + blockIdx.x * 128;
    float acc[8][8];
#pragma unroll
    for (int i = 0; i < 8; i++)
#pragma unroll
        for (int j = 0; j < 8; j++) acc[i][j] = 0.f;

    for (int k0 = 0; k0 < K; k0 += 16) {
#pragma unroll
        for (int ld = 0; ld < 2; ld++) {
            int vv = tid + ld * 256;
            int r = vv >> 2, kc = (vv & 3) << 2;
            float4 av = *(const float4*)(Ap + (size_t)r * K + k0 + kc);
            As[kc][r] = av.x; As[kc + 1][r] = av.y;
            As[kc + 2][r] = av.z; As[kc + 3][r] = av.w;
        }
#pragma unroll
        for (int ld = 0; ld < 2; ld++) {
            int vv = tid + ld * 256;
            int r = vv >> 5, c = (vv & 31) << 2;
            *(float4*)&Bs[r][c] = *(const float4*)(Bp + (size_t)(k0 + r) * Nn + c);
        }
        __syncthreads();
#pragma unroll
        for (int kk = 0; kk < 16; kk++) {
            float4 a0 = *(const float4*)&As[kk][tr * 8];
            float4 a1 = *(const float4*)&As[kk][tr * 8 + 4];
            float4 b0 = *(const float4*)&Bs[kk][tc * 8];
            float4 b1 = *(const float4*)&Bs[kk][tc * 8 + 4];
            float ra[8] = {a0.x, a0.y, a0.z, a0.w, a1.x, a1.y, a1.z, a1.w};
            float rb[8] = {b0.x, b0.y, b0.z, b0.w, b1.x, b1.y, b1.z, b1.w};
#pragma unroll
            for (int i = 0; i < 8; i++)
#pragma unroll
                for (int j = 0; j < 8; j++) acc[i][j] += ra[i] * rb[j];
        }
        __syncthreads();
    }
    int gn0 = blockIdx.x * 128 + tc * 8;
#pragma unroll
    for (int i = 0; i < 8; i++) {
        size_t grow = (size_t)(blockIdx.y * 128 + tr * 8 + i) * Nn + gn0;
#pragma unroll
        for (int j = 0; j < 8; j += 4) {
            float4 o;
            float* po = (float*)&o;
#pragma unroll
            for (int jj = 0; jj < 4; jj++) {
                float val = acc[i][j + jj] + bias[gn0 + j + jj];
                if (GELU) {
                    float x3 = val * val * val;
                    val = 0.5f * val * (1.f + tanhf(0.7978845608028654f * (val + 0.044715f * x3)));
                }
                po[jj] = val;
            }
            *(float4*)(C + grow + j) = o;
        }
    }
}

// ---------------- block-sparse attention (flash-style, unified) ----------------
// grid: (NBLK, NH, BB). Middle q-blocks attend to 8 gathered key blocks
// (global 0, global 63, window m-1/m/m+1, 3 random — duplicates kept, as in ref).
// Edge q-blocks (m==0, m==63) attend to all 64 blocks (full attention).
__global__ __launch_bounds__(256) void attn_kernel(
    const float* __restrict__ q, const float* __restrict__ k,
    const float* __restrict__ v, const int* __restrict__ rb,
    float* __restrict__ out)
{
    extern __shared__ float sm[];
    float* qs = sm;               // [64][65]
    float* ks = sm + 64 * 65;     // [64][65]
    float* vs = sm + 2 * 64 * 65; // [64][65]
    float* ps = sm + 3 * 64 * 65; // [64][65]
    int m = blockIdx.x, h = blockIdx.y, b = blockIdx.z;
    int t = threadIdx.x;
    int row = t >> 2, c0 = (t & 3) << 4;

    const float* qb = q + (size_t)(b * NTOK + m * BS) * DM + h * DHEAD;
    for (int i = t; i < 4096; i += 256) {
        int r = i >> 6, c = i & 63;
        qs[r * 65 + c] = qb[(size_t)r * DM + c];
    }
    bool edge = (m == 0) || (m == NBLK - 1);
    int nkb = edge ? NBLK : 8;
    int list[8];
    if (!edge) {
        const int* r3 = rb + (h * NBLK + m) * RR;
        list[0] = 0; list[1] = NBLK - 1;
        list[2] = m - 1; list[3] = m; list[4] = m + 1;
        list[5] = r3[0]; list[6] = r3[1]; list[7] = r3[2];
    }
    float mrow = -3e38f, lrow = 0.f;
    float oacc[16];
#pragma unroll
    for (int i = 0; i < 16; i++) oacc[i] = 0.f;
    __syncthreads();

    const float scale = 0.125f; // 1/sqrt(64)
    for (int kb = 0; kb < nkb; kb++) {
        int blk = edge ? kb : list[kb];
        const float* kbp = k + (size_t)(b * NTOK + blk * BS) * DM + h * DHEAD;
        const float* vbp = v + (size_t)(b * NTOK + blk * BS) * DM + h * DHEAD;
        for (int i = t; i < 4096; i += 256) {
            int r = i >> 6, c = i & 63;
            ks[r * 65 + c] = kbp[(size_t)r * DM + c];
            vs[r * 65 + c] = vbp[(size_t)r * DM + c];
        }
        __syncthreads();

        float s[16];
#pragma unroll
        for (int j = 0; j < 16; j++) s[j] = 0.f;
        for (int d = 0; d < 64; d++) {
            float qv = qs[row * 65 + d];
#pragma unroll
            for (int j = 0; j < 16; j++) s[j] += qv * ks[(c0 + j) * 65 + d];
        }
        float tmax = -3e38f;
#pragma unroll
        for (int j = 0; j < 16; j++) { s[j] *= scale; tmax = fmaxf(tmax, s[j]); }
        tmax = fmaxf(tmax, __shfl_xor_sync(0xffffffffu, tmax, 1));
        tmax = fmaxf(tmax, __shfl_xor_sync(0xffffffffu, tmax, 2));
        float newm = fmaxf(mrow, tmax);
        float corr = __expf(mrow - newm);
        float psum = 0.f;
#pragma unroll
        for (int j = 0; j < 16; j++) {
            float p = __expf(s[j] - newm);
            ps[row * 65 + c0 + j] = p;
            psum += p;
        }
        psum += __shfl_xor_sync(0xffffffffu, psum, 1);
        psum += __shfl_xor_sync(0xffffffffu, psum, 2);
        lrow = lrow * corr + psum;
        mrow = newm;
#pragma unroll
        for (int i = 0; i < 16; i++) oacc[i] *= corr;
        __syncwarp();
        for (int j = 0; j < 64; j++) {
            float pv = ps[row * 65 + j];
#pragma unroll
            for (int d2 = 0; d2 < 16; d2++) oacc[d2] += pv * vs[j * 65 + c0 + d2];
        }
        __syncthreads();
    }
    float inv = 1.f / lrow;
    float* ob = out + (size_t)(b * NTOK + m * BS + row) * DM + h * DHEAD + c0;
#pragma unroll
    for (int d2 = 0; d2 < 16; d2++) ob[d2] = oacc[d2] * inv;
}

// ---------------- final pooled head ----------------
__global__ __launch_bounds__(256) void final_part_kernel(
    const float* __restrict__ x, const float* __restrict__ fcw,
    float* __restrict__ part)
{
    int c = blockIdx.x, b = blockIdx.y;
    float acc = 0.f;
#pragma unroll
    for (int i = 0; i < 3; i++) {
        int d = threadIdx.x + i * 256;
        float s = 0.f;
        int n0 = c * 128;
        for (int n = n0; n < n0 + 128; n++)
            s += x[((size_t)b * NTOK + n) * DM + d];
        acc += s * fcw[d];
    }
    float dummy = 0.f;
    block_reduce2(acc, dummy);
    if (threadIdx.x == 0) part[b * 32 + c] = acc;
}

__global__ void final_sum_kernel(const float* __restrict__ part,
                                 const float* __restrict__ fcb,
                                 float* __restrict__ out)
{
    int t = threadIdx.x; // 64 threads
    int b = t >> 5, lane = t & 31;
    float v = part[b * 32 + lane];
#pragma unroll
    for (int off = 16; off > 0; off >>= 1)
        v += __shfl_down_sync(0xffffffffu, v, off);
    if (lane == 0) out[b] = v * (1.f / NTOK) + fcb[0];
}

// ---------------- driver ----------------
extern "C" void kernel_launch(void* const* d_in, const int* in_sizes, int n_in,
                              void* d_out, int out_size)
{
    const float* inputs = (const float*)d_in[0];
    const int*   rb_all = (const int*)d_in[1];
    const float* pos = (const float*)d_in[2];
    const float* tt  = (const float*)d_in[3];
    const float* eg  = (const float*)d_in[4];
    const float* eb  = (const float*)d_in[5];
    const float* Wq  = (const float*)d_in[6];  const float* bq = (const float*)d_in[7];
    const float* Wk  = (const float*)d_in[8];  const float* bk = (const float*)d_in[9];
    const float* Wv  = (const float*)d_in[10]; const float* bv = (const float*)d_in[11];
    const float* Wo  = (const float*)d_in[12]; const float* bo = (const float*)d_in[13];
    const float* l1g = (const float*)d_in[14]; const float* l1b = (const float*)d_in[15];
    const float* Wi  = (const float*)d_in[16]; const float* bi = (const float*)d_in[17];
    const float* Wd  = (const float*)d_in[18]; const float* bd = (const float*)d_in[19];
    const float* l2g = (const float*)d_in[20]; const float* l2b = (const float*)d_in[21];
    const float* fcw = (const float*)d_in[22]; const float* fcb = (const float*)d_in[23];
    float* out = (float*)d_out;

    float *x, *q, *k, *v, *ctx, *tb, *a, *hh, *part;
    cudaGetSymbolAddress((void**)&x,   g_x);
    cudaGetSymbolAddress((void**)&q,   g_q);
    cudaGetSymbolAddress((void**)&k,   g_k);
    cudaGetSymbolAddress((void**)&v,   g_v);
    cudaGetSymbolAddress((void**)&ctx, g_ctx);
    cudaGetSymbolAddress((void**)&tb,  g_t);
    cudaGetSymbolAddress((void**)&a,   g_a);
    cudaGetSymbolAddress((void**)&hh,  g_h);
    cudaGetSymbolAddress((void**)&part, g_part);

    const int ATTN_SMEM = 4 * 64 * 65 * 4; // 66560 bytes
    cudaFuncSetAttribute(attn_kernel, cudaFuncAttributeMaxDynamicSharedMemorySize, ATTN_SMEM);

    const int MROWS = BB * NTOK;           // 8192
    dim3 gemm_dd(DM / 128, MROWS / 128);   // (6, 64)
    dim3 gemm_ff(FFD / 128, MROWS / 128);  // (24, 64)

    embed_ln_kernel<<<MROWS, 256>>>(inputs, pos, tt, eg, eb, x);

    for (int l = 0; l < NL; l++) {
        size_t wdd = (size_t)l * DM * DM;
        sgemm_kernel<0><<<gemm_dd, 256>>>(x, Wq + wdd, bq + l * DM, q, MROWS, DM, DM);
        sgemm_kernel<0><<<gemm_dd, 256>>>(x, Wk + wdd, bk + l * DM, k, MROWS, DM, DM);
        sgemm_kernel<0><<<gemm_dd, 256>>>(x, Wv + wdd, bv + l * DM, v, MROWS, DM, DM);

        attn_kernel<<<dim3(NBLK, NH, BB), 256, ATTN_SMEM>>>(
            q, k, v, rb_all + l * NH * NBLK * RR, ctx);

        sgemm_kernel<0><<<gemm_dd, 256>>>(ctx, Wo + wdd, bo + l * DM, tb, MROWS, DM, DM);
        ln_add_kernel<<<MROWS, 256>>>(x, tb, l1g + l * DM, l1b + l * DM, a);

        sgemm_kernel<1><<<gemm_ff, 256>>>(a, Wi + (size_t)l * DM * FFD, bi + l * FFD,
                                          hh, MROWS, FFD, DM);
        sgemm_kernel<0><<<gemm_dd, 256>>>(hh, Wd + (size_t)l * FFD * DM, bd + l * DM,
                                          tb, MROWS, DM, FFD);
        ln_add_kernel<<<MROWS, 256>>>(a, tb, l2g + l * DM, l2b + l * DM, x);
    }

    final_part_kernel<<<dim3(32, BB), 256>>>(x, fcw, part);
    final_sum_kernel<<<1, 64>>>(part, fcb, out);
}

// round 3
// speedup vs baseline: 1.4069x; 1.4069x over previous
#include <cuda_runtime.h>
#include <math.h>
#include <stdint.h>

#define BB 2
#define NTOK 4096
#define DM 768
#define NH 12
#define DHEAD 64
#define NBLK 64
#define BS 64
#define FFD 3072
#define NL 2
#define RR 3

// ---------------- scratch (device globals; no allocation) ----------------
__device__ float g_x[BB * NTOK * DM];
__device__ float g_q[BB * NTOK * DM];
__device__ float g_k[BB * NTOK * DM];
__device__ float g_v[BB * NTOK * DM];
__device__ float g_ctx[BB * NTOK * DM];
__device__ float g_t[BB * NTOK * DM];
__device__ float g_a[BB * NTOK * DM];
__device__ float g_h[BB * NTOK * FFD];
__device__ float g_part[BB * 32];
// edge-attention partials: [e][h][b][s][row][col] / [e][h][b][s][row]
__device__ float g_eo[2 * NH * BB * 8 * 64 * 64];
__device__ float g_em[2 * NH * BB * 8 * 64];
__device__ float g_el[2 * NH * BB * 8 * 64];

// ---------------- helpers ----------------
__device__ __forceinline__ float to_tf32(float x) {
    uint32_t u; asm("cvt.rna.tf32.f32 %0, %1;" : "=r"(u) : "f"(x));
    return __uint_as_float(u);
}

__device__ __forceinline__ void mma_tf32(float* c, const uint32_t* a, const uint32_t* b) {
    asm volatile(
        "mma.sync.aligned.m16n8k8.row.col.f32.tf32.tf32.f32 "
        "{%0,%1,%2,%3}, {%4,%5,%6,%7}, {%8,%9}, {%0,%1,%2,%3};"
        : "+f"(c[0]), "+f"(c[1]), "+f"(c[2]), "+f"(c[3])
        : "r"(a[0]), "r"(a[1]), "r"(a[2]), "r"(a[3]), "r"(b[0]), "r"(b[1]));
}

// ---------------- block reduce (sum of two values) ----------------
__device__ __forceinline__ void block_reduce2(float& s, float& s2) {
#pragma unroll
    for (int off = 16; off > 0; off >>= 1) {
        s  += __shfl_down_sync(0xffffffffu, s, off);
        s2 += __shfl_down_sync(0xffffffffu, s2, off);
    }
    __shared__ float sh[16];
    int w = threadIdx.x >> 5, lane = threadIdx.x & 31;
    if (lane == 0) { sh[w] = s; sh[8 + w] = s2; }
    __syncthreads();
    if (threadIdx.x == 0) {
        float a = 0.f, b = 0.f;
#pragma unroll
        for (int i = 0; i < 8; i++) { a += sh[i]; b += sh[8 + i]; }
        sh[0] = a; sh[8] = b;
    }
    __syncthreads();
    s = sh[0]; s2 = sh[8];
}

// ---------------- embedding + LayerNorm ----------------
__global__ __launch_bounds__(256) void embed_ln_kernel(
    const float* __restrict__ e, const float* __restrict__ pos,
    const float* __restrict__ tt, const float* __restrict__ g,
    const float* __restrict__ bta, float* __restrict__ out)
{
    int row = blockIdx.x;
    int n = row & (NTOK - 1);
    size_t base = (size_t)row * DM;
    float v[3]; float s = 0.f, s2 = 0.f;
#pragma unroll
    for (int i = 0; i < 3; i++) {
        int d = threadIdx.x + i * 256;
        float val = e[base + d] + pos[(size_t)n * DM + d] + tt[d];
        v[i] = val; s += val; s2 += val * val;
    }
    block_reduce2(s, s2);
    float mean = s * (1.f / DM);
    float var = s2 * (1.f / DM) - mean * mean;
    float rstd = rsqrtf(var + 1e-12f);
#pragma unroll
    for (int i = 0; i < 3; i++) {
        int d = threadIdx.x + i * 256;
        out[base + d] = (v[i] - mean) * rstd * g[d] + bta[d];
    }
}

// ---------------- residual add + LayerNorm ----------------
__global__ __launch_bounds__(256) void ln_add_kernel(
    const float* __restrict__ r, const float* __restrict__ y,
    const float* __restrict__ g, const float* __restrict__ bta,
    float* __restrict__ out)
{
    int row = blockIdx.x;
    size_t base = (size_t)row * DM;
    float v[3]; float s = 0.f, s2 = 0.f;
#pragma unroll
    for (int i = 0; i < 3; i++) {
        int d = threadIdx.x + i * 256;
        float val = r[base + d] + y[base + d];
        v[i] = val; s += val; s2 += val * val;
    }
    block_reduce2(s, s2);
    float mean = s * (1.f / DM);
    float var = s2 * (1.f / DM) - mean * mean;
    float rstd = rsqrtf(var + 1e-12f);
#pragma unroll
    for (int i = 0; i < 3; i++) {
        int d = threadIdx.x + i * 256;
        out[base + d] = (v[i] - mean) * rstd * g[d] + bta[d];
    }
}

// ---------------- mma.sync 3xTF32 GEMM: C = A(MxK) @ W(KxN) + bias [+GELU] ----------------
// CTA tile 128x128, K-chunk 16, double buffered. 8 warps in 4x2 -> warp tile 32x64.
// Each fp32 operand split into tf32 hi + tf32 lo; accumulate hh + hl + lh in fp32.
template<int GELU>
__global__ __launch_bounds__(256, 1) void mgemm_kernel(
    const float* __restrict__ A, const float* __restrict__ W,
    const float* __restrict__ bias, float* __restrict__ C,
    int M, int Nn, int K)
{
    extern __shared__ float sm[];
    // per-buffer float offsets
    const int AH = 0;              // [128][20]
    const int AL = 2560;           // [128][20]
    const int BH = 5120;           // [16][132]
    const int BL = 5120 + 2112;    // [16][132]
    const int BUFS = 5120 + 4224;  // 9344 floats per buffer

    const int t = threadIdx.x;
    const int wid = t >> 5, lane = t & 31;
    const int wr0 = (wid >> 1) * 32;   // warp row in tile
    const int wc0 = (wid & 1) * 64;    // warp col in tile
    const int lr = lane >> 2;          // 0..7
    const int lc = lane & 3;           // 0..3

    const float* Ap = A + (size_t)blockIdx.y * 128 * K;
    const float* Wp = W + blockIdx.x * 128;

    float acc[2][8][4];
#pragma unroll
    for (int i = 0; i < 2; i++)
#pragma unroll
        for (int j = 0; j < 8; j++)
#pragma unroll
            for (int q = 0; q < 4; q++) acc[i][j][q] = 0.f;

    // load indices (two float4 loads per thread for A and for B)
    int ar[2], akq[2], bkr[2], bnq[2];
#pragma unroll
    for (int i = 0; i < 2; i++) {
        int v = t + i * 256;
        ar[i] = v >> 2; akq[i] = v & 3;      // A: row 0..127, float4 0..3 (16 k-floats)
        bkr[i] = v >> 5; bnq[i] = v & 31;    // B: k-row 0..15, float4 0..31 (128 n-floats)
    }

    float4 aR[2], bR[2];
    auto LDG = [&](int k0) {
#pragma unroll
        for (int i = 0; i < 2; i++) {
            aR[i] = *(const float4*)(Ap + (size_t)ar[i] * K + k0 + akq[i] * 4);
            bR[i] = *(const float4*)(Wp + (size_t)(k0 + bkr[i]) * Nn + bnq[i] * 4);
        }
    };
    auto STS = [&](int b) {
        float* base = sm + b * BUFS;
#pragma unroll
        for (int i = 0; i < 2; i++) {
            float4 h, l;
            h.x = to_tf32(aR[i].x); l.x = to_tf32(aR[i].x - h.x);
            h.y = to_tf32(aR[i].y); l.y = to_tf32(aR[i].y - h.y);
            h.z = to_tf32(aR[i].z); l.z = to_tf32(aR[i].z - h.z);
            h.w = to_tf32(aR[i].w); l.w = to_tf32(aR[i].w - h.w);
            *(float4*)(base + AH + ar[i] * 20 + akq[i] * 4) = h;
            *(float4*)(base + AL + ar[i] * 20 + akq[i] * 4) = l;
            float4 bh, bl;
            bh.x = to_tf32(bR[i].x); bl.x = to_tf32(bR[i].x - bh.x);
            bh.y = to_tf32(bR[i].y); bl.y = to_tf32(bR[i].y - bh.y);
            bh.z = to_tf32(bR[i].z); bl.z = to_tf32(bR[i].z - bh.z);
            bh.w = to_tf32(bR[i].w); bl.w = to_tf32(bR[i].w - bh.w);
            *(float4*)(base + BH + bkr[i] * 132 + bnq[i] * 4) = bh;
            *(float4*)(base + BL + bkr[i] * 132 + bnq[i] * 4) = bl;
        }
    };

    auto COMP = [&](int b) {
        const uint32_t* ah = (const uint32_t*)(sm + b * BUFS + AH);
        const uint32_t* al = (const uint32_t*)(sm + b * BUFS + AL);
        const uint32_t* bh = (const uint32_t*)(sm + b * BUFS + BH);
        const uint32_t* bl = (const uint32_t*)(sm + b * BUFS + BL);
#pragma unroll
        for (int ks = 0; ks < 2; ks++) {
            int kb = ks * 8;
            uint32_t af[2][4], bf[8][2];
            // ---- pass hh ----
#pragma unroll
            for (int mt = 0; mt < 2; mt++) {
                int r = wr0 + mt * 16 + lr;
                af[mt][0] = ah[r * 20 + kb + lc];
                af[mt][1] = ah[(r + 8) * 20 + kb + lc];
                af[mt][2] = ah[r * 20 + kb + lc + 4];
                af[mt][3] = ah[(r + 8) * 20 + kb + lc + 4];
            }
#pragma unroll
            for (int nt = 0; nt < 8; nt++) {
                int n = wc0 + nt * 8 + lr;
                bf[nt][0] = bh[(kb + lc) * 132 + n];
                bf[nt][1] = bh[(kb + lc + 4) * 132 + n];
            }
#pragma unroll
            for (int mt = 0; mt < 2; mt++)
#pragma unroll
                for (int nt = 0; nt < 8; nt++) mma_tf32(acc[mt][nt], af[mt], bf[nt]);
            // ---- pass hl (reuse a_hi, load b_lo) ----
#pragma unroll
            for (int nt = 0; nt < 8; nt++) {
                int n = wc0 + nt * 8 + lr;
                bf[nt][0] = bl[(kb + lc) * 132 + n];
                bf[nt][1] = bl[(kb + lc + 4) * 132 + n];
            }
#pragma unroll
            for (int mt = 0; mt < 2; mt++)
#pragma unroll
                for (int nt = 0; nt < 8; nt++) mma_tf32(acc[mt][nt], af[mt], bf[nt]);
            // ---- pass lh (load a_lo, reload b_hi) ----
#pragma unroll
            for (int mt = 0; mt < 2; mt++) {
                int r = wr0 + mt * 16 + lr;
                af[mt][0] = al[r * 20 + kb + lc];
                af[mt][1] = al[(r + 8) * 20 + kb + lc];
                af[mt][2] = al[r * 20 + kb + lc + 4];
                af[mt][3] = al[(r + 8) * 20 + kb + lc + 4];
            }
#pragma unroll
            for (int nt = 0; nt < 8; nt++) {
                int n = wc0 + nt * 8 + lr;
                bf[nt][0] = bh[(kb + lc) * 132 + n];
                bf[nt][1] = bh[(kb + lc + 4) * 132 + n];
            }
#pragma unroll
            for (int mt = 0; mt < 2; mt++)
#pragma unroll
                for (int nt = 0; nt < 8; nt++) mma_tf32(acc[mt][nt], af[mt], bf[nt]);
        }
    };

    const int nch = K / 16;
    LDG(0); STS(0);
    __syncthreads();
    for (int c = 0; c < nch; c++) {
        if (c + 1 < nch) LDG((c + 1) * 16);
        COMP(c & 1);
        if (c + 1 < nch) { STS((c + 1) & 1); __syncthreads(); }
    }

    // epilogue
#pragma unroll
    for (int mt = 0; mt < 2; mt++) {
        int r = blockIdx.y * 128 + wr0 + mt * 16 + lr;
#pragma unroll
        for (int nt = 0; nt < 8; nt++) {
            int cc = blockIdx.x * 128 + wc0 + nt * 8 + lc * 2;
            float b0 = bias[cc], b1 = bias[cc + 1];
            float v[4];
            v[0] = acc[mt][nt][0] + b0; v[1] = acc[mt][nt][1] + b1;
            v[2] = acc[mt][nt][2] + b0; v[3] = acc[mt][nt][3] + b1;
            if (GELU) {
#pragma unroll
                for (int q = 0; q < 4; q++) {
                    float x3 = v[q] * v[q] * v[q];
                    v[q] = 0.5f * v[q] * (1.f + tanhf(0.7978845608028654f * (v[q] + 0.044715f * x3)));
                }
            }
            *(float2*)(C + (size_t)r * Nn + cc) = make_float2(v[0], v[1]);
            *(float2*)(C + (size_t)(r + 8) * Nn + cc) = make_float2(v[2], v[3]);
        }
    }
}

// ---------------- block-sparse attention: middle q-blocks ----------------
__global__ __launch_bounds__(256) void attn_mid_kernel(
    const float* __restrict__ q, const float* __restrict__ k,
    const float* __restrict__ v, const int* __restrict__ rb,
    float* __restrict__ out)
{
    extern __shared__ float sm[];
    float* qs = sm;
    float* ks = sm + 64 * 65;
    float* vs = sm + 2 * 64 * 65;
    float* ps = sm + 3 * 64 * 65;
    int m = blockIdx.x + 1, h = blockIdx.y, b = blockIdx.z;
    int t = threadIdx.x;
    int row = t >> 2, c0 = (t & 3) << 4;

    const float* qb = q + (size_t)(b * NTOK + m * BS) * DM + h * DHEAD;
    for (int i = t; i < 4096; i += 256) {
        int r = i >> 6, c = i & 63;
        qs[r * 65 + c] = qb[(size_t)r * DM + c];
    }
    int list[8];
    {
        const int* r3 = rb + (h * NBLK + m) * RR;
        list[0] = 0; list[1] = NBLK - 1;
        list[2] = m - 1; list[3] = m; list[4] = m + 1;
        list[5] = r3[0]; list[6] = r3[1]; list[7] = r3[2];
    }
    float mrow = -3e38f, lrow = 0.f;
    float oacc[16];
#pragma unroll
    for (int i = 0; i < 16; i++) oacc[i] = 0.f;
    __syncthreads();

    const float scale = 0.125f;
    for (int kb = 0; kb < 8; kb++) {
        int blk = list[kb];
        const float* kbp = k + (size_t)(b * NTOK + blk * BS) * DM + h * DHEAD;
        const float* vbp = v + (size_t)(b * NTOK + blk * BS) * DM + h * DHEAD;
        for (int i = t; i < 4096; i += 256) {
            int r = i >> 6, c = i & 63;
            ks[r * 65 + c] = kbp[(size_t)r * DM + c];
            vs[r * 65 + c] = vbp[(size_t)r * DM + c];
        }
        __syncthreads();

        float s[16];
#pragma unroll
        for (int j = 0; j < 16; j++) s[j] = 0.f;
        for (int d = 0; d < 64; d++) {
            float qv = qs[row * 65 + d];
#pragma unroll
            for (int j = 0; j < 16; j++) s[j] += qv * ks[(c0 + j) * 65 + d];
        }
        float tmax = -3e38f;
#pragma unroll
        for (int j = 0; j < 16; j++) { s[j] *= scale; tmax = fmaxf(tmax, s[j]); }
        tmax = fmaxf(tmax, __shfl_xor_sync(0xffffffffu, tmax, 1));
        tmax = fmaxf(tmax, __shfl_xor_sync(0xffffffffu, tmax, 2));
        float newm = fmaxf(mrow, tmax);
        float corr = __expf(mrow - newm);
        float psum = 0.f;
#pragma unroll
        for (int j = 0; j < 16; j++) {
            float p = __expf(s[j] - newm);
            ps[row * 65 + c0 + j] = p;
            psum += p;
        }
        psum += __shfl_xor_sync(0xffffffffu, psum, 1);
        psum += __shfl_xor_sync(0xffffffffu, psum, 2);
        lrow = lrow * corr + psum;
        mrow = newm;
#pragma unroll
        for (int i = 0; i < 16; i++) oacc[i] *= corr;
        __syncwarp();
        for (int j = 0; j < 64; j++) {
            float pv = ps[row * 65 + j];
#pragma unroll
            for (int d2 = 0; d2 < 16; d2++) oacc[d2] += pv * vs[j * 65 + c0 + d2];
        }
        __syncthreads();
    }
    float inv = 1.f / lrow;
    float* ob = out + (size_t)(b * NTOK + m * BS + row) * DM + h * DHEAD + c0;
#pragma unroll
    for (int d2 = 0; d2 < 16; d2++) ob[d2] = oacc[d2] * inv;
}

// ---------------- edge q-blocks: split-KV partials ----------------
// grid (8, NH, BB*2): x = s (key-block octave), z = b*2 + e
__global__ __launch_bounds__(256) void attn_edge_kernel(
    const float* __restrict__ q, const float* __restrict__ k,
    const float* __restrict__ v,
    float* __restrict__ eo, float* __restrict__ em, float* __restrict__ el)
{
    extern __shared__ float sm[];
    float* qs = sm;
    float* ks = sm + 64 * 65;
    float* vs = sm + 2 * 64 * 65;
    float* ps = sm + 3 * 64 * 65;
    int s0 = blockIdx.x, h = blockIdx.y;
    int b = blockIdx.z >> 1, e = blockIdx.z & 1;
    int m = e ? (NBLK - 1) : 0;
    int t = threadIdx.x;
    int row = t >> 2, c0 = (t & 3) << 4;

    const float* qb = q + (size_t)(b * NTOK + m * BS) * DM + h * DHEAD;
    for (int i = t; i < 4096; i += 256) {
        int r = i >> 6, c = i & 63;
        qs[r * 65 + c] = qb[(size_t)r * DM + c];
    }
    float mrow = -3e38f, lrow = 0.f;
    float oacc[16];
#pragma unroll
    for (int i = 0; i < 16; i++) oacc[i] = 0.f;
    __syncthreads();

    const float scale = 0.125f;
    for (int kb = s0 * 8; kb < s0 * 8 + 8; kb++) {
        const float* kbp = k + (size_t)(b * NTOK + kb * BS) * DM + h * DHEAD;
        const float* vbp = v + (size_t)(b * NTOK + kb * BS) * DM + h * DHEAD;
        for (int i = t; i < 4096; i += 256) {
            int r = i >> 6, c = i & 63;
            ks[r * 65 + c] = kbp[(size_t)r * DM + c];
            vs[r * 65 + c] = vbp[(size_t)r * DM + c];
        }
        __syncthreads();

        float s[16];
#pragma unroll
        for (int j = 0; j < 16; j++) s[j] = 0.f;
        for (int d = 0; d < 64; d++) {
            float qv = qs[row * 65 + d];
#pragma unroll
            for (int j = 0; j < 16; j++) s[j] += qv * ks[(c0 + j) * 65 + d];
        }
        float tmax = -3e38f;
#pragma unroll
        for (int j = 0; j < 16; j++) { s[j] *= scale; tmax = fmaxf(tmax, s[j]); }
        tmax = fmaxf(tmax, __shfl_xor_sync(0xffffffffu, tmax, 1));
        tmax = fmaxf(tmax, __shfl_xor_sync(0xffffffffu, tmax, 2));
        float newm = fmaxf(mrow, tmax);
        float corr = __expf(mrow - newm);
        float psum = 0.f;
#pragma unroll
        for (int j = 0; j < 16; j++) {
            float p = __expf(s[j] - newm);
            ps[row * 65 + c0 + j] = p;
            psum += p;
        }
        psum += __shfl_xor_sync(0xffffffffu, psum, 1);
        psum += __shfl_xor_sync(0xffffffffu, psum, 2);
        lrow = lrow * corr + psum;
        mrow = newm;
#pragma unroll
        for (int i = 0; i < 16; i++) oacc[i] *= corr;
        __syncwarp();
        for (int j = 0; j < 64; j++) {
            float pv = ps[row * 65 + j];
#pragma unroll
            for (int d2 = 0; d2 < 16; d2++) oacc[d2] += pv * vs[j * 65 + c0 + d2];
        }
        __syncthreads();
    }
    size_t pbase = ((((size_t)e * NH + h) * BB + b) * 8 + s0);
    float* op = eo + pbase * 4096 + row * 64 + c0;
#pragma unroll
    for (int d2 = 0; d2 < 16; d2++) op[d2] = oacc[d2];   // unnormalized
    if ((t & 3) == 0) {
        em[pbase * 64 + row] = mrow;
        el[pbase * 64 + row] = lrow;
    }
}

// grid (2, NH, BB): combine 8 partials per edge q-block
__global__ __launch_bounds__(256) void attn_edge_combine_kernel(
    const float* __restrict__ eo, const float* __restrict__ em,
    const float* __restrict__ el, float* __restrict__ out)
{
    int e = blockIdx.x, h = blockIdx.y, b = blockIdx.z;
    int m = e ? (NBLK - 1) : 0;
    int t = threadIdx.x;
    int row = t >> 2, c0 = (t & 3) << 4;
    size_t base0 = ((((size_t)e * NH + h) * BB + b) * 8);

    float M = -3e38f;
#pragma unroll
    for (int s = 0; s < 8; s++) M = fmaxf(M, em[(base0 + s) * 64 + row]);
    float L = 0.f;
    float w[8];
#pragma unroll
    for (int s = 0; s < 8; s++) {
        w[s] = __expf(em[(base0 + s) * 64 + row] - M);
        L += w[s] * el[(base0 + s) * 64 + row];
    }
    float acc[16];
#pragma unroll
    for (int j = 0; j < 16; j++) acc[j] = 0.f;
#pragma unroll
    for (int s = 0; s < 8; s++) {
        const float* op = eo + (base0 + s) * 4096 + row * 64 + c0;
#pragma unroll
        for (int j = 0; j < 16; j++) acc[j] += w[s] * op[j];
    }
    float inv = 1.f / L;
    float* ob = out + (size_t)(b * NTOK + m * BS + row) * DM + h * DHEAD + c0;
#pragma unroll
    for (int j = 0; j < 16; j++) ob[j] = acc[j] * inv;
}

// ---------------- final pooled head ----------------
__global__ __launch_bounds__(256) void final_part_kernel(
    const float* __restrict__ x, const float* __restrict__ fcw,
    float* __restrict__ part)
{
    int c = blockIdx.x, b = blockIdx.y;
    float acc = 0.f;
#pragma unroll
    for (int i = 0; i < 3; i++) {
        int d = threadIdx.x + i * 256;
        float s = 0.f;
        int n0 = c * 128;
        for (int n = n0; n < n0 + 128; n++)
            s += x[((size_t)b * NTOK + n) * DM + d];
        acc += s * fcw[d];
    }
    float dummy = 0.f;
    block_reduce2(acc, dummy);
    if (threadIdx.x == 0) part[b * 32 + c] = acc;
}

__global__ void final_sum_kernel(const float* __restrict__ part,
                                 const float* __restrict__ fcb,
                                 float* __restrict__ out)
{
    int t = threadIdx.x;
    int b = t >> 5, lane = t & 31;
    float v = part[b * 32 + lane];
#pragma unroll
    for (int off = 16; off > 0; off >>= 1)
        v += __shfl_down_sync(0xffffffffu, v, off);
    if (lane == 0) out[b] = v * (1.f / NTOK) + fcb[0];
}

// ---------------- driver ----------------
extern "C" void kernel_launch(void* const* d_in, const int* in_sizes, int n_in,
                              void* d_out, int out_size)
{
    const float* inputs = (const float*)d_in[0];
    const int*   rb_all = (const int*)d_in[1];
    const float* pos = (const float*)d_in[2];
    const float* tt  = (const float*)d_in[3];
    const float* eg  = (const float*)d_in[4];
    const float* eb  = (const float*)d_in[5];
    const float* Wq  = (const float*)d_in[6];  const float* bq = (const float*)d_in[7];
    const float* Wk  = (const float*)d_in[8];  const float* bk = (const float*)d_in[9];
    const float* Wv  = (const float*)d_in[10]; const float* bv = (const float*)d_in[11];
    const float* Wo  = (const float*)d_in[12]; const float* bo = (const float*)d_in[13];
    const float* l1g = (const float*)d_in[14]; const float* l1b = (const float*)d_in[15];
    const float* Wi  = (const float*)d_in[16]; const float* bi = (const float*)d_in[17];
    const float* Wd  = (const float*)d_in[18]; const float* bd = (const float*)d_in[19];
    const float* l2g = (const float*)d_in[20]; const float* l2b = (const float*)d_in[21];
    const float* fcw = (const float*)d_in[22]; const float* fcb = (const float*)d_in[23];
    float* out = (float*)d_out;

    float *x, *q, *k, *v, *ctx, *tb, *a, *hh, *part, *eo, *em, *el;
    cudaGetSymbolAddress((void**)&x,   g_x);
    cudaGetSymbolAddress((void**)&q,   g_q);
    cudaGetSymbolAddress((void**)&k,   g_k);
    cudaGetSymbolAddress((void**)&v,   g_v);
    cudaGetSymbolAddress((void**)&ctx, g_ctx);
    cudaGetSymbolAddress((void**)&tb,  g_t);
    cudaGetSymbolAddress((void**)&a,   g_a);
    cudaGetSymbolAddress((void**)&hh,  g_h);
    cudaGetSymbolAddress((void**)&part, g_part);
    cudaGetSymbolAddress((void**)&eo,  g_eo);
    cudaGetSymbolAddress((void**)&em,  g_em);
    cudaGetSymbolAddress((void**)&el,  g_el);

    const int ATTN_SMEM = 4 * 64 * 65 * 4;       // 66560 bytes
    const int GEMM_SMEM = 2 * 9344 * 4;          // 74752 bytes
    cudaFuncSetAttribute(attn_mid_kernel, cudaFuncAttributeMaxDynamicSharedMemorySize, ATTN_SMEM);
    cudaFuncSetAttribute(attn_edge_kernel, cudaFuncAttributeMaxDynamicSharedMemorySize, ATTN_SMEM);
    cudaFuncSetAttribute(mgemm_kernel<0>, cudaFuncAttributeMaxDynamicSharedMemorySize, GEMM_SMEM);
    cudaFuncSetAttribute(mgemm_kernel<1>, cudaFuncAttributeMaxDynamicSharedMemorySize, GEMM_SMEM);

    const int MROWS = BB * NTOK;                 // 8192
    dim3 gemm_dd(DM / 128, MROWS / 128);         // (6, 64)
    dim3 gemm_ff(FFD / 128, MROWS / 128);        // (24, 64)

    embed_ln_kernel<<<MROWS, 256>>>(inputs, pos, tt, eg, eb, x);

    for (int l = 0; l < NL; l++) {
        size_t wdd = (size_t)l * DM * DM;
        mgemm_kernel<0><<<gemm_dd, 256, GEMM_SMEM>>>(x, Wq + wdd, bq + l * DM, q, MROWS, DM, DM);
        mgemm_kernel<0><<<gemm_dd, 256, GEMM_SMEM>>>(x, Wk + wdd, bk + l * DM, k, MROWS, DM, DM);
        mgemm_kernel<0><<<gemm_dd, 256, GEMM_SMEM>>>(x, Wv + wdd, bv + l * DM, v, MROWS, DM, DM);

        attn_mid_kernel<<<dim3(NBLK - 2, NH, BB), 256, ATTN_SMEM>>>(
            q, k, v, rb_all + l * NH * NBLK * RR, ctx);
        attn_edge_kernel<<<dim3(8, NH, BB * 2), 256, ATTN_SMEM>>>(q, k, v, eo, em, el);
        attn_edge_combine_kernel<<<dim3(2, NH, BB), 256>>>(eo, em, el, ctx);

        mgemm_kernel<0><<<gemm_dd, 256, GEMM_SMEM>>>(ctx, Wo + wdd, bo + l * DM, tb, MROWS, DM, DM);
        ln_add_kernel<<<MROWS, 256>>>(x, tb, l1g + l * DM, l1b + l * DM, a);

        mgemm_kernel<1><<<gemm_ff, 256, GEMM_SMEM>>>(a, Wi + (size_t)l * DM * FFD, bi + l * FFD,
                                                     hh, MROWS, FFD, DM);
        mgemm_kernel<0><<<gemm_dd, 256, GEMM_SMEM>>>(hh, Wd + (size_t)l * FFD * DM, bd + l * DM,
                                                     tb, MROWS, DM, FFD);
        ln_add_kernel<<<MROWS, 256>>>(a, tb, l2g + l * DM, l2b + l * DM, x);
    }

    final_part_kernel<<<dim3(32, BB), 256>>>(x, fcw, part);
    final_sum_kernel<<<1, 64>>>(part, fcb, out);
}

// round 4
// speedup vs baseline: 1.7142x; 1.2184x over previous
#include <cuda_runtime.h>
#include <math.h>
#include <stdint.h>

#define BB 2
#define NTOK 4096
#define DM 768
#define NH 12
#define DHEAD 64
#define NBLK 64
#define BS 64
#define FFD 3072
#define NL 2
#define RR 3

// ---------------- scratch (device globals; no allocation) ----------------
__device__ float g_x[BB * NTOK * DM];
__device__ float g_q[BB * NTOK * DM];
__device__ float g_k[BB * NTOK * DM];
__device__ float g_v[BB * NTOK * DM];
__device__ float g_ctx[BB * NTOK * DM];
__device__ float g_t[BB * NTOK * DM];
__device__ float g_a[BB * NTOK * DM];
__device__ float g_h[BB * NTOK * FFD];
__device__ float g_part[BB * 32];
// edge-attention partials
__device__ float g_eo[2 * NH * BB * 8 * 64 * 64];
__device__ float g_em[2 * NH * BB * 8 * 64];
__device__ float g_el[2 * NH * BB * 8 * 64];

// ---------------- helpers ----------------
__device__ __forceinline__ uint32_t f2bf(float x) {   // round-to-nearest-even bf16 (as u16)
    uint32_t u = __float_as_uint(x);
    return (u + 0x7FFFu + ((u >> 16) & 1u)) >> 16;
}
__device__ __forceinline__ float bf2f(uint32_t h) { return __uint_as_float(h << 16); }

__device__ __forceinline__ void mma_bf16(float* c, const uint32_t* a, const uint32_t* b) {
    asm volatile(
        "mma.sync.aligned.m16n8k16.row.col.f32.bf16.bf16.f32 "
        "{%0,%1,%2,%3}, {%4,%5,%6,%7}, {%8,%9}, {%0,%1,%2,%3};"
        : "+f"(c[0]), "+f"(c[1]), "+f"(c[2]), "+f"(c[3])
        : "r"(a[0]), "r"(a[1]), "r"(a[2]), "r"(a[3]), "r"(b[0]), "r"(b[1]));
}

// ---------------- block reduce (sum of two values) ----------------
__device__ __forceinline__ void block_reduce2(float& s, float& s2) {
#pragma unroll
    for (int off = 16; off > 0; off >>= 1) {
        s  += __shfl_down_sync(0xffffffffu, s, off);
        s2 += __shfl_down_sync(0xffffffffu, s2, off);
    }
    __shared__ float sh[16];
    int w = threadIdx.x >> 5, lane = threadIdx.x & 31;
    if (lane == 0) { sh[w] = s; sh[8 + w] = s2; }
    __syncthreads();
    if (threadIdx.x == 0) {
        float a = 0.f, b = 0.f;
#pragma unroll
        for (int i = 0; i < 8; i++) { a += sh[i]; b += sh[8 + i]; }
        sh[0] = a; sh[8] = b;
    }
    __syncthreads();
    s = sh[0]; s2 = sh[8];
}

// ---------------- embedding + LayerNorm ----------------
__global__ __launch_bounds__(256) void embed_ln_kernel(
    const float* __restrict__ e, const float* __restrict__ pos,
    const float* __restrict__ tt, const float* __restrict__ g,
    const float* __restrict__ bta, float* __restrict__ out)
{
    int row = blockIdx.x;
    int n = row & (NTOK - 1);
    size_t base = (size_t)row * DM;
    float v[3]; float s = 0.f, s2 = 0.f;
#pragma unroll
    for (int i = 0; i < 3; i++) {
        int d = threadIdx.x + i * 256;
        float val = e[base + d] + pos[(size_t)n * DM + d] + tt[d];
        v[i] = val; s += val; s2 += val * val;
    }
    block_reduce2(s, s2);
    float mean = s * (1.f / DM);
    float var = s2 * (1.f / DM) - mean * mean;
    float rstd = rsqrtf(var + 1e-12f);
#pragma unroll
    for (int i = 0; i < 3; i++) {
        int d = threadIdx.x + i * 256;
        out[base + d] = (v[i] - mean) * rstd * g[d] + bta[d];
    }
}

// ---------------- residual add + LayerNorm ----------------
__global__ __launch_bounds__(256) void ln_add_kernel(
    const float* __restrict__ r, const float* __restrict__ y,
    const float* __restrict__ g, const float* __restrict__ bta,
    float* __restrict__ out)
{
    int row = blockIdx.x;
    size_t base = (size_t)row * DM;
    float v[3]; float s = 0.f, s2 = 0.f;
#pragma unroll
    for (int i = 0; i < 3; i++) {
        int d = threadIdx.x + i * 256;
        float val = r[base + d] + y[base + d];
        v[i] = val; s += val; s2 += val * val;
    }
    block_reduce2(s, s2);
    float mean = s * (1.f / DM);
    float var = s2 * (1.f / DM) - mean * mean;
    float rstd = rsqrtf(var + 1e-12f);
#pragma unroll
    for (int i = 0; i < 3; i++) {
        int d = threadIdx.x + i * 256;
        out[base + d] = (v[i] - mean) * rstd * g[d] + bta[d];
    }
}

// ---------------- mma.sync 3x-bf16 GEMM: C = A(MxK) @ W(KxN) + bias [+GELU] ----------------
// fp32 operands split hi/lo in bf16; accumulate hh + hl + lh in fp32 via m16n8k16.
// CTA tile 128x128, K-chunk 32, double buffered. 8 warps 4x2 -> warp tile 32x64.
// Smem layouts (uint32 words, each = bf16 pair along k):
//   A2 [row 0..127][kpair 0..15] pad 20   B2 [kpair 0..15][n 0..127] pad 132
template<int GELU>
__global__ __launch_bounds__(256, 1) void mgemm_kernel(
    const float* __restrict__ A, const float* __restrict__ W,
    const float* __restrict__ bias, float* __restrict__ C,
    int M, int Nn, int K)
{
    extern __shared__ uint32_t sm[];
    const int AH = 0;        // 128*20 = 2560
    const int AL = 2560;
    const int BH = 5120;     // 16*132 = 2112
    const int BL = 7232;
    const int BUFS = 9344;

    const int t = threadIdx.x;
    const int wid = t >> 5, lane = t & 31;
    const int wr0 = (wid >> 1) * 32;
    const int wc0 = (wid & 1) * 64;
    const int lr = lane >> 2;
    const int lc = lane & 3;

    const float* Ap = A + (size_t)blockIdx.y * 128 * K;
    const float* Wp = W + blockIdx.x * 128;

    float acc[2][8][4];
#pragma unroll
    for (int i = 0; i < 2; i++)
#pragma unroll
        for (int j = 0; j < 8; j++)
#pragma unroll
            for (int q = 0; q < 4; q++) acc[i][j][q] = 0.f;

    // A: 4 tasks/thread: f = t + i*256, r = f>>3 (0..127), kq = f&7 (float4 in 32 k)
    // B: 2 tasks/thread: f = t + i*256, kp = f>>5 (0..15), nq = f&31 (float4 in 128 n)
    float4 aR[4], bR0[2], bR1[2];
    auto LDG = [&](int k0) {
#pragma unroll
        for (int i = 0; i < 4; i++) {
            int f = t + i * 256;
            aR[i] = *(const float4*)(Ap + (size_t)(f >> 3) * K + k0 + (f & 7) * 4);
        }
#pragma unroll
        for (int i = 0; i < 2; i++) {
            int f = t + i * 256;
            int kp = f >> 5, nq = f & 31;
            bR0[i] = *(const float4*)(Wp + (size_t)(k0 + kp * 2) * Nn + nq * 4);
            bR1[i] = *(const float4*)(Wp + (size_t)(k0 + kp * 2 + 1) * Nn + nq * 4);
        }
    };
    auto STS = [&](int b) {
        uint32_t* base = sm + b * BUFS;
#pragma unroll
        for (int i = 0; i < 4; i++) {
            int f = t + i * 256;
            int r = f >> 3, kq = f & 7;
            const float* v = (const float*)&aR[i];
            uint32_t h[4], l[4];
#pragma unroll
            for (int j = 0; j < 4; j++) {
                h[j] = f2bf(v[j]);
                l[j] = f2bf(v[j] - bf2f(h[j]));
            }
            uint2 uh = make_uint2(h[0] | (h[1] << 16), h[2] | (h[3] << 16));
            uint2 ul = make_uint2(l[0] | (l[1] << 16), l[2] | (l[3] << 16));
            *(uint2*)(base + AH + r * 20 + kq * 2) = uh;
            *(uint2*)(base + AL + r * 20 + kq * 2) = ul;
        }
#pragma unroll
        for (int i = 0; i < 2; i++) {
            int f = t + i * 256;
            int kp = f >> 5, nq = f & 31;
            const float* w0 = (const float*)&bR0[i];
            const float* w1 = (const float*)&bR1[i];
            uint4 uh, ul;
            uint32_t* ph = (uint32_t*)&uh;
            uint32_t* pl = (uint32_t*)&ul;
#pragma unroll
            for (int j = 0; j < 4; j++) {
                uint32_t h0 = f2bf(w0[j]), h1 = f2bf(w1[j]);
                ph[j] = h0 | (h1 << 16);
                uint32_t l0 = f2bf(w0[j] - bf2f(h0)), l1 = f2bf(w1[j] - bf2f(h1));
                pl[j] = l0 | (l1 << 16);
            }
            *(uint4*)(base + BH + kp * 132 + nq * 4) = uh;
            *(uint4*)(base + BL + kp * 132 + nq * 4) = ul;
        }
    };

    auto COMP = [&](int b) {
        const uint32_t* ah = sm + b * BUFS + AH;
        const uint32_t* al = sm + b * BUFS + AL;
        const uint32_t* bh = sm + b * BUFS + BH;
        const uint32_t* bl = sm + b * BUFS + BL;
#pragma unroll
        for (int s = 0; s < 2; s++) {
            int kb = s * 8;  // kpair base for this k16 step
            uint32_t af[2][4], bf[8][2];
            // ---- hh ----
#pragma unroll
            for (int mt = 0; mt < 2; mt++) {
                int r = wr0 + mt * 16 + lr;
                af[mt][0] = ah[r * 20 + kb + lc];
                af[mt][1] = ah[(r + 8) * 20 + kb + lc];
                af[mt][2] = ah[r * 20 + kb + lc + 4];
                af[mt][3] = ah[(r + 8) * 20 + kb + lc + 4];
            }
#pragma unroll
            for (int nt = 0; nt < 8; nt++) {
                int n = wc0 + nt * 8 + lr;
                bf[nt][0] = bh[(kb + lc) * 132 + n];
                bf[nt][1] = bh[(kb + lc + 4) * 132 + n];
            }
#pragma unroll
            for (int mt = 0; mt < 2; mt++)
#pragma unroll
                for (int nt = 0; nt < 8; nt++) mma_bf16(acc[mt][nt], af[mt], bf[nt]);
            // ---- hl (reuse a_hi) ----
#pragma unroll
            for (int nt = 0; nt < 8; nt++) {
                int n = wc0 + nt * 8 + lr;
                bf[nt][0] = bl[(kb + lc) * 132 + n];
                bf[nt][1] = bl[(kb + lc + 4) * 132 + n];
            }
#pragma unroll
            for (int mt = 0; mt < 2; mt++)
#pragma unroll
                for (int nt = 0; nt < 8; nt++) mma_bf16(acc[mt][nt], af[mt], bf[nt]);
            // ---- lh ----
#pragma unroll
            for (int mt = 0; mt < 2; mt++) {
                int r = wr0 + mt * 16 + lr;
                af[mt][0] = al[r * 20 + kb + lc];
                af[mt][1] = al[(r + 8) * 20 + kb + lc];
                af[mt][2] = al[r * 20 + kb + lc + 4];
                af[mt][3] = al[(r + 8) * 20 + kb + lc + 4];
            }
#pragma unroll
            for (int nt = 0; nt < 8; nt++) {
                int n = wc0 + nt * 8 + lr;
                bf[nt][0] = bh[(kb + lc) * 132 + n];
                bf[nt][1] = bh[(kb + lc + 4) * 132 + n];
            }
#pragma unroll
            for (int mt = 0; mt < 2; mt++)
#pragma unroll
                for (int nt = 0; nt < 8; nt++) mma_bf16(acc[mt][nt], af[mt], bf[nt]);
        }
    };

    const int nch = K / 32;
    LDG(0); STS(0);
    __syncthreads();
    for (int c = 0; c < nch; c++) {
        if (c + 1 < nch) LDG((c + 1) * 32);
        COMP(c & 1);
        if (c + 1 < nch) { STS((c + 1) & 1); __syncthreads(); }
    }

    // epilogue
#pragma unroll
    for (int mt = 0; mt < 2; mt++) {
        int r = blockIdx.y * 128 + wr0 + mt * 16 + lr;
#pragma unroll
        for (int nt = 0; nt < 8; nt++) {
            int cc = blockIdx.x * 128 + wc0 + nt * 8 + lc * 2;
            float b0 = bias[cc], b1 = bias[cc + 1];
            float v[4];
            v[0] = acc[mt][nt][0] + b0; v[1] = acc[mt][nt][1] + b1;
            v[2] = acc[mt][nt][2] + b0; v[3] = acc[mt][nt][3] + b1;
            if (GELU) {
#pragma unroll
                for (int q = 0; q < 4; q++) {
                    float x3 = v[q] * v[q] * v[q];
                    v[q] = 0.5f * v[q] * (1.f + tanhf(0.7978845608028654f * (v[q] + 0.044715f * x3)));
                }
            }
            *(float2*)(C + (size_t)r * Nn + cc) = make_float2(v[0], v[1]);
            *(float2*)(C + (size_t)(r + 8) * Nn + cc) = make_float2(v[2], v[3]);
        }
    }
}

// ---------------- block-sparse attention: middle q-blocks ----------------
__global__ __launch_bounds__(256) void attn_mid_kernel(
    const float* __restrict__ q, const float* __restrict__ k,
    const float* __restrict__ v, const int* __restrict__ rb,
    float* __restrict__ out)
{
    extern __shared__ float smf[];
    float* qs = smf;
    float* ks = smf + 64 * 65;
    float* vs = smf + 2 * 64 * 65;
    float* ps = smf + 3 * 64 * 65;
    int m = blockIdx.x + 1, h = blockIdx.y, b = blockIdx.z;
    int t = threadIdx.x;
    int row = t >> 2, c0 = (t & 3) << 4;

    const float* qb = q + (size_t)(b * NTOK + m * BS) * DM + h * DHEAD;
    for (int i = t; i < 4096; i += 256) {
        int r = i >> 6, c = i & 63;
        qs[r * 65 + c] = qb[(size_t)r * DM + c];
    }
    int list[8];
    {
        const int* r3 = rb + (h * NBLK + m) * RR;
        list[0] = 0; list[1] = NBLK - 1;
        list[2] = m - 1; list[3] = m; list[4] = m + 1;
        list[5] = r3[0]; list[6] = r3[1]; list[7] = r3[2];
    }
    float mrow = -3e38f, lrow = 0.f;
    float oacc[16];
#pragma unroll
    for (int i = 0; i < 16; i++) oacc[i] = 0.f;
    __syncthreads();

    const float scale = 0.125f;
    for (int kb = 0; kb < 8; kb++) {
        int blk = list[kb];
        const float* kbp = k + (size_t)(b * NTOK + blk * BS) * DM + h * DHEAD;
        const float* vbp = v + (size_t)(b * NTOK + blk * BS) * DM + h * DHEAD;
        for (int i = t; i < 4096; i += 256) {
            int r = i >> 6, c = i & 63;
            ks[r * 65 + c] = kbp[(size_t)r * DM + c];
            vs[r * 65 + c] = vbp[(size_t)r * DM + c];
        }
        __syncthreads();

        float s[16];
#pragma unroll
        for (int j = 0; j < 16; j++) s[j] = 0.f;
        for (int d = 0; d < 64; d++) {
            float qv = qs[row * 65 + d];
#pragma unroll
            for (int j = 0; j < 16; j++) s[j] += qv * ks[(c0 + j) * 65 + d];
        }
        float tmax = -3e38f;
#pragma unroll
        for (int j = 0; j < 16; j++) { s[j] *= scale; tmax = fmaxf(tmax, s[j]); }
        tmax = fmaxf(tmax, __shfl_xor_sync(0xffffffffu, tmax, 1));
        tmax = fmaxf(tmax, __shfl_xor_sync(0xffffffffu, tmax, 2));
        float newm = fmaxf(mrow, tmax);
        float corr = __expf(mrow - newm);
        float psum = 0.f;
#pragma unroll
        for (int j = 0; j < 16; j++) {
            float p = __expf(s[j] - newm);
            ps[row * 65 + c0 + j] = p;
            psum += p;
        }
        psum += __shfl_xor_sync(0xffffffffu, psum, 1);
        psum += __shfl_xor_sync(0xffffffffu, psum, 2);
        lrow = lrow * corr + psum;
        mrow = newm;
#pragma unroll
        for (int i = 0; i < 16; i++) oacc[i] *= corr;
        __syncwarp();
        for (int j = 0; j < 64; j++) {
            float pv = ps[row * 65 + j];
#pragma unroll
            for (int d2 = 0; d2 < 16; d2++) oacc[d2] += pv * vs[j * 65 + c0 + d2];
        }
        __syncthreads();
    }
    float inv = 1.f / lrow;
    float* ob = out + (size_t)(b * NTOK + m * BS + row) * DM + h * DHEAD + c0;
#pragma unroll
    for (int d2 = 0; d2 < 16; d2++) ob[d2] = oacc[d2] * inv;
}

// ---------------- edge q-blocks: split-KV partials ----------------
__global__ __launch_bounds__(256) void attn_edge_kernel(
    const float* __restrict__ q, const float* __restrict__ k,
    const float* __restrict__ v,
    float* __restrict__ eo, float* __restrict__ em, float* __restrict__ el)
{
    extern __shared__ float smf[];
    float* qs = smf;
    float* ks = smf + 64 * 65;
    float* vs = smf + 2 * 64 * 65;
    float* ps = smf + 3 * 64 * 65;
    int s0 = blockIdx.x, h = blockIdx.y;
    int b = blockIdx.z >> 1, e = blockIdx.z & 1;
    int m = e ? (NBLK - 1) : 0;
    int t = threadIdx.x;
    int row = t >> 2, c0 = (t & 3) << 4;

    const float* qb = q + (size_t)(b * NTOK + m * BS) * DM + h * DHEAD;
    for (int i = t; i < 4096; i += 256) {
        int r = i >> 6, c = i & 63;
        qs[r * 65 + c] = qb[(size_t)r * DM + c];
    }
    float mrow = -3e38f, lrow = 0.f;
    float oacc[16];
#pragma unroll
    for (int i = 0; i < 16; i++) oacc[i] = 0.f;
    __syncthreads();

    const float scale = 0.125f;
    for (int kb = s0 * 8; kb < s0 * 8 + 8; kb++) {
        const float* kbp = k + (size_t)(b * NTOK + kb * BS) * DM + h * DHEAD;
        const float* vbp = v + (size_t)(b * NTOK + kb * BS) * DM + h * DHEAD;
        for (int i = t; i < 4096; i += 256) {
            int r = i >> 6, c = i & 63;
            ks[r * 65 + c] = kbp[(size_t)r * DM + c];
            vs[r * 65 + c] = vbp[(size_t)r * DM + c];
        }
        __syncthreads();

        float s[16];
#pragma unroll
        for (int j = 0; j < 16; j++) s[j] = 0.f;
        for (int d = 0; d < 64; d++) {
            float qv = qs[row * 65 + d];
#pragma unroll
            for (int j = 0; j < 16; j++) s[j] += qv * ks[(c0 + j) * 65 + d];
        }
        float tmax = -3e38f;
#pragma unroll
        for (int j = 0; j < 16; j++) { s[j] *= scale; tmax = fmaxf(tmax, s[j]); }
        tmax = fmaxf(tmax, __shfl_xor_sync(0xffffffffu, tmax, 1));
        tmax = fmaxf(tmax, __shfl_xor_sync(0xffffffffu, tmax, 2));
        float newm = fmaxf(mrow, tmax);
        float corr = __expf(mrow - newm);
        float psum = 0.f;
#pragma unroll
        for (int j = 0; j < 16; j++) {
            float p = __expf(s[j] - newm);
            ps[row * 65 + c0 + j] = p;
            psum += p;
        }
        psum += __shfl_xor_sync(0xffffffffu, psum, 1);
        psum += __shfl_xor_sync(0xffffffffu, psum, 2);
        lrow = lrow * corr + psum;
        mrow = newm;
#pragma unroll
        for (int i = 0; i < 16; i++) oacc[i] *= corr;
        __syncwarp();
        for (int j = 0; j < 64; j++) {
            float pv = ps[row * 65 + j];
#pragma unroll
            for (int d2 = 0; d2 < 16; d2++) oacc[d2] += pv * vs[j * 65 + c0 + d2];
        }
        __syncthreads();
    }
    size_t pbase = ((((size_t)e * NH + h) * BB + b) * 8 + s0);
    float* op = eo + pbase * 4096 + row * 64 + c0;
#pragma unroll
    for (int d2 = 0; d2 < 16; d2++) op[d2] = oacc[d2];
    if ((t & 3) == 0) {
        em[pbase * 64 + row] = mrow;
        el[pbase * 64 + row] = lrow;
    }
}

__global__ __launch_bounds__(256) void attn_edge_combine_kernel(
    const float* __restrict__ eo, const float* __restrict__ em,
    const float* __restrict__ el, float* __restrict__ out)
{
    int e = blockIdx.x, h = blockIdx.y, b = blockIdx.z;
    int m = e ? (NBLK - 1) : 0;
    int t = threadIdx.x;
    int row = t >> 2, c0 = (t & 3) << 4;
    size_t base0 = ((((size_t)e * NH + h) * BB + b) * 8);

    float M = -3e38f;
#pragma unroll
    for (int s = 0; s < 8; s++) M = fmaxf(M, em[(base0 + s) * 64 + row]);
    float L = 0.f;
    float w[8];
#pragma unroll
    for (int s = 0; s < 8; s++) {
        w[s] = __expf(em[(base0 + s) * 64 + row] - M);
        L += w[s] * el[(base0 + s) * 64 + row];
    }
    float acc[16];
#pragma unroll
    for (int j = 0; j < 16; j++) acc[j] = 0.f;
#pragma unroll
    for (int s = 0; s < 8; s++) {
        const float* op = eo + (base0 + s) * 4096 + row * 64 + c0;
#pragma unroll
        for (int j = 0; j < 16; j++) acc[j] += w[s] * op[j];
    }
    float inv = 1.f / L;
    float* ob = out + (size_t)(b * NTOK + m * BS + row) * DM + h * DHEAD + c0;
#pragma unroll
    for (int j = 0; j < 16; j++) ob[j] = acc[j] * inv;
}

// ---------------- final pooled head ----------------
__global__ __launch_bounds__(256) void final_part_kernel(
    const float* __restrict__ x, const float* __restrict__ fcw,
    float* __restrict__ part)
{
    int c = blockIdx.x, b = blockIdx.y;
    float acc = 0.f;
#pragma unroll
    for (int i = 0; i < 3; i++) {
        int d = threadIdx.x + i * 256;
        float s = 0.f;
        int n0 = c * 128;
        for (int n = n0; n < n0 + 128; n++)
            s += x[((size_t)b * NTOK + n) * DM + d];
        acc += s * fcw[d];
    }
    float dummy = 0.f;
    block_reduce2(acc, dummy);
    if (threadIdx.x == 0) part[b * 32 + c] = acc;
}

__global__ void final_sum_kernel(const float* __restrict__ part,
                                 const float* __restrict__ fcb,
                                 float* __restrict__ out)
{
    int t = threadIdx.x;
    int b = t >> 5, lane = t & 31;
    float v = part[b * 32 + lane];
#pragma unroll
    for (int off = 16; off > 0; off >>= 1)
        v += __shfl_down_sync(0xffffffffu, v, off);
    if (lane == 0) out[b] = v * (1.f / NTOK) + fcb[0];
}

// ---------------- driver ----------------
extern "C" void kernel_launch(void* const* d_in, const int* in_sizes, int n_in,
                              void* d_out, int out_size)
{
    const float* inputs = (const float*)d_in[0];
    const int*   rb_all = (const int*)d_in[1];
    const float* pos = (const float*)d_in[2];
    const float* tt  = (const float*)d_in[3];
    const float* eg  = (const float*)d_in[4];
    const float* eb  = (const float*)d_in[5];
    const float* Wq  = (const float*)d_in[6];  const float* bq = (const float*)d_in[7];
    const float* Wk  = (const float*)d_in[8];  const float* bk = (const float*)d_in[9];
    const float* Wv  = (const float*)d_in[10]; const float* bv = (const float*)d_in[11];
    const float* Wo  = (const float*)d_in[12]; const float* bo = (const float*)d_in[13];
    const float* l1g = (const float*)d_in[14]; const float* l1b = (const float*)d_in[15];
    const float* Wi  = (const float*)d_in[16]; const float* bi = (const float*)d_in[17];
    const float* Wd  = (const float*)d_in[18]; const float* bd = (const float*)d_in[19];
    const float* l2g = (const float*)d_in[20]; const float* l2b = (const float*)d_in[21];
    const float* fcw = (const float*)d_in[22]; const float* fcb = (const float*)d_in[23];
    float* out = (float*)d_out;

    float *x, *q, *k, *v, *ctx, *tb, *a, *hh, *part, *eo, *em, *el;
    cudaGetSymbolAddress((void**)&x,   g_x);
    cudaGetSymbolAddress((void**)&q,   g_q);
    cudaGetSymbolAddress((void**)&k,   g_k);
    cudaGetSymbolAddress((void**)&v,   g_v);
    cudaGetSymbolAddress((void**)&ctx, g_ctx);
    cudaGetSymbolAddress((void**)&tb,  g_t);
    cudaGetSymbolAddress((void**)&a,   g_a);
    cudaGetSymbolAddress((void**)&hh,  g_h);
    cudaGetSymbolAddress((void**)&part, g_part);
    cudaGetSymbolAddress((void**)&eo,  g_eo);
    cudaGetSymbolAddress((void**)&em,  g_em);
    cudaGetSymbolAddress((void**)&el,  g_el);

    const int ATTN_SMEM = 4 * 64 * 65 * 4;       // 66560 bytes
    const int GEMM_SMEM = 2 * 9344 * 4;          // 74752 bytes
    cudaFuncSetAttribute(attn_mid_kernel, cudaFuncAttributeMaxDynamicSharedMemorySize, ATTN_SMEM);
    cudaFuncSetAttribute(attn_edge_kernel, cudaFuncAttributeMaxDynamicSharedMemorySize, ATTN_SMEM);
    cudaFuncSetAttribute(mgemm_kernel<0>, cudaFuncAttributeMaxDynamicSharedMemorySize, GEMM_SMEM);
    cudaFuncSetAttribute(mgemm_kernel<1>, cudaFuncAttributeMaxDynamicSharedMemorySize, GEMM_SMEM);

    const int MROWS = BB * NTOK;                 // 8192
    dim3 gemm_dd(DM / 128, MROWS / 128);         // (6, 64)
    dim3 gemm_ff(FFD / 128, MROWS / 128);        // (24, 64)

    embed_ln_kernel<<<MROWS, 256>>>(inputs, pos, tt, eg, eb, x);

    for (int l = 0; l < NL; l++) {
        size_t wdd = (size_t)l * DM * DM;
        mgemm_kernel<0><<<gemm_dd, 256, GEMM_SMEM>>>(x, Wq + wdd, bq + l * DM, q, MROWS, DM, DM);
        mgemm_kernel<0><<<gemm_dd, 256, GEMM_SMEM>>>(x, Wk + wdd, bk + l * DM, k, MROWS, DM, DM);
        mgemm_kernel<0><<<gemm_dd, 256, GEMM_SMEM>>>(x, Wv + wdd, bv + l * DM, v, MROWS, DM, DM);

        attn_mid_kernel<<<dim3(NBLK - 2, NH, BB), 256, ATTN_SMEM>>>(
            q, k, v, rb_all + l * NH * NBLK * RR, ctx);
        attn_edge_kernel<<<dim3(8, NH, BB * 2), 256, ATTN_SMEM>>>(q, k, v, eo, em, el);
        attn_edge_combine_kernel<<<dim3(2, NH, BB), 256>>>(eo, em, el, ctx);

        mgemm_kernel<0><<<gemm_dd, 256, GEMM_SMEM>>>(ctx, Wo + wdd, bo + l * DM, tb, MROWS, DM, DM);
        ln_add_kernel<<<MROWS, 256>>>(x, tb, l1g + l * DM, l1b + l * DM, a);

        mgemm_kernel<1><<<gemm_ff, 256, GEMM_SMEM>>>(a, Wi + (size_t)l * DM * FFD, bi + l * FFD,
                                                     hh, MROWS, FFD, DM);
        mgemm_kernel<0><<<gemm_dd, 256, GEMM_SMEM>>>(hh, Wd + (size_t)l * FFD * DM, bd + l * DM,
                                                     tb, MROWS, DM, FFD);
        ln_add_kernel<<<MROWS, 256>>>(a, tb, l2g + l * DM, l2b + l * DM, x);
    }

    final_part_kernel<<<dim3(32, BB), 256>>>(x, fcw, part);
    final_sum_kernel<<<1, 64>>>(part, fcb, out);
}

// round 5
// speedup vs baseline: 2.3675x; 1.3811x over previous
#include <cuda_runtime.h>
#include <math.h>
#include <stdint.h>

#define BB 2
#define NTOK 4096
#define DM 768
#define NH 12
#define DHEAD 64
#define NBLK 64
#define BS 64
#define FFD 3072
#define NL 2
#define RR 3

// ---------------- scratch (device globals; no allocation) ----------------
__device__ float g_x[BB * NTOK * DM];
__device__ float g_q[BB * NTOK * DM];
__device__ float g_k[BB * NTOK * DM];
__device__ float g_v[BB * NTOK * DM];
__device__ float g_ctx[BB * NTOK * DM];
__device__ float g_t[BB * NTOK * DM];
__device__ float g_a[BB * NTOK * DM];
__device__ float g_h[BB * NTOK * FFD];
__device__ float g_part[BB * 32];
// packed bf16 hi/lo buffers (k-pair packed uint32)
__device__ uint32_t g_ah[BB * NTOK * FFD / 2];   // activations hi  [M][K/2]
__device__ uint32_t g_al[BB * NTOK * FFD / 2];   // activations lo
__device__ uint32_t g_wh[DM * FFD / 2];          // weights hi      [N][K/2]
__device__ uint32_t g_wl[DM * FFD / 2];          // weights lo
// edge-attention partials
__device__ float g_eo[2 * NH * BB * 8 * 64 * 64];
__device__ float g_em[2 * NH * BB * 8 * 64];
__device__ float g_el[2 * NH * BB * 8 * 64];

// ---------------- helpers ----------------
__device__ __forceinline__ uint32_t f2bf(float x) {
    uint32_t u = __float_as_uint(x);
    return (u + 0x7FFFu + ((u >> 16) & 1u)) >> 16;
}
__device__ __forceinline__ float bf2f(uint32_t h) { return __uint_as_float(h << 16); }

__device__ __forceinline__ uint32_t smem_u32(const void* p) {
    uint32_t a;
    asm("{ .reg .u64 t; cvta.to.shared.u64 t, %1; cvt.u32.u64 %0, t; }" : "=r"(a) : "l"(p));
    return a;
}
__device__ __forceinline__ void cp16(uint32_t saddr, const void* g) {
    asm volatile("cp.async.ca.shared.global [%0], [%1], 16;" :: "r"(saddr), "l"(g));
}
#define CP_COMMIT() asm volatile("cp.async.commit_group;" ::: "memory")
#define CP_WAIT1()  asm volatile("cp.async.wait_group 1;" ::: "memory")
#define CP_WAIT0()  asm volatile("cp.async.wait_group 0;" ::: "memory")

__device__ __forceinline__ void ldmat_x4(uint32_t* r, uint32_t saddr) {
    asm volatile("ldmatrix.sync.aligned.m8n8.x4.shared.b16 {%0,%1,%2,%3}, [%4];"
                 : "=r"(r[0]), "=r"(r[1]), "=r"(r[2]), "=r"(r[3]) : "r"(saddr));
}
__device__ __forceinline__ void mma_bf16(float* c, const uint32_t* a, const uint32_t* b) {
    asm volatile(
        "mma.sync.aligned.m16n8k16.row.col.f32.bf16.bf16.f32 "
        "{%0,%1,%2,%3}, {%4,%5,%6,%7}, {%8,%9}, {%0,%1,%2,%3};"
        : "+f"(c[0]), "+f"(c[1]), "+f"(c[2]), "+f"(c[3])
        : "r"(a[0]), "r"(a[1]), "r"(a[2]), "r"(a[3]), "r"(b[0]), "r"(b[1]));
}

// ---------------- pack kernels ----------------
// activations: fp32 [M][K] -> hi/lo uint32 [M][K/2] (k-pair packed)
__global__ __launch_bounds__(256) void pack_act_kernel(
    const float* __restrict__ in, uint32_t* __restrict__ hi,
    uint32_t* __restrict__ lo, int n)
{
    int i = blockIdx.x * 256 + threadIdx.x;
    if (i < n) {
        float2 v = ((const float2*)in)[i];
        uint32_t h0 = f2bf(v.x), h1 = f2bf(v.y);
        hi[i] = h0 | (h1 << 16);
        lo[i] = f2bf(v.x - bf2f(h0)) | (f2bf(v.y - bf2f(h1)) << 16);
    }
}

// weights: fp32 W[K][N] -> hi/lo uint32 [N][K/2] (transpose + k-pair pack)
__global__ __launch_bounds__(256) void pack_w_kernel(
    const float* __restrict__ W, uint32_t* __restrict__ hi,
    uint32_t* __restrict__ lo, int K, int N)
{
    __shared__ float tile[64][33];
    int k0 = blockIdx.y * 64, n0 = blockIdx.x * 32;
    int t = threadIdx.x;
    for (int i = t; i < 64 * 32; i += 256) {
        int r = i >> 5, c = i & 31;
        tile[r][c] = W[(size_t)(k0 + r) * N + n0 + c];
    }
    __syncthreads();
    int Kh = K >> 1;
    for (int i = t; i < 32 * 32; i += 256) {
        int n = i >> 5, kp = i & 31;
        float a = tile[kp * 2][n], b = tile[kp * 2 + 1][n];
        uint32_t h0 = f2bf(a), h1 = f2bf(b);
        size_t o = (size_t)(n0 + n) * Kh + (k0 >> 1) + kp;
        hi[o] = h0 | (h1 << 16);
        lo[o] = f2bf(a - bf2f(h0)) | (f2bf(b - bf2f(h1)) << 16);
    }
}

// ---------------- block reduce ----------------
__device__ __forceinline__ void block_reduce2(float& s, float& s2) {
#pragma unroll
    for (int off = 16; off > 0; off >>= 1) {
        s  += __shfl_down_sync(0xffffffffu, s, off);
        s2 += __shfl_down_sync(0xffffffffu, s2, off);
    }
    __shared__ float sh[16];
    int w = threadIdx.x >> 5, lane = threadIdx.x & 31;
    if (lane == 0) { sh[w] = s; sh[8 + w] = s2; }
    __syncthreads();
    if (threadIdx.x == 0) {
        float a = 0.f, b = 0.f;
#pragma unroll
        for (int i = 0; i < 8; i++) { a += sh[i]; b += sh[8 + i]; }
        sh[0] = a; sh[8] = b;
    }
    __syncthreads();
    s = sh[0]; s2 = sh[8];
}

// ---------------- embedding + LayerNorm ----------------
__global__ __launch_bounds__(256) void embed_ln_kernel(
    const float* __restrict__ e, const float* __restrict__ pos,
    const float* __restrict__ tt, const float* __restrict__ g,
    const float* __restrict__ bta, float* __restrict__ out)
{
    int row = blockIdx.x;
    int n = row & (NTOK - 1);
    size_t base = (size_t)row * DM;
    float v[3]; float s = 0.f, s2 = 0.f;
#pragma unroll
    for (int i = 0; i < 3; i++) {
        int d = threadIdx.x + i * 256;
        float val = e[base + d] + pos[(size_t)n * DM + d] + tt[d];
        v[i] = val; s += val; s2 += val * val;
    }
    block_reduce2(s, s2);
    float mean = s * (1.f / DM);
    float var = s2 * (1.f / DM) - mean * mean;
    float rstd = rsqrtf(var + 1e-12f);
#pragma unroll
    for (int i = 0; i < 3; i++) {
        int d = threadIdx.x + i * 256;
        out[base + d] = (v[i] - mean) * rstd * g[d] + bta[d];
    }
}

__global__ __launch_bounds__(256) void ln_add_kernel(
    const float* __restrict__ r, const float* __restrict__ y,
    const float* __restrict__ g, const float* __restrict__ bta,
    float* __restrict__ out)
{
    int row = blockIdx.x;
    size_t base = (size_t)row * DM;
    float v[3]; float s = 0.f, s2 = 0.f;
#pragma unroll
    for (int i = 0; i < 3; i++) {
        int d = threadIdx.x + i * 256;
        float val = r[base + d] + y[base + d];
        v[i] = val; s += val; s2 += val * val;
    }
    block_reduce2(s, s2);
    float mean = s * (1.f / DM);
    float var = s2 * (1.f / DM) - mean * mean;
    float rstd = rsqrtf(var + 1e-12f);
#pragma unroll
    for (int i = 0; i < 3; i++) {
        int d = threadIdx.x + i * 256;
        out[base + d] = (v[i] - mean) * rstd * g[d] + bta[d];
    }
}

// ---------------- packed bf16 3-pass GEMM via cp.async + ldmatrix ----------------
// A: [M][Kh] hi/lo packed, B: [N][Kh] hi/lo packed (N-major, k-contiguous).
// CTA tile 128x128, chunk = 16 kpairs (K=32). 8 warps 4x2 -> warp tile 32x64.
template<int GELU>
__global__ __launch_bounds__(256) void mgemm_kernel(
    const uint32_t* __restrict__ Ah, const uint32_t* __restrict__ Al,
    const uint32_t* __restrict__ Bh, const uint32_t* __restrict__ Bl,
    const float* __restrict__ bias, float* __restrict__ C,
    int Kh, int Nn)
{
    extern __shared__ uint32_t sm[];
    uint32_t smem_addr = smem_u32(sm);
    // per-buffer u32 offsets (each region 128 rows x 20 pitch)
    const int RAH = 0, RAL = 2560, RBH = 5120, RBL = 7680;
    const uint32_t BUF_BYTES = 40960;

    const int t = threadIdx.x;
    const int wid = t >> 5, lane = t & 31;
    const int wr0 = (wid >> 1) * 32;
    const int wc0 = (wid & 1) * 64;
    const int lr = lane >> 2, lc = lane & 3;
    const int aRow0 = blockIdx.y * 128;
    const int bRow0 = blockIdx.x * 128;

    float acc[2][8][4];
#pragma unroll
    for (int i = 0; i < 2; i++)
#pragma unroll
        for (int j = 0; j < 8; j++)
#pragma unroll
            for (int q = 0; q < 4; q++) acc[i][j][q] = 0.f;

    auto ISSUE = [&](int c) {
        uint32_t sb = smem_addr + (uint32_t)(c & 1) * BUF_BYTES;
        int kp0 = c * 16;
#pragma unroll
        for (int i = 0; i < 8; i++) {
            int reg = i >> 1;
            int f = t + (i & 1) * 256;
            int row = f >> 2, w4 = f & 3;
            const uint32_t* g;
            if (reg == 0)      g = Ah + (size_t)(aRow0 + row) * Kh + kp0 + w4 * 4;
            else if (reg == 1) g = Al + (size_t)(aRow0 + row) * Kh + kp0 + w4 * 4;
            else if (reg == 2) g = Bh + (size_t)(bRow0 + row) * Kh + kp0 + w4 * 4;
            else               g = Bl + (size_t)(bRow0 + row) * Kh + kp0 + w4 * 4;
            cp16(sb + (uint32_t)((reg == 0 ? RAH : reg == 1 ? RAL : reg == 2 ? RBH : RBL)
                                 + row * 20 + w4 * 4) * 4u, g);
        }
        CP_COMMIT();
    };

    uint32_t af[2][4], bf[8][2];
    auto LDA = [&](uint32_t sb, int regOff, int kb) {
#pragma unroll
        for (int mt = 0; mt < 2; mt++) {
            uint32_t addr = sb + (uint32_t)((regOff + (wr0 + mt * 16 + (lane & 15)) * 20
                                            + kb + ((lane >> 4) << 2)) * 4);
            ldmat_x4(af[mt], addr);
        }
    };
    auto LDB = [&](uint32_t sb, int regOff, int kb) {
#pragma unroll
        for (int nt0 = 0; nt0 < 8; nt0 += 2) {
            uint32_t regs[4];
            uint32_t addr = sb + (uint32_t)((regOff + (wc0 + nt0 * 8 + ((lane & 16) >> 1)
                                            + (lane & 7)) * 20 + kb + ((lane & 8) >> 1)) * 4);
            ldmat_x4(regs, addr);
            bf[nt0][0] = regs[0]; bf[nt0][1] = regs[1];
            bf[nt0 + 1][0] = regs[2]; bf[nt0 + 1][1] = regs[3];
        }
    };
    auto MMAS = [&]() {
#pragma unroll
        for (int mt = 0; mt < 2; mt++)
#pragma unroll
            for (int nt = 0; nt < 8; nt++) mma_bf16(acc[mt][nt], af[mt], bf[nt]);
    };
    auto COMP = [&](int buf) {
        uint32_t sb = smem_addr + (uint32_t)buf * BUF_BYTES;
#pragma unroll
        for (int s = 0; s < 2; s++) {
            int kb = s * 8;
            LDA(sb, RAH, kb); LDB(sb, RBH, kb); MMAS();   // hh
            LDB(sb, RBL, kb); MMAS();                     // hl
            LDA(sb, RAL, kb); LDB(sb, RBH, kb); MMAS();   // lh
        }
    };

    const int nch = Kh / 16;
    ISSUE(0);
    if (nch > 1) ISSUE(1);
    for (int c = 0; c < nch; c++) {
        if (c + 1 < nch) { CP_WAIT1(); } else { CP_WAIT0(); }
        __syncthreads();
        COMP(c & 1);
        __syncthreads();
        if (c + 2 < nch) ISSUE(c + 2);
    }

    // epilogue
#pragma unroll
    for (int mt = 0; mt < 2; mt++) {
        int r = blockIdx.y * 128 + wr0 + mt * 16 + lr;
#pragma unroll
        for (int nt = 0; nt < 8; nt++) {
            int cc = blockIdx.x * 128 + wc0 + nt * 8 + lc * 2;
            float b0 = bias[cc], b1 = bias[cc + 1];
            float v[4];
            v[0] = acc[mt][nt][0] + b0; v[1] = acc[mt][nt][1] + b1;
            v[2] = acc[mt][nt][2] + b0; v[3] = acc[mt][nt][3] + b1;
            if (GELU) {
#pragma unroll
                for (int q = 0; q < 4; q++) {
                    float z = 0.7978845608028654f * (v[q] + 0.044715f * v[q] * v[q] * v[q]);
                    float e = __expf(2.f * z);
                    float th = 1.f - 2.f / (e + 1.f);
                    v[q] = 0.5f * v[q] * (1.f + th);
                }
            }
            *(float2*)(C + (size_t)r * Nn + cc) = make_float2(v[0], v[1]);
            *(float2*)(C + (size_t)(r + 8) * Nn + cc) = make_float2(v[2], v[3]);
        }
    }
}

// ---------------- attention flash step (shared by mid/edge) ----------------
// pitch 68. QK cols: c = qq + 4j. PV/out cols: c0 = qq*16 + [0..15].
__device__ __forceinline__ void flash_step(
    const float* __restrict__ kbp, const float* __restrict__ vbp,
    const float* qs, float* ks, float* vs, float* ps,
    int t, int row, int qq, int c0,
    float& mrow, float& lrow, float* oacc)
{
    for (int i = t * 4; i < 4096; i += 1024) {
        int r = i >> 6, c = i & 63;
        *(float4*)&ks[r * 68 + c] = *(const float4*)&kbp[(size_t)r * DM + c];
        *(float4*)&vs[r * 68 + c] = *(const float4*)&vbp[(size_t)r * DM + c];
    }
    __syncthreads();

    float s[16];
#pragma unroll
    for (int j = 0; j < 16; j++) s[j] = 0.f;
    for (int d = 0; d < 64; d += 4) {
        float4 qv = *(const float4*)&qs[row * 68 + d];
#pragma unroll
        for (int j = 0; j < 16; j++) {
            float4 kv = *(const float4*)&ks[(qq + 4 * j) * 68 + d];
            s[j] += qv.x * kv.x + qv.y * kv.y + qv.z * kv.z + qv.w * kv.w;
        }
    }
    const float scale = 0.125f;
    float tmax = -3e38f;
#pragma unroll
    for (int j = 0; j < 16; j++) { s[j] *= scale; tmax = fmaxf(tmax, s[j]); }
    tmax = fmaxf(tmax, __shfl_xor_sync(0xffffffffu, tmax, 1));
    tmax = fmaxf(tmax, __shfl_xor_sync(0xffffffffu, tmax, 2));
    float newm = fmaxf(mrow, tmax);
    float corr = __expf(mrow - newm);
    float psum = 0.f;
#pragma unroll
    for (int j = 0; j < 16; j++) {
        float p = __expf(s[j] - newm);
        ps[row * 68 + qq + 4 * j] = p;
        psum += p;
    }
    psum += __shfl_xor_sync(0xffffffffu, psum, 1);
    psum += __shfl_xor_sync(0xffffffffu, psum, 2);
    lrow = lrow * corr + psum;
    mrow = newm;
#pragma unroll
    for (int i = 0; i < 16; i++) oacc[i] *= corr;
    __syncwarp();
    for (int j = 0; j < 64; j++) {
        float pv = ps[row * 68 + j];
        const float* vr = &vs[j * 68 + c0];
        float4 v0 = *(const float4*)(vr);
        float4 v1 = *(const float4*)(vr + 4);
        float4 v2 = *(const float4*)(vr + 8);
        float4 v3 = *(const float4*)(vr + 12);
        oacc[0]  += pv * v0.x; oacc[1]  += pv * v0.y; oacc[2]  += pv * v0.z; oacc[3]  += pv * v0.w;
        oacc[4]  += pv * v1.x; oacc[5]  += pv * v1.y; oacc[6]  += pv * v1.z; oacc[7]  += pv * v1.w;
        oacc[8]  += pv * v2.x; oacc[9]  += pv * v2.y; oacc[10] += pv * v2.z; oacc[11] += pv * v2.w;
        oacc[12] += pv * v3.x; oacc[13] += pv * v3.y; oacc[14] += pv * v3.z; oacc[15] += pv * v3.w;
    }
    __syncthreads();
}

// ---------------- block-sparse attention: middle q-blocks ----------------
__global__ __launch_bounds__(256) void attn_mid_kernel(
    const float* __restrict__ q, const float* __restrict__ k,
    const float* __restrict__ v, const int* __restrict__ rb,
    float* __restrict__ out)
{
    extern __shared__ float smf[];
    float* qs = smf;
    float* ks = smf + 4352;
    float* vs = smf + 2 * 4352;
    float* ps = smf + 3 * 4352;
    int m = blockIdx.x + 1, h = blockIdx.y, b = blockIdx.z;
    int t = threadIdx.x;
    int row = t >> 2, qq = t & 3, c0 = qq << 4;

    const float* qb = q + (size_t)(b * NTOK + m * BS) * DM + h * DHEAD;
    for (int i = t * 4; i < 4096; i += 1024) {
        int r = i >> 6, c = i & 63;
        *(float4*)&qs[r * 68 + c] = *(const float4*)&qb[(size_t)r * DM + c];
    }
    int list[8];
    {
        const int* r3 = rb + (h * NBLK + m) * RR;
        list[0] = 0; list[1] = NBLK - 1;
        list[2] = m - 1; list[3] = m; list[4] = m + 1;
        list[5] = r3[0]; list[6] = r3[1]; list[7] = r3[2];
    }
    float mrow = -3e38f, lrow = 0.f;
    float oacc[16];
#pragma unroll
    for (int i = 0; i < 16; i++) oacc[i] = 0.f;
    __syncthreads();

    for (int kb = 0; kb < 8; kb++) {
        int blk = list[kb];
        flash_step(k + (size_t)(b * NTOK + blk * BS) * DM + h * DHEAD,
                   v + (size_t)(b * NTOK + blk * BS) * DM + h * DHEAD,
                   qs, ks, vs, ps, t, row, qq, c0, mrow, lrow, oacc);
    }
    float inv = 1.f / lrow;
    float* ob = out + (size_t)(b * NTOK + m * BS + row) * DM + h * DHEAD + c0;
#pragma unroll
    for (int i = 0; i < 16; i += 4) {
        float4 o = make_float4(oacc[i] * inv, oacc[i + 1] * inv,
                               oacc[i + 2] * inv, oacc[i + 3] * inv);
        *(float4*)(ob + i) = o;
    }
}

// ---------------- edge q-blocks: split-KV partials ----------------
__global__ __launch_bounds__(256) void attn_edge_kernel(
    const float* __restrict__ q, const float* __restrict__ k,
    const float* __restrict__ v,
    float* __restrict__ eo, float* __restrict__ em, float* __restrict__ el)
{
    extern __shared__ float smf[];
    float* qs = smf;
    float* ks = smf + 4352;
    float* vs = smf + 2 * 4352;
    float* ps = smf + 3 * 4352;
    int s0 = blockIdx.x, h = blockIdx.y;
    int b = blockIdx.z >> 1, e = blockIdx.z & 1;
    int m = e ? (NBLK - 1) : 0;
    int t = threadIdx.x;
    int row = t >> 2, qq = t & 3, c0 = qq << 4;

    const float* qb = q + (size_t)(b * NTOK + m * BS) * DM + h * DHEAD;
    for (int i = t * 4; i < 4096; i += 1024) {
        int r = i >> 6, c = i & 63;
        *(float4*)&qs[r * 68 + c] = *(const float4*)&qb[(size_t)r * DM + c];
    }
    float mrow = -3e38f, lrow = 0.f;
    float oacc[16];
#pragma unroll
    for (int i = 0; i < 16; i++) oacc[i] = 0.f;
    __syncthreads();

    for (int kb = s0 * 8; kb < s0 * 8 + 8; kb++) {
        flash_step(k + (size_t)(b * NTOK + kb * BS) * DM + h * DHEAD,
                   v + (size_t)(b * NTOK + kb * BS) * DM + h * DHEAD,
                   qs, ks, vs, ps, t, row, qq, c0, mrow, lrow, oacc);
    }
    size_t pbase = ((((size_t)e * NH + h) * BB + b) * 8 + s0);
    float* op = eo + pbase * 4096 + row * 64 + c0;
#pragma unroll
    for (int i = 0; i < 16; i += 4)
        *(float4*)(op + i) = make_float4(oacc[i], oacc[i + 1], oacc[i + 2], oacc[i + 3]);
    if (qq == 0) {
        em[pbase * 64 + row] = mrow;
        el[pbase * 64 + row] = lrow;
    }
}

__global__ __launch_bounds__(256) void attn_edge_combine_kernel(
    const float* __restrict__ eo, const float* __restrict__ em,
    const float* __restrict__ el, float* __restrict__ out)
{
    int e = blockIdx.x, h = blockIdx.y, b = blockIdx.z;
    int m = e ? (NBLK - 1) : 0;
    int t = threadIdx.x;
    int row = t >> 2, c0 = (t & 3) << 4;
    size_t base0 = ((((size_t)e * NH + h) * BB + b) * 8);

    float M = -3e38f;
#pragma unroll
    for (int s = 0; s < 8; s++) M = fmaxf(M, em[(base0 + s) * 64 + row]);
    float L = 0.f;
    float w[8];
#pragma unroll
    for (int s = 0; s < 8; s++) {
        w[s] = __expf(em[(base0 + s) * 64 + row] - M);
        L += w[s] * el[(base0 + s) * 64 + row];
    }
    float acc[16];
#pragma unroll
    for (int j = 0; j < 16; j++) acc[j] = 0.f;
#pragma unroll
    for (int s = 0; s < 8; s++) {
        const float* op = eo + (base0 + s) * 4096 + row * 64 + c0;
#pragma unroll
        for (int j = 0; j < 16; j++) acc[j] += w[s] * op[j];
    }
    float inv = 1.f / L;
    float* ob = out + (size_t)(b * NTOK + m * BS + row) * DM + h * DHEAD + c0;
#pragma unroll
    for (int j = 0; j < 16; j++) ob[j] = acc[j] * inv;
}

// ---------------- final pooled head ----------------
__global__ __launch_bounds__(256) void final_part_kernel(
    const float* __restrict__ x, const float* __restrict__ fcw,
    float* __restrict__ part)
{
    int c = blockIdx.x, b = blockIdx.y;
    float acc = 0.f;
#pragma unroll
    for (int i = 0; i < 3; i++) {
        int d = threadIdx.x + i * 256;
        float s = 0.f;
        int n0 = c * 128;
        for (int n = n0; n < n0 + 128; n++)
            s += x[((size_t)b * NTOK + n) * DM + d];
        acc += s * fcw[d];
    }
    float dummy = 0.f;
    block_reduce2(acc, dummy);
    if (threadIdx.x == 0) part[b * 32 + c] = acc;
}

__global__ void final_sum_kernel(const float* __restrict__ part,
                                 const float* __restrict__ fcb,
                                 float* __restrict__ out)
{
    int t = threadIdx.x;
    int b = t >> 5, lane = t & 31;
    float v = part[b * 32 + lane];
#pragma unroll
    for (int off = 16; off > 0; off >>= 1)
        v += __shfl_down_sync(0xffffffffu, v, off);
    if (lane == 0) out[b] = v * (1.f / NTOK) + fcb[0];
}

// ---------------- driver ----------------
extern "C" void kernel_launch(void* const* d_in, const int* in_sizes, int n_in,
                              void* d_out, int out_size)
{
    const float* inputs = (const float*)d_in[0];
    const int*   rb_all = (const int*)d_in[1];
    const float* pos = (const float*)d_in[2];
    const float* tt  = (const float*)d_in[3];
    const float* eg  = (const float*)d_in[4];
    const float* eb  = (const float*)d_in[5];
    const float* Wq  = (const float*)d_in[6];  const float* bq = (const float*)d_in[7];
    const float* Wk  = (const float*)d_in[8];  const float* bk = (const float*)d_in[9];
    const float* Wv  = (const float*)d_in[10]; const float* bv = (const float*)d_in[11];
    const float* Wo  = (const float*)d_in[12]; const float* bo = (const float*)d_in[13];
    const float* l1g = (const float*)d_in[14]; const float* l1b = (const float*)d_in[15];
    const float* Wi  = (const float*)d_in[16]; const float* bi = (const float*)d_in[17];
    const float* Wd  = (const float*)d_in[18]; const float* bd = (const float*)d_in[19];
    const float* l2g = (const float*)d_in[20]; const float* l2b = (const float*)d_in[21];
    const float* fcw = (const float*)d_in[22]; const float* fcb = (const float*)d_in[23];
    float* out = (float*)d_out;

    float *x, *q, *k, *v, *ctx, *tb, *a, *hh, *part, *eo, *em, *el;
    uint32_t *ah, *al, *wh, *wl;
    cudaGetSymbolAddress((void**)&x,   g_x);
    cudaGetSymbolAddress((void**)&q,   g_q);
    cudaGetSymbolAddress((void**)&k,   g_k);
    cudaGetSymbolAddress((void**)&v,   g_v);
    cudaGetSymbolAddress((void**)&ctx, g_ctx);
    cudaGetSymbolAddress((void**)&tb,  g_t);
    cudaGetSymbolAddress((void**)&a,   g_a);
    cudaGetSymbolAddress((void**)&hh,  g_h);
    cudaGetSymbolAddress((void**)&part, g_part);
    cudaGetSymbolAddress((void**)&eo,  g_eo);
    cudaGetSymbolAddress((void**)&em,  g_em);
    cudaGetSymbolAddress((void**)&el,  g_el);
    cudaGetSymbolAddress((void**)&ah,  g_ah);
    cudaGetSymbolAddress((void**)&al,  g_al);
    cudaGetSymbolAddress((void**)&wh,  g_wh);
    cudaGetSymbolAddress((void**)&wl,  g_wl);

    const int ATTN_SMEM = 4 * 64 * 68 * 4;       // 69632 bytes
    const int GEMM_SMEM = 2 * 40960;             // 81920 bytes
    cudaFuncSetAttribute(attn_mid_kernel, cudaFuncAttributeMaxDynamicSharedMemorySize, ATTN_SMEM);
    cudaFuncSetAttribute(attn_edge_kernel, cudaFuncAttributeMaxDynamicSharedMemorySize, ATTN_SMEM);
    cudaFuncSetAttribute(mgemm_kernel<0>, cudaFuncAttributeMaxDynamicSharedMemorySize, GEMM_SMEM);
    cudaFuncSetAttribute(mgemm_kernel<1>, cudaFuncAttributeMaxDynamicSharedMemorySize, GEMM_SMEM);

    const int MROWS = BB * NTOK;                 // 8192
    dim3 gemm_dd(DM / 128, MROWS / 128);         // (6, 64)
    dim3 gemm_ff(FFD / 128, MROWS / 128);        // (24, 64)
    const int PA_DD = MROWS * DM / 2;            // packed act words (K=768)
    const int PA_FF = MROWS * FFD / 2;           // packed act words (K=3072)

    embed_ln_kernel<<<MROWS, 256>>>(inputs, pos, tt, eg, eb, x);

    for (int l = 0; l < NL; l++) {
        size_t wdd = (size_t)l * DM * DM;
        size_t wff = (size_t)l * DM * FFD;

        pack_act_kernel<<<(PA_DD + 255) / 256, 256>>>(x, ah, al, PA_DD);
        pack_w_kernel<<<dim3(DM / 32, DM / 64), 256>>>(Wq + wdd, wh, wl, DM, DM);
        mgemm_kernel<0><<<gemm_dd, 256, GEMM_SMEM>>>(ah, al, wh, wl, bq + l * DM, q, DM / 2, DM);
        pack_w_kernel<<<dim3(DM / 32, DM / 64), 256>>>(Wk + wdd, wh, wl, DM, DM);
        mgemm_kernel<0><<<gemm_dd, 256, GEMM_SMEM>>>(ah, al, wh, wl, bk + l * DM, k, DM / 2, DM);
        pack_w_kernel<<<dim3(DM / 32, DM / 64), 256>>>(Wv + wdd, wh, wl, DM, DM);
        mgemm_kernel<0><<<gemm_dd, 256, GEMM_SMEM>>>(ah, al, wh, wl, bv + l * DM, v, DM / 2, DM);

        attn_mid_kernel<<<dim3(NBLK - 2, NH, BB), 256, ATTN_SMEM>>>(
            q, k, v, rb_all + l * NH * NBLK * RR, ctx);
        attn_edge_kernel<<<dim3(8, NH, BB * 2), 256, ATTN_SMEM>>>(q, k, v, eo, em, el);
        attn_edge_combine_kernel<<<dim3(2, NH, BB), 256>>>(eo, em, el, ctx);

        pack_act_kernel<<<(PA_DD + 255) / 256, 256>>>(ctx, ah, al, PA_DD);
        pack_w_kernel<<<dim3(DM / 32, DM / 64), 256>>>(Wo + wdd, wh, wl, DM, DM);
        mgemm_kernel<0><<<gemm_dd, 256, GEMM_SMEM>>>(ah, al, wh, wl, bo + l * DM, tb, DM / 2, DM);
        ln_add_kernel<<<MROWS, 256>>>(x, tb, l1g + l * DM, l1b + l * DM, a);

        pack_act_kernel<<<(PA_DD + 255) / 256, 256>>>(a, ah, al, PA_DD);
        pack_w_kernel<<<dim3(FFD / 32, DM / 64), 256>>>(Wi + wff, wh, wl, DM, FFD);
        mgemm_kernel<1><<<gemm_ff, 256, GEMM_SMEM>>>(ah, al, wh, wl, bi + l * FFD, hh, DM / 2, FFD);

        pack_act_kernel<<<(PA_FF + 255) / 256, 256>>>(hh, ah, al, PA_FF);
        pack_w_kernel<<<dim3(DM / 32, FFD / 64), 256>>>(Wd + wff, wh, wl, FFD, DM);
        mgemm_kernel<0><<<gemm_dd, 256, GEMM_SMEM>>>(ah, al, wh, wl, bd + l * DM, tb, FFD / 2, DM);
        ln_add_kernel<<<MROWS, 256>>>(a, tb, l2g + l * DM, l2b + l * DM, x);
    }

    final_part_kernel<<<dim3(32, BB), 256>>>(x, fcw, part);
    final_sum_kernel<<<1, 64>>>(part, fcb, out);
}

// round 6
// speedup vs baseline: 2.5034x; 1.0574x over previous
#include <cuda_runtime.h>
#include <math.h>
#include <stdint.h>

#define BB 2
#define NTOK 4096
#define DM 768
#define NH 12
#define DHEAD 64
#define NBLK 64
#define BS 64
#define FFD 3072
#define NL 2
#define RR 3
#define KH_DD (DM / 2)    // 384 kpairs
#define KH_FF (FFD / 2)   // 1536 kpairs

// ---------------- scratch (device globals; no allocation) ----------------
__device__ float g_x[BB * NTOK * DM];
__device__ float g_q[BB * NTOK * DM];
__device__ float g_k[BB * NTOK * DM];
__device__ float g_v[BB * NTOK * DM];
__device__ float g_t[BB * NTOK * DM];
__device__ float g_a[BB * NTOK * DM];
__device__ float g_part[BB * 32];
// packed bf16 hi/lo activation buffers (k-pair packed uint32)
__device__ uint32_t g_pxh[BB * NTOK * KH_DD];   // x or a packed
__device__ uint32_t g_pxl[BB * NTOK * KH_DD];
__device__ uint32_t g_pch[BB * NTOK * KH_DD];   // ctx packed
__device__ uint32_t g_pcl[BB * NTOK * KH_DD];
__device__ uint32_t g_phh[BB * NTOK * KH_FF];   // ffn hidden packed
__device__ uint32_t g_phl[BB * NTOK * KH_FF];
// packed weights [N][K/2]
__device__ uint32_t g_wh[DM * FFD / 2];
__device__ uint32_t g_wl[DM * FFD / 2];
// edge-attention partials
__device__ float g_eo[2 * NH * BB * 8 * 64 * 64];
__device__ float g_em[2 * NH * BB * 8 * 64];
__device__ float g_el[2 * NH * BB * 8 * 64];

// ---------------- helpers ----------------
__device__ __forceinline__ uint32_t f2bf(float x) {
    uint32_t u = __float_as_uint(x);
    return (u + 0x7FFFu + ((u >> 16) & 1u)) >> 16;
}
__device__ __forceinline__ float bf2f(uint32_t h) { return __uint_as_float(h << 16); }
__device__ __forceinline__ void pack2(float a, float b, uint32_t& hi, uint32_t& lo) {
    uint32_t h0 = f2bf(a), h1 = f2bf(b);
    hi = h0 | (h1 << 16);
    lo = f2bf(a - bf2f(h0)) | (f2bf(b - bf2f(h1)) << 16);
}

__device__ __forceinline__ uint32_t smem_u32(const void* p) {
    uint32_t a;
    asm("{ .reg .u64 t; cvta.to.shared.u64 t, %1; cvt.u32.u64 %0, t; }" : "=r"(a) : "l"(p));
    return a;
}
__device__ __forceinline__ void cp16(uint32_t saddr, const void* g) {
    asm volatile("cp.async.ca.shared.global [%0], [%1], 16;" :: "r"(saddr), "l"(g));
}
#define CP_COMMIT() asm volatile("cp.async.commit_group;" ::: "memory")
#define CP_WAIT1()  asm volatile("cp.async.wait_group 1;" ::: "memory")
#define CP_WAIT0()  asm volatile("cp.async.wait_group 0;" ::: "memory")

__device__ __forceinline__ void ldmat_x4(uint32_t* r, uint32_t saddr) {
    asm volatile("ldmatrix.sync.aligned.m8n8.x4.shared.b16 {%0,%1,%2,%3}, [%4];"
                 : "=r"(r[0]), "=r"(r[1]), "=r"(r[2]), "=r"(r[3]) : "r"(saddr));
}
__device__ __forceinline__ void mma_bf16(float* c, const uint32_t* a, const uint32_t* b) {
    asm volatile(
        "mma.sync.aligned.m16n8k16.row.col.f32.bf16.bf16.f32 "
        "{%0,%1,%2,%3}, {%4,%5,%6,%7}, {%8,%9}, {%0,%1,%2,%3};"
        : "+f"(c[0]), "+f"(c[1]), "+f"(c[2]), "+f"(c[3])
        : "r"(a[0]), "r"(a[1]), "r"(a[2]), "r"(a[3]), "r"(b[0]), "r"(b[1]));
}

// ---------------- weight pack: fp32 W[K][N] -> hi/lo uint32 [N][K/2] ----------------
__global__ __launch_bounds__(256) void pack_w_kernel(
    const float* __restrict__ W, uint32_t* __restrict__ hi,
    uint32_t* __restrict__ lo, int K, int N)
{
    __shared__ float tile[64][33];
    int k0 = blockIdx.y * 64, n0 = blockIdx.x * 32;
    int t = threadIdx.x;
    for (int i = t; i < 64 * 32; i += 256) {
        int r = i >> 5, c = i & 31;
        tile[r][c] = W[(size_t)(k0 + r) * N + n0 + c];
    }
    __syncthreads();
    int Kh = K >> 1;
    for (int i = t; i < 32 * 32; i += 256) {
        int n = i >> 5, kp = i & 31;
        size_t o = (size_t)(n0 + n) * Kh + (k0 >> 1) + kp;
        pack2(tile[kp * 2][n], tile[kp * 2 + 1][n], hi[o], lo[o]);
    }
}

// ---------------- block reduce ----------------
__device__ __forceinline__ void block_reduce2(float& s, float& s2) {
#pragma unroll
    for (int off = 16; off > 0; off >>= 1) {
        s  += __shfl_down_sync(0xffffffffu, s, off);
        s2 += __shfl_down_sync(0xffffffffu, s2, off);
    }
    __shared__ float sh[16];
    int w = threadIdx.x >> 5, lane = threadIdx.x & 31;
    if (lane == 0) { sh[w] = s; sh[8 + w] = s2; }
    __syncthreads();
    if (threadIdx.x == 0) {
        float a = 0.f, b = 0.f;
#pragma unroll
        for (int i = 0; i < 8; i++) { a += sh[i]; b += sh[8 + i]; }
        sh[0] = a; sh[8] = b;
    }
    __syncthreads();
    s = sh[0]; s2 = sh[8];
}

// ---------------- LN kernels (write float + packed hi/lo) ----------------
// thread t handles pair t; threads <128 also handle pair 256+t. 384 pairs total.
__device__ __forceinline__ void ln_core(
    float2 v0, float2 v1, int t, const float* g, const float* bta,
    float* out, uint32_t* ph, uint32_t* pl, size_t rowp)
{
    float s = v0.x + v0.y, s2 = v0.x * v0.x + v0.y * v0.y;
    if (t < 128) { s += v1.x + v1.y; s2 += v1.x * v1.x + v1.y * v1.y; }
    block_reduce2(s, s2);
    float mean = s * (1.f / DM);
    float var = s2 * (1.f / DM) - mean * mean;
    float rstd = rsqrtf(var + 1e-12f);
    {
        float2 gg = *(const float2*)(g + 2 * t);
        float2 bb = *(const float2*)(bta + 2 * t);
        float a = (v0.x - mean) * rstd * gg.x + bb.x;
        float b = (v0.y - mean) * rstd * gg.y + bb.y;
        ((float2*)out)[rowp + t] = make_float2(a, b);
        pack2(a, b, ph[rowp + t], pl[rowp + t]);
    }
    if (t < 128) {
        float2 gg = *(const float2*)(g + 512 + 2 * t);
        float2 bb = *(const float2*)(bta + 512 + 2 * t);
        float a = (v1.x - mean) * rstd * gg.x + bb.x;
        float b = (v1.y - mean) * rstd * gg.y + bb.y;
        ((float2*)out)[rowp + 256 + t] = make_float2(a, b);
        pack2(a, b, ph[rowp + 256 + t], pl[rowp + 256 + t]);
    }
}

__global__ __launch_bounds__(256) void embed_ln_kernel(
    const float* __restrict__ e, const float* __restrict__ pos,
    const float* __restrict__ tt, const float* __restrict__ g,
    const float* __restrict__ bta, float* __restrict__ out,
    uint32_t* __restrict__ ph, uint32_t* __restrict__ pl)
{
    int row = blockIdx.x, t = threadIdx.x;
    int n = row & (NTOK - 1);
    size_t rowp = (size_t)row * 384;
    size_t posp = (size_t)n * 384;
    float2 v0, v1 = make_float2(0.f, 0.f);
    {
        float2 a = ((const float2*)e)[rowp + t];
        float2 p = ((const float2*)pos)[posp + t];
        float2 tt2 = ((const float2*)tt)[t];
        v0 = make_float2(a.x + p.x + tt2.x, a.y + p.y + tt2.y);
    }
    if (t < 128) {
        float2 a = ((const float2*)e)[rowp + 256 + t];
        float2 p = ((const float2*)pos)[posp + 256 + t];
        float2 tt2 = ((const float2*)tt)[256 + t];
        v1 = make_float2(a.x + p.x + tt2.x, a.y + p.y + tt2.y);
    }
    ln_core(v0, v1, t, g, bta, out, ph, pl, rowp);
}

__global__ __launch_bounds__(256) void ln_add_kernel(
    const float* __restrict__ r, const float* __restrict__ y,
    const float* __restrict__ g, const float* __restrict__ bta,
    float* __restrict__ out, uint32_t* __restrict__ ph, uint32_t* __restrict__ pl)
{
    int row = blockIdx.x, t = threadIdx.x;
    size_t rowp = (size_t)row * 384;
    float2 v0, v1 = make_float2(0.f, 0.f);
    {
        float2 a = ((const float2*)r)[rowp + t];
        float2 b = ((const float2*)y)[rowp + t];
        v0 = make_float2(a.x + b.x, a.y + b.y);
    }
    if (t < 128) {
        float2 a = ((const float2*)r)[rowp + 256 + t];
        float2 b = ((const float2*)y)[rowp + 256 + t];
        v1 = make_float2(a.x + b.x, a.y + b.y);
    }
    ln_core(v0, v1, t, g, bta, out, ph, pl, rowp);
}

// ---------------- packed bf16 3-pass GEMM via cp.async + ldmatrix ----------------
// A: [M][Kh] hi/lo packed, B: [N][Kh] hi/lo packed. CTA tile 128x128.
// Chunk = 16 kpairs (K=32). Smem: pitch 16 words + XOR swizzle (c4 ^= (row>>1)&3).
// PACK=1: write GELU'd output pre-packed (k-pair along N) to Oh/Ol instead of C.
template<int GELU, int PACK>
__global__ __launch_bounds__(256, 2) void mgemm_kernel(
    const uint32_t* __restrict__ Ah, const uint32_t* __restrict__ Al,
    const uint32_t* __restrict__ Bh, const uint32_t* __restrict__ Bl,
    const float* __restrict__ bias, float* __restrict__ C,
    uint32_t* __restrict__ Oh, uint32_t* __restrict__ Ol,
    int Kh, int Nn)
{
    extern __shared__ uint32_t sm[];
    uint32_t smem_addr = smem_u32(sm);
    const int RAH = 0, RAL = 2048, RBH = 4096, RBL = 6144;  // u32 offsets
    const uint32_t BUF_BYTES = 32768;

    const int t = threadIdx.x;
    const int wid = t >> 5, lane = t & 31;
    const int wr0 = (wid >> 1) * 32;
    const int wc0 = (wid & 1) * 64;
    const int lr = lane >> 2, lc = lane & 3;
    const int aRow0 = blockIdx.y * 128;
    const int bRow0 = blockIdx.x * 128;

    float acc[2][8][4];
#pragma unroll
    for (int i = 0; i < 2; i++)
#pragma unroll
        for (int j = 0; j < 8; j++)
#pragma unroll
            for (int q = 0; q < 4; q++) acc[i][j][q] = 0.f;

    auto ISSUE = [&](int c) {
        uint32_t sb = smem_addr + (uint32_t)(c & 1) * BUF_BYTES;
        int kp0 = c * 16;
#pragma unroll
        for (int i = 0; i < 8; i++) {
            int reg = i >> 1;
            int f = t + (i & 1) * 256;
            int row = f >> 2, w4 = f & 3;
            int sw = (w4 ^ ((row >> 1) & 3)) << 2;
            const uint32_t* g;
            int ro;
            if (reg == 0)      { g = Ah + (size_t)(aRow0 + row) * Kh + kp0 + w4 * 4; ro = RAH; }
            else if (reg == 1) { g = Al + (size_t)(aRow0 + row) * Kh + kp0 + w4 * 4; ro = RAL; }
            else if (reg == 2) { g = Bh + (size_t)(bRow0 + row) * Kh + kp0 + w4 * 4; ro = RBH; }
            else               { g = Bl + (size_t)(bRow0 + row) * Kh + kp0 + w4 * 4; ro = RBL; }
            cp16(sb + (uint32_t)(ro + row * 16 + sw) * 4u, g);
        }
        CP_COMMIT();
    };

    uint32_t af[2][4], bf[8][2];
    auto LDA = [&](uint32_t sb, int regOff, int s) {
#pragma unroll
        for (int mt = 0; mt < 2; mt++) {
            int row = wr0 + mt * 16 + (lane & 15);
            int c4 = (2 * s + (lane >> 4)) ^ ((row >> 1) & 3);
            ldmat_x4(af[mt], sb + (uint32_t)((regOff + row * 16 + (c4 << 2)) * 4));
        }
    };
    auto LDB = [&](uint32_t sb, int regOff, int s) {
#pragma unroll
        for (int nt0 = 0; nt0 < 8; nt0 += 2) {
            int row = wc0 + nt0 * 8 + ((lane & 16) >> 1) + (lane & 7);
            int c4 = (2 * s + ((lane & 8) >> 3)) ^ ((row >> 1) & 3);
            uint32_t regs[4];
            ldmat_x4(regs, sb + (uint32_t)((regOff + row * 16 + (c4 << 2)) * 4));
            bf[nt0][0] = regs[0]; bf[nt0][1] = regs[1];
            bf[nt0 + 1][0] = regs[2]; bf[nt0 + 1][1] = regs[3];
        }
    };
    auto MMAS = [&]() {
#pragma unroll
        for (int mt = 0; mt < 2; mt++)
#pragma unroll
            for (int nt = 0; nt < 8; nt++) mma_bf16(acc[mt][nt], af[mt], bf[nt]);
    };
    auto COMP = [&](int buf) {
        uint32_t sb = smem_addr + (uint32_t)buf * BUF_BYTES;
#pragma unroll
        for (int s = 0; s < 2; s++) {
            LDA(sb, RAH, s); LDB(sb, RBH, s); MMAS();   // hh
            LDB(sb, RBL, s); MMAS();                    // hl
            LDA(sb, RAL, s); LDB(sb, RBH, s); MMAS();   // lh
        }
    };

    const int nch = Kh / 16;
    ISSUE(0);
    if (nch > 1) ISSUE(1);
    for (int c = 0; c < nch; c++) {
        if (c + 1 < nch) { CP_WAIT1(); } else { CP_WAIT0(); }
        __syncthreads();
        COMP(c & 1);
        __syncthreads();
        if (c + 2 < nch) ISSUE(c + 2);
    }

    // epilogue
    const int Khn = Nn >> 1;
#pragma unroll
    for (int mt = 0; mt < 2; mt++) {
        int r = blockIdx.y * 128 + wr0 + mt * 16 + lr;
#pragma unroll
        for (int nt = 0; nt < 8; nt++) {
            int cc = blockIdx.x * 128 + wc0 + nt * 8 + lc * 2;
            float b0 = bias[cc], b1 = bias[cc + 1];
            float v[4];
            v[0] = acc[mt][nt][0] + b0; v[1] = acc[mt][nt][1] + b1;
            v[2] = acc[mt][nt][2] + b0; v[3] = acc[mt][nt][3] + b1;
            if (GELU) {
#pragma unroll
                for (int q = 0; q < 4; q++) {
                    float z = 0.7978845608028654f * (v[q] + 0.044715f * v[q] * v[q] * v[q]);
                    float e = __expf(2.f * z);
                    v[q] = 0.5f * v[q] * (2.f - 2.f / (e + 1.f));
                }
            }
            if (PACK) {
                int kp = cc >> 1;
                pack2(v[0], v[1], Oh[(size_t)r * Khn + kp], Ol[(size_t)r * Khn + kp]);
                pack2(v[2], v[3], Oh[(size_t)(r + 8) * Khn + kp], Ol[(size_t)(r + 8) * Khn + kp]);
            } else {
                *(float2*)(C + (size_t)r * Nn + cc) = make_float2(v[0], v[1]);
                *(float2*)(C + (size_t)(r + 8) * Nn + cc) = make_float2(v[2], v[3]);
            }
        }
    }
}

// ---------------- attention flash step ----------------
__device__ __forceinline__ void flash_step(
    const float* __restrict__ kbp, const float* __restrict__ vbp,
    const float* qs, float* ks, float* vs, float* ps,
    int t, int row, int qq, int c0,
    float& mrow, float& lrow, float* oacc)
{
    for (int i = t * 4; i < 4096; i += 1024) {
        int r = i >> 6, c = i & 63;
        *(float4*)&ks[r * 68 + c] = *(const float4*)&kbp[(size_t)r * DM + c];
        *(float4*)&vs[r * 68 + c] = *(const float4*)&vbp[(size_t)r * DM + c];
    }
    __syncthreads();

    float s[16];
#pragma unroll
    for (int j = 0; j < 16; j++) s[j] = 0.f;
    for (int d = 0; d < 64; d += 4) {
        float4 qv = *(const float4*)&qs[row * 68 + d];
#pragma unroll
        for (int j = 0; j < 16; j++) {
            float4 kv = *(const float4*)&ks[(qq + 4 * j) * 68 + d];
            s[j] += qv.x * kv.x + qv.y * kv.y + qv.z * kv.z + qv.w * kv.w;
        }
    }
    const float scale = 0.125f;
    float tmax = -3e38f;
#pragma unroll
    for (int j = 0; j < 16; j++) { s[j] *= scale; tmax = fmaxf(tmax, s[j]); }
    tmax = fmaxf(tmax, __shfl_xor_sync(0xffffffffu, tmax, 1));
    tmax = fmaxf(tmax, __shfl_xor_sync(0xffffffffu, tmax, 2));
    float newm = fmaxf(mrow, tmax);
    float corr = __expf(mrow - newm);
    float psum = 0.f;
#pragma unroll
    for (int j = 0; j < 16; j++) {
        float p = __expf(s[j] - newm);
        ps[row * 68 + qq + 4 * j] = p;
        psum += p;
    }
    psum += __shfl_xor_sync(0xffffffffu, psum, 1);
    psum += __shfl_xor_sync(0xffffffffu, psum, 2);
    lrow = lrow * corr + psum;
    mrow = newm;
#pragma unroll
    for (int i = 0; i < 16; i++) oacc[i] *= corr;
    __syncwarp();
    for (int j = 0; j < 64; j++) {
        float pv = ps[row * 68 + j];
        const float* vr = &vs[j * 68 + c0];
        float4 v0 = *(const float4*)(vr);
        float4 v1 = *(const float4*)(vr + 4);
        float4 v2 = *(const float4*)(vr + 8);
        float4 v3 = *(const float4*)(vr + 12);
        oacc[0]  += pv * v0.x; oacc[1]  += pv * v0.y; oacc[2]  += pv * v0.z; oacc[3]  += pv * v0.w;
        oacc[4]  += pv * v1.x; oacc[5]  += pv * v1.y; oacc[6]  += pv * v1.z; oacc[7]  += pv * v1.w;
        oacc[8]  += pv * v2.x; oacc[9]  += pv * v2.y; oacc[10] += pv * v2.z; oacc[11] += pv * v2.w;
        oacc[12] += pv * v3.x; oacc[13] += pv * v3.y; oacc[14] += pv * v3.z; oacc[15] += pv * v3.w;
    }
    __syncthreads();
}

// ---------------- block-sparse attention: middle q-blocks (write packed ctx) ----------------
__global__ __launch_bounds__(256) void attn_mid_kernel(
    const float* __restrict__ q, const float* __restrict__ k,
    const float* __restrict__ v, const int* __restrict__ rb,
    uint32_t* __restrict__ pch, uint32_t* __restrict__ pcl)
{
    extern __shared__ float smf[];
    float* qs = smf;
    float* ks = smf + 4352;
    float* vs = smf + 2 * 4352;
    float* ps = smf + 3 * 4352;
    int m = blockIdx.x + 1, h = blockIdx.y, b = blockIdx.z;
    int t = threadIdx.x;
    int row = t >> 2, qq = t & 3, c0 = qq << 4;

    const float* qb = q + (size_t)(b * NTOK + m * BS) * DM + h * DHEAD;
    for (int i = t * 4; i < 4096; i += 1024) {
        int r = i >> 6, c = i & 63;
        *(float4*)&qs[r * 68 + c] = *(const float4*)&qb[(size_t)r * DM + c];
    }
    int list[8];
    {
        const int* r3 = rb + (h * NBLK + m) * RR;
        list[0] = 0; list[1] = NBLK - 1;
        list[2] = m - 1; list[3] = m; list[4] = m + 1;
        list[5] = r3[0]; list[6] = r3[1]; list[7] = r3[2];
    }
    float mrow = -3e38f, lrow = 0.f;
    float oacc[16];
#pragma unroll
    for (int i = 0; i < 16; i++) oacc[i] = 0.f;
    __syncthreads();

    for (int kb = 0; kb < 8; kb++) {
        int blk = list[kb];
        flash_step(k + (size_t)(b * NTOK + blk * BS) * DM + h * DHEAD,
                   v + (size_t)(b * NTOK + blk * BS) * DM + h * DHEAD,
                   qs, ks, vs, ps, t, row, qq, c0, mrow, lrow, oacc);
    }
    float inv = 1.f / lrow;
    size_t orow = (size_t)(b * NTOK + m * BS + row) * KH_DD + ((h * DHEAD + c0) >> 1);
#pragma unroll
    for (int j = 0; j < 8; j++)
        pack2(oacc[2 * j] * inv, oacc[2 * j + 1] * inv, pch[orow + j], pcl[orow + j]);
}

// ---------------- edge q-blocks: split-KV partials ----------------
__global__ __launch_bounds__(256) void attn_edge_kernel(
    const float* __restrict__ q, const float* __restrict__ k,
    const float* __restrict__ v,
    float* __restrict__ eo, float* __restrict__ em, float* __restrict__ el)
{
    extern __shared__ float smf[];
    float* qs = smf;
    float* ks = smf + 4352;
    float* vs = smf + 2 * 4352;
    float* ps = smf + 3 * 4352;
    int s0 = blockIdx.x, h = blockIdx.y;
    int b = blockIdx.z >> 1, e = blockIdx.z & 1;
    int m = e ? (NBLK - 1) : 0;
    int t = threadIdx.x;
    int row = t >> 2, qq = t & 3, c0 = qq << 4;

    const float* qb = q + (size_t)(b * NTOK + m * BS) * DM + h * DHEAD;
    for (int i = t * 4; i < 4096; i += 1024) {
        int r = i >> 6, c = i & 63;
        *(float4*)&qs[r * 68 + c] = *(const float4*)&qb[(size_t)r * DM + c];
    }
    float mrow = -3e38f, lrow = 0.f;
    float oacc[16];
#pragma unroll
    for (int i = 0; i < 16; i++) oacc[i] = 0.f;
    __syncthreads();

    for (int kb = s0 * 8; kb < s0 * 8 + 8; kb++) {
        flash_step(k + (size_t)(b * NTOK + kb * BS) * DM + h * DHEAD,
                   v + (size_t)(b * NTOK + kb * BS) * DM + h * DHEAD,
                   qs, ks, vs, ps, t, row, qq, c0, mrow, lrow, oacc);
    }
    size_t pbase = ((((size_t)e * NH + h) * BB + b) * 8 + s0);
    float* op = eo + pbase * 4096 + row * 64 + c0;
#pragma unroll
    for (int i = 0; i < 16; i += 4)
        *(float4*)(op + i) = make_float4(oacc[i], oacc[i + 1], oacc[i + 2], oacc[i + 3]);
    if (qq == 0) {
        em[pbase * 64 + row] = mrow;
        el[pbase * 64 + row] = lrow;
    }
}

__global__ __launch_bounds__(256) void attn_edge_combine_kernel(
    const float* __restrict__ eo, const float* __restrict__ em,
    const float* __restrict__ el,
    uint32_t* __restrict__ pch, uint32_t* __restrict__ pcl)
{
    int e = blockIdx.x, h = blockIdx.y, b = blockIdx.z;
    int m = e ? (NBLK - 1) : 0;
    int t = threadIdx.x;
    int row = t >> 2, c0 = (t & 3) << 4;
    size_t base0 = ((((size_t)e * NH + h) * BB + b) * 8);

    float M = -3e38f;
#pragma unroll
    for (int s = 0; s < 8; s++) M = fmaxf(M, em[(base0 + s) * 64 + row]);
    float L = 0.f;
    float w[8];
#pragma unroll
    for (int s = 0; s < 8; s++) {
        w[s] = __expf(em[(base0 + s) * 64 + row] - M);
        L += w[s] * el[(base0 + s) * 64 + row];
    }
    float acc[16];
#pragma unroll
    for (int j = 0; j < 16; j++) acc[j] = 0.f;
#pragma unroll
    for (int s = 0; s < 8; s++) {
        const float* op = eo + (base0 + s) * 4096 + row * 64 + c0;
#pragma unroll
        for (int j = 0; j < 16; j++) acc[j] += w[s] * op[j];
    }
    float inv = 1.f / L;
    size_t orow = (size_t)(b * NTOK + m * BS + row) * KH_DD + ((h * DHEAD + c0) >> 1);
#pragma unroll
    for (int j = 0; j < 8; j++)
        pack2(acc[2 * j] * inv, acc[2 * j + 1] * inv, pch[orow + j], pcl[orow + j]);
}

// ---------------- final pooled head ----------------
__global__ __launch_bounds__(256) void final_part_kernel(
    const float* __restrict__ x, const float* __restrict__ fcw,
    float* __restrict__ part)
{
    int c = blockIdx.x, b = blockIdx.y;
    float acc = 0.f;
#pragma unroll
    for (int i = 0; i < 3; i++) {
        int d = threadIdx.x + i * 256;
        float s = 0.f;
        int n0 = c * 128;
        for (int n = n0; n < n0 + 128; n++)
            s += x[((size_t)b * NTOK + n) * DM + d];
        acc += s * fcw[d];
    }
    float dummy = 0.f;
    block_reduce2(acc, dummy);
    if (threadIdx.x == 0) part[b * 32 + c] = acc;
}

__global__ void final_sum_kernel(const float* __restrict__ part,
                                 const float* __restrict__ fcb,
                                 float* __restrict__ out)
{
    int t = threadIdx.x;
    int b = t >> 5, lane = t & 31;
    float v = part[b * 32 + lane];
#pragma unroll
    for (int off = 16; off > 0; off >>= 1)
        v += __shfl_down_sync(0xffffffffu, v, off);
    if (lane == 0) out[b] = v * (1.f / NTOK) + fcb[0];
}

// ---------------- driver ----------------
extern "C" void kernel_launch(void* const* d_in, const int* in_sizes, int n_in,
                              void* d_out, int out_size)
{
    const float* inputs = (const float*)d_in[0];
    const int*   rb_all = (const int*)d_in[1];
    const float* pos = (const float*)d_in[2];
    const float* tt  = (const float*)d_in[3];
    const float* eg  = (const float*)d_in[4];
    const float* eb  = (const float*)d_in[5];
    const float* Wq  = (const float*)d_in[6];  const float* bq = (const float*)d_in[7];
    const float* Wk  = (const float*)d_in[8];  const float* bk = (const float*)d_in[9];
    const float* Wv  = (const float*)d_in[10]; const float* bv = (const float*)d_in[11];
    const float* Wo  = (const float*)d_in[12]; const float* bo = (const float*)d_in[13];
    const float* l1g = (const float*)d_in[14]; const float* l1b = (const float*)d_in[15];
    const float* Wi  = (const float*)d_in[16]; const float* bi = (const float*)d_in[17];
    const float* Wd  = (const float*)d_in[18]; const float* bd = (const float*)d_in[19];
    const float* l2g = (const float*)d_in[20]; const float* l2b = (const float*)d_in[21];
    const float* fcw = (const float*)d_in[22]; const float* fcb = (const float*)d_in[23];
    float* out = (float*)d_out;

    float *x, *q, *k, *v, *tb, *a, *part, *eo, *em, *el;
    uint32_t *pxh, *pxl, *pch, *pcl, *phh, *phl, *wh, *wl;
    cudaGetSymbolAddress((void**)&x,   g_x);
    cudaGetSymbolAddress((void**)&q,   g_q);
    cudaGetSymbolAddress((void**)&k,   g_k);
    cudaGetSymbolAddress((void**)&v,   g_v);
    cudaGetSymbolAddress((void**)&tb,  g_t);
    cudaGetSymbolAddress((void**)&a,   g_a);
    cudaGetSymbolAddress((void**)&part, g_part);
    cudaGetSymbolAddress((void**)&eo,  g_eo);
    cudaGetSymbolAddress((void**)&em,  g_em);
    cudaGetSymbolAddress((void**)&el,  g_el);
    cudaGetSymbolAddress((void**)&pxh, g_pxh);
    cudaGetSymbolAddress((void**)&pxl, g_pxl);
    cudaGetSymbolAddress((void**)&pch, g_pch);
    cudaGetSymbolAddress((void**)&pcl, g_pcl);
    cudaGetSymbolAddress((void**)&phh, g_phh);
    cudaGetSymbolAddress((void**)&phl, g_phl);
    cudaGetSymbolAddress((void**)&wh,  g_wh);
    cudaGetSymbolAddress((void**)&wl,  g_wl);

    const int ATTN_SMEM = 4 * 64 * 68 * 4;       // 69632 bytes
    const int GEMM_SMEM = 2 * 32768;             // 65536 bytes
    cudaFuncSetAttribute(attn_mid_kernel, cudaFuncAttributeMaxDynamicSharedMemorySize, ATTN_SMEM);
    cudaFuncSetAttribute(attn_edge_kernel, cudaFuncAttributeMaxDynamicSharedMemorySize, ATTN_SMEM);
    cudaFuncSetAttribute((const void*)mgemm_kernel<0, 0>, cudaFuncAttributeMaxDynamicSharedMemorySize, GEMM_SMEM);
    cudaFuncSetAttribute((const void*)mgemm_kernel<1, 1>, cudaFuncAttributeMaxDynamicSharedMemorySize, GEMM_SMEM);

    const int MROWS = BB * NTOK;                 // 8192
    dim3 gemm_dd(DM / 128, MROWS / 128);         // (6, 64)
    dim3 gemm_ff(FFD / 128, MROWS / 128);        // (24, 64)

    embed_ln_kernel<<<MROWS, 256>>>(inputs, pos, tt, eg, eb, x, pxh, pxl);

    for (int l = 0; l < NL; l++) {
        size_t wdd = (size_t)l * DM * DM;
        size_t wff = (size_t)l * DM * FFD;

        pack_w_kernel<<<dim3(DM / 32, DM / 64), 256>>>(Wq + wdd, wh, wl, DM, DM);
        mgemm_kernel<0, 0><<<gemm_dd, 256, GEMM_SMEM>>>(pxh, pxl, wh, wl, bq + l * DM,
                                                        q, nullptr, nullptr, KH_DD, DM);
        pack_w_kernel<<<dim3(DM / 32, DM / 64), 256>>>(Wk + wdd, wh, wl, DM, DM);
        mgemm_kernel<0, 0><<<gemm_dd, 256, GEMM_SMEM>>>(pxh, pxl, wh, wl, bk + l * DM,
                                                        k, nullptr, nullptr, KH_DD, DM);
        pack_w_kernel<<<dim3(DM / 32, DM / 64), 256>>>(Wv + wdd, wh, wl, DM, DM);
        mgemm_kernel<0, 0><<<gemm_dd, 256, GEMM_SMEM>>>(pxh, pxl, wh, wl, bv + l * DM,
                                                        v, nullptr, nullptr, KH_DD, DM);

        attn_mid_kernel<<<dim3(NBLK - 2, NH, BB), 256, ATTN_SMEM>>>(
            q, k, v, rb_all + l * NH * NBLK * RR, pch, pcl);
        attn_edge_kernel<<<dim3(8, NH, BB * 2), 256, ATTN_SMEM>>>(q, k, v, eo, em, el);
        attn_edge_combine_kernel<<<dim3(2, NH, BB), 256>>>(eo, em, el, pch, pcl);

        pack_w_kernel<<<dim3(DM / 32, DM / 64), 256>>>(Wo + wdd, wh, wl, DM, DM);
        mgemm_kernel<0, 0><<<gemm_dd, 256, GEMM_SMEM>>>(pch, pcl, wh, wl, bo + l * DM,
                                                        tb, nullptr, nullptr, KH_DD, DM);
        ln_add_kernel<<<MROWS, 256>>>(x, tb, l1g + l * DM, l1b + l * DM, a, pxh, pxl);

        pack_w_kernel<<<dim3(FFD / 32, DM / 64), 256>>>(Wi + wff, wh, wl, DM, FFD);
        mgemm_kernel<1, 1><<<gemm_ff, 256, GEMM_SMEM>>>(pxh, pxl, wh, wl, bi + l * FFD,
                                                        nullptr, phh, phl, KH_DD, FFD);

        pack_w_kernel<<<dim3(DM / 32, FFD / 64), 256>>>(Wd + wff, wh, wl, FFD, DM);
        mgemm_kernel<0, 0><<<gemm_dd, 256, GEMM_SMEM>>>(phh, phl, wh, wl, bd + l * DM,
                                                        tb, nullptr, nullptr, KH_FF, DM);
        ln_add_kernel<<<MROWS, 256>>>(a, tb, l2g + l * DM, l2b + l * DM, x, pxh, pxl);
    }

    final_part_kernel<<<dim3(32, BB), 256>>>(x, fcw, part);
    final_sum_kernel<<<1, 64>>>(part, fcb, out);
}

// round 7
// speedup vs baseline: 4.6614x; 1.8620x over previous
#include <cuda_runtime.h>
#include <math.h>
#include <stdint.h>

#define BB 2
#define NTOK 4096
#define DM 768
#define NH 12
#define DHEAD 64
#define NBLK 64
#define BS 64
#define FFD 3072
#define NL 2
#define RR 3
#define KH_DD (DM / 2)    // 384
#define KH_FF (FFD / 2)   // 1536
#define GS 2304           // fused qkv row stride

// ---------------- scratch ----------------
__device__ float g_x[BB * NTOK * DM];
__device__ float g_qkv[BB * NTOK * GS];
__device__ float g_t[BB * NTOK * DM];
__device__ float g_a[BB * NTOK * DM];
__device__ float g_part[BB * 32];
__device__ float g_bqkv[GS];
__device__ uint32_t g_pxh[BB * NTOK * KH_DD];
__device__ uint32_t g_pxl[BB * NTOK * KH_DD];
__device__ uint32_t g_pch[BB * NTOK * KH_DD];
__device__ uint32_t g_pcl[BB * NTOK * KH_DD];
__device__ uint32_t g_phh[BB * NTOK * KH_FF];
__device__ uint32_t g_phl[BB * NTOK * KH_FF];
__device__ uint32_t g_wh[DM * FFD / 2];
__device__ uint32_t g_wl[DM * FFD / 2];
__device__ float g_eo[2 * NH * BB * 8 * 64 * 64];
__device__ float g_em[2 * NH * BB * 8 * 64];
__device__ float g_el[2 * NH * BB * 8 * 64];

// ---------------- helpers ----------------
__device__ __forceinline__ uint32_t f2bf(float x) {
    uint32_t u = __float_as_uint(x);
    return (u + 0x7FFFu + ((u >> 16) & 1u)) >> 16;
}
__device__ __forceinline__ float bf2f(uint32_t h) { return __uint_as_float(h << 16); }
__device__ __forceinline__ void pack2(float a, float b, uint32_t& hi, uint32_t& lo) {
    uint32_t h0 = f2bf(a), h1 = f2bf(b);
    hi = h0 | (h1 << 16);
    lo = f2bf(a - bf2f(h0)) | (f2bf(b - bf2f(h1)) << 16);
}
__device__ __forceinline__ uint32_t smem_u32(const void* p) {
    uint32_t a;
    asm("{ .reg .u64 t; cvta.to.shared.u64 t, %1; cvt.u32.u64 %0, t; }" : "=r"(a) : "l"(p));
    return a;
}
__device__ __forceinline__ void cp16(uint32_t saddr, const void* g) {
    asm volatile("cp.async.ca.shared.global [%0], [%1], 16;" :: "r"(saddr), "l"(g));
}
#define CP_COMMIT() asm volatile("cp.async.commit_group;" ::: "memory")
#define CP_WAIT1()  asm volatile("cp.async.wait_group 1;" ::: "memory")
#define CP_WAIT0()  asm volatile("cp.async.wait_group 0;" ::: "memory")

__device__ __forceinline__ void ldmat_x4(uint32_t* r, uint32_t saddr) {
    asm volatile("ldmatrix.sync.aligned.m8n8.x4.shared.b16 {%0,%1,%2,%3}, [%4];"
                 : "=r"(r[0]), "=r"(r[1]), "=r"(r[2]), "=r"(r[3]) : "r"(saddr));
}
__device__ __forceinline__ void ldmat_x4_t(uint32_t* r, uint32_t saddr) {
    asm volatile("ldmatrix.sync.aligned.m8n8.x4.trans.shared.b16 {%0,%1,%2,%3}, [%4];"
                 : "=r"(r[0]), "=r"(r[1]), "=r"(r[2]), "=r"(r[3]) : "r"(saddr));
}
__device__ __forceinline__ void mma_bf16(float* c, const uint32_t* a, const uint32_t* b) {
    asm volatile(
        "mma.sync.aligned.m16n8k16.row.col.f32.bf16.bf16.f32 "
        "{%0,%1,%2,%3}, {%4,%5,%6,%7}, {%8,%9}, {%0,%1,%2,%3};"
        : "+f"(c[0]), "+f"(c[1]), "+f"(c[2]), "+f"(c[3])
        : "r"(a[0]), "r"(a[1]), "r"(a[2]), "r"(a[3]), "r"(b[0]), "r"(b[1]));
}

// ---------------- weight pack ----------------
__global__ __launch_bounds__(256) void pack_w_kernel(
    const float* __restrict__ W, uint32_t* __restrict__ hi,
    uint32_t* __restrict__ lo, int K, int N)
{
    __shared__ float tile[64][33];
    int k0 = blockIdx.y * 64, n0 = blockIdx.x * 32;
    int t = threadIdx.x;
    for (int i = t; i < 64 * 32; i += 256) {
        int r = i >> 5, c = i & 31;
        tile[r][c] = W[(size_t)(k0 + r) * N + n0 + c];
    }
    __syncthreads();
    int Kh = K >> 1;
    for (int i = t; i < 32 * 32; i += 256) {
        int n = i >> 5, kp = i & 31;
        size_t o = (size_t)(n0 + n) * Kh + (k0 >> 1) + kp;
        pack2(tile[kp * 2][n], tile[kp * 2 + 1][n], hi[o], lo[o]);
    }
}

__global__ void concat_bias_kernel(const float* __restrict__ a, const float* __restrict__ b,
                                   const float* __restrict__ c, float* __restrict__ o)
{
    int t = blockIdx.x * 256 + threadIdx.x;
    if (t < DM) o[t] = a[t];
    else if (t < 2 * DM) o[t] = b[t - DM];
    else if (t < 3 * DM) o[t] = c[t - 2 * DM];
}

// ---------------- block reduce ----------------
__device__ __forceinline__ void block_reduce2(float& s, float& s2) {
#pragma unroll
    for (int off = 16; off > 0; off >>= 1) {
        s  += __shfl_down_sync(0xffffffffu, s, off);
        s2 += __shfl_down_sync(0xffffffffu, s2, off);
    }
    __shared__ float sh[16];
    int w = threadIdx.x >> 5, lane = threadIdx.x & 31;
    if (lane == 0) { sh[w] = s; sh[8 + w] = s2; }
    __syncthreads();
    if (threadIdx.x == 0) {
        float a = 0.f, b = 0.f;
#pragma unroll
        for (int i = 0; i < 8; i++) { a += sh[i]; b += sh[8 + i]; }
        sh[0] = a; sh[8] = b;
    }
    __syncthreads();
    s = sh[0]; s2 = sh[8];
}

// ---------------- LN kernels (float + packed out) ----------------
__device__ __forceinline__ void ln_core(
    float2 v0, float2 v1, int t, const float* g, const float* bta,
    float* out, uint32_t* ph, uint32_t* pl, size_t rowp)
{
    float s = v0.x + v0.y, s2 = v0.x * v0.x + v0.y * v0.y;
    if (t < 128) { s += v1.x + v1.y; s2 += v1.x * v1.x + v1.y * v1.y; }
    block_reduce2(s, s2);
    float mean = s * (1.f / DM);
    float var = s2 * (1.f / DM) - mean * mean;
    float rstd = rsqrtf(var + 1e-12f);
    {
        float2 gg = *(const float2*)(g + 2 * t);
        float2 bb = *(const float2*)(bta + 2 * t);
        float a = (v0.x - mean) * rstd * gg.x + bb.x;
        float b = (v0.y - mean) * rstd * gg.y + bb.y;
        ((float2*)out)[rowp + t] = make_float2(a, b);
        pack2(a, b, ph[rowp + t], pl[rowp + t]);
    }
    if (t < 128) {
        float2 gg = *(const float2*)(g + 512 + 2 * t);
        float2 bb = *(const float2*)(bta + 512 + 2 * t);
        float a = (v1.x - mean) * rstd * gg.x + bb.x;
        float b = (v1.y - mean) * rstd * gg.y + bb.y;
        ((float2*)out)[rowp + 256 + t] = make_float2(a, b);
        pack2(a, b, ph[rowp + 256 + t], pl[rowp + 256 + t]);
    }
}

__global__ __launch_bounds__(256) void embed_ln_kernel(
    const float* __restrict__ e, const float* __restrict__ pos,
    const float* __restrict__ tt, const float* __restrict__ g,
    const float* __restrict__ bta, float* __restrict__ out,
    uint32_t* __restrict__ ph, uint32_t* __restrict__ pl)
{
    int row = blockIdx.x, t = threadIdx.x;
    int n = row & (NTOK - 1);
    size_t rowp = (size_t)row * 384;
    size_t posp = (size_t)n * 384;
    float2 v0, v1 = make_float2(0.f, 0.f);
    {
        float2 a = ((const float2*)e)[rowp + t];
        float2 p = ((const float2*)pos)[posp + t];
        float2 tt2 = ((const float2*)tt)[t];
        v0 = make_float2(a.x + p.x + tt2.x, a.y + p.y + tt2.y);
    }
    if (t < 128) {
        float2 a = ((const float2*)e)[rowp + 256 + t];
        float2 p = ((const float2*)pos)[posp + 256 + t];
        float2 tt2 = ((const float2*)tt)[256 + t];
        v1 = make_float2(a.x + p.x + tt2.x, a.y + p.y + tt2.y);
    }
    ln_core(v0, v1, t, g, bta, out, ph, pl, rowp);
}

__global__ __launch_bounds__(256) void ln_add_kernel(
    const float* __restrict__ r, const float* __restrict__ y,
    const float* __restrict__ g, const float* __restrict__ bta,
    float* __restrict__ out, uint32_t* __restrict__ ph, uint32_t* __restrict__ pl)
{
    int row = blockIdx.x, t = threadIdx.x;
    size_t rowp = (size_t)row * 384;
    float2 v0, v1 = make_float2(0.f, 0.f);
    {
        float2 a = ((const float2*)r)[rowp + t];
        float2 b = ((const float2*)y)[rowp + t];
        v0 = make_float2(a.x + b.x, a.y + b.y);
    }
    if (t < 128) {
        float2 a = ((const float2*)r)[rowp + 256 + t];
        float2 b = ((const float2*)y)[rowp + 256 + t];
        v1 = make_float2(a.x + b.x, a.y + b.y);
    }
    ln_core(v0, v1, t, g, bta, out, ph, pl, rowp);
}

// ---------------- packed bf16 3-pass GEMM ----------------
template<int GELU, int PACK>
__global__ __launch_bounds__(256, 2) void mgemm_kernel(
    const uint32_t* __restrict__ Ah, const uint32_t* __restrict__ Al,
    const uint32_t* __restrict__ Bh, const uint32_t* __restrict__ Bl,
    const float* __restrict__ bias, float* __restrict__ C,
    uint32_t* __restrict__ Oh, uint32_t* __restrict__ Ol,
    int Kh, int Nn)
{
    extern __shared__ uint32_t sm[];
    uint32_t smem_addr = smem_u32(sm);
    const int RAH = 0, RAL = 2048, RBH = 4096, RBL = 6144;
    const uint32_t BUF_BYTES = 32768;

    const int t = threadIdx.x;
    const int wid = t >> 5, lane = t & 31;
    const int wr0 = (wid >> 1) * 32;
    const int wc0 = (wid & 1) * 64;
    const int lr = lane >> 2, lc = lane & 3;
    const int aRow0 = blockIdx.y * 128;
    const int bRow0 = blockIdx.x * 128;

    float acc[2][8][4];
#pragma unroll
    for (int i = 0; i < 2; i++)
#pragma unroll
        for (int j = 0; j < 8; j++)
#pragma unroll
            for (int q = 0; q < 4; q++) acc[i][j][q] = 0.f;

    auto ISSUE = [&](int c) {
        uint32_t sb = smem_addr + (uint32_t)(c & 1) * BUF_BYTES;
        int kp0 = c * 16;
#pragma unroll
        for (int i = 0; i < 8; i++) {
            int reg = i >> 1;
            int f = t + (i & 1) * 256;
            int row = f >> 2, w4 = f & 3;
            int sw = (w4 ^ ((row >> 1) & 3)) << 2;
            const uint32_t* g;
            int ro;
            if (reg == 0)      { g = Ah + (size_t)(aRow0 + row) * Kh + kp0 + w4 * 4; ro = RAH; }
            else if (reg == 1) { g = Al + (size_t)(aRow0 + row) * Kh + kp0 + w4 * 4; ro = RAL; }
            else if (reg == 2) { g = Bh + (size_t)(bRow0 + row) * Kh + kp0 + w4 * 4; ro = RBH; }
            else               { g = Bl + (size_t)(bRow0 + row) * Kh + kp0 + w4 * 4; ro = RBL; }
            cp16(sb + (uint32_t)(ro + row * 16 + sw) * 4u, g);
        }
        CP_COMMIT();
    };

    uint32_t af[2][4], bf[8][2];
    auto LDA = [&](uint32_t sb, int regOff, int s) {
#pragma unroll
        for (int mt = 0; mt < 2; mt++) {
            int row = wr0 + mt * 16 + (lane & 15);
            int c4 = (2 * s + (lane >> 4)) ^ ((row >> 1) & 3);
            ldmat_x4(af[mt], sb + (uint32_t)((regOff + row * 16 + (c4 << 2)) * 4));
        }
    };
    auto LDB = [&](uint32_t sb, int regOff, int s) {
#pragma unroll
        for (int nt0 = 0; nt0 < 8; nt0 += 2) {
            int row = wc0 + nt0 * 8 + ((lane & 16) >> 1) + (lane & 7);
            int c4 = (2 * s + ((lane & 8) >> 3)) ^ ((row >> 1) & 3);
            uint32_t regs[4];
            ldmat_x4(regs, sb + (uint32_t)((regOff + row * 16 + (c4 << 2)) * 4));
            bf[nt0][0] = regs[0]; bf[nt0][1] = regs[1];
            bf[nt0 + 1][0] = regs[2]; bf[nt0 + 1][1] = regs[3];
        }
    };
    auto MMAS = [&]() {
#pragma unroll
        for (int mt = 0; mt < 2; mt++)
#pragma unroll
            for (int nt = 0; nt < 8; nt++) mma_bf16(acc[mt][nt], af[mt], bf[nt]);
    };
    auto COMP = [&](int buf) {
        uint32_t sb = smem_addr + (uint32_t)buf * BUF_BYTES;
#pragma unroll
        for (int s = 0; s < 2; s++) {
            LDA(sb, RAH, s); LDB(sb, RBH, s); MMAS();
            LDB(sb, RBL, s); MMAS();
            LDA(sb, RAL, s); LDB(sb, RBH, s); MMAS();
        }
    };

    const int nch = Kh / 16;
    ISSUE(0);
    if (nch > 1) ISSUE(1);
    for (int c = 0; c < nch; c++) {
        if (c + 1 < nch) { CP_WAIT1(); } else { CP_WAIT0(); }
        __syncthreads();
        COMP(c & 1);
        __syncthreads();
        if (c + 2 < nch) ISSUE(c + 2);
    }

    const int Khn = Nn >> 1;
#pragma unroll
    for (int mt = 0; mt < 2; mt++) {
        int r = blockIdx.y * 128 + wr0 + mt * 16 + lr;
#pragma unroll
        for (int nt = 0; nt < 8; nt++) {
            int cc = blockIdx.x * 128 + wc0 + nt * 8 + lc * 2;
            float b0 = bias[cc], b1 = bias[cc + 1];
            float v[4];
            v[0] = acc[mt][nt][0] + b0; v[1] = acc[mt][nt][1] + b1;
            v[2] = acc[mt][nt][2] + b0; v[3] = acc[mt][nt][3] + b1;
            if (GELU) {
#pragma unroll
                for (int q = 0; q < 4; q++) {
                    float z = 0.7978845608028654f * (v[q] + 0.044715f * v[q] * v[q] * v[q]);
                    float e = __expf(2.f * z);
                    v[q] = 0.5f * v[q] * (2.f - 2.f / (e + 1.f));
                }
            }
            if (PACK) {
                int kp = cc >> 1;
                pack2(v[0], v[1], Oh[(size_t)r * Khn + kp], Ol[(size_t)r * Khn + kp]);
                pack2(v[2], v[3], Oh[(size_t)(r + 8) * Khn + kp], Ol[(size_t)(r + 8) * Khn + kp]);
            } else {
                *(float2*)(C + (size_t)r * Nn + cc) = make_float2(v[0], v[1]);
                *(float2*)(C + (size_t)(r + 8) * Nn + cc) = make_float2(v[2], v[3]);
            }
        }
    }
}

// ---------------- attention: mma flash kernel ----------------
// 8 warps: (wid&3) -> q-row group of 16; (wid>>2) -> k-slice of 32 cols.
// Each slice keeps independent online softmax; merged in-CTA at the end.
template<int EDGE>
__global__ __launch_bounds__(256) void attn_mma_kernel(
    const float* __restrict__ qkv, const int* __restrict__ rb,
    uint32_t* __restrict__ pch, uint32_t* __restrict__ pcl,
    float* __restrict__ eo, float* __restrict__ em, float* __restrict__ el)
{
    extern __shared__ uint32_t su[];
    uint32_t sbase = smem_u32(su);
    const int RQH = 0, RQL = 2048, RKH = 4096, RKL = 6144, RVH = 8192, RVL = 10496;
    int t = threadIdx.x, wid = t >> 5, lane = t & 31;
    int mrow0 = (wid & 3) * 16;
    int kh2 = wid >> 2;
    int kcol0 = kh2 * 32;

    int h = blockIdx.y;
    int b, m, s0 = 0, e = 0;
    if (EDGE) { s0 = blockIdx.x; b = blockIdx.z >> 1; e = blockIdx.z & 1; m = e ? (NBLK - 1) : 0; }
    else { m = blockIdx.x + 1; b = blockIdx.z; }

    const float* qp = qkv + (size_t)(b * NTOK + m * BS) * GS + h * DHEAD;
    const float* kbase = qkv + (size_t)b * NTOK * GS + DM + h * DHEAD;
    const float* vbase = qkv + (size_t)b * NTOK * GS + 2 * DM + h * DHEAD;

    // Q fill (once)
    for (int u = t; u < 512; u += 256) {
        int r = u >> 3, c4 = u & 7;
        const float* src = qp + (size_t)r * GS + c4 * 8;
        float4 v0 = *(const float4*)src, v1 = *(const float4*)(src + 4);
        uint4 hi, lo;
        pack2(v0.x, v0.y, hi.x, lo.x); pack2(v0.z, v0.w, hi.y, lo.y);
        pack2(v1.x, v1.y, hi.z, lo.z); pack2(v1.z, v1.w, hi.w, lo.w);
        int off = r * 32 + ((c4 ^ (r & 7)) << 2);
        *(uint4*)(su + RQH + off) = hi;
        *(uint4*)(su + RQL + off) = lo;
    }

    int list[8];
    if (!EDGE) {
        const int* r3 = rb + (h * NBLK + m) * RR;
        list[0] = 0; list[1] = NBLK - 1;
        list[2] = m - 1; list[3] = m; list[4] = m + 1;
        list[5] = r3[0]; list[6] = r3[1]; list[7] = r3[2];
    }

    float o[8][4];
#pragma unroll
    for (int i = 0; i < 8; i++)
#pragma unroll
        for (int j = 0; j < 4; j++) o[i][j] = 0.f;
    float m0 = -1e30f, m8 = -1e30f, l0 = 0.f, l8 = 0.f;

    __syncthreads();

    for (int step = 0; step < 8; step++) {
        int blk = EDGE ? (s0 * 8 + step) : list[step];
        const float* kp = kbase + (size_t)(blk * BS) * GS;
        const float* vp = vbase + (size_t)(blk * BS) * GS;
        for (int u = t; u < 512; u += 256) {
            int r = u >> 3, c4 = u & 7;
            const float* src = kp + (size_t)r * GS + c4 * 8;
            float4 v0 = *(const float4*)src, v1 = *(const float4*)(src + 4);
            uint4 hi, lo;
            pack2(v0.x, v0.y, hi.x, lo.x); pack2(v0.z, v0.w, hi.y, lo.y);
            pack2(v1.x, v1.y, hi.z, lo.z); pack2(v1.z, v1.w, hi.w, lo.w);
            int off = r * 32 + ((c4 ^ (r & 7)) << 2);
            *(uint4*)(su + RKH + off) = hi;
            *(uint4*)(su + RKL + off) = lo;
        }
        for (int u = t; u < 512; u += 256) {
            int j = u >> 3, d0 = (u & 7) * 8;
            const float* src = vp + (size_t)j * GS + d0;
            float4 v0 = *(const float4*)src, v1 = *(const float4*)(src + 4);
            uint4 hi, lo;
            pack2(v0.x, v0.y, hi.x, lo.x); pack2(v0.z, v0.w, hi.y, lo.y);
            pack2(v1.x, v1.y, hi.z, lo.z); pack2(v1.z, v1.w, hi.w, lo.w);
            int off = j * 36 + d0 / 2;
            *(uint4*)(su + RVH + off) = hi;
            *(uint4*)(su + RVL + off) = lo;
        }
        __syncthreads();

        // QK^T 3-pass
        float s[4][4];
#pragma unroll
        for (int i = 0; i < 4; i++)
#pragma unroll
            for (int j = 0; j < 4; j++) s[i][j] = 0.f;
#pragma unroll
        for (int ks = 0; ks < 4; ks++) {
            uint32_t aH[4], aL[4];
            {
                int r = mrow0 + (lane & 15);
                int c4 = (2 * ks + (lane >> 4)) ^ (r & 7);
                ldmat_x4(aH, sbase + (uint32_t)((RQH + r * 32 + (c4 << 2)) * 4));
                ldmat_x4(aL, sbase + (uint32_t)((RQL + r * 32 + (c4 << 2)) * 4));
            }
#pragma unroll
            for (int ntp = 0; ntp < 4; ntp += 2) {
                uint32_t bh[4], bl[4];
                {
                    int r = kcol0 + ntp * 8 + ((lane & 16) >> 1) + (lane & 7);
                    int c4 = (2 * ks + ((lane & 8) >> 3)) ^ (r & 7);
                    ldmat_x4(bh, sbase + (uint32_t)((RKH + r * 32 + (c4 << 2)) * 4));
                    ldmat_x4(bl, sbase + (uint32_t)((RKL + r * 32 + (c4 << 2)) * 4));
                }
                mma_bf16(s[ntp], aH, bh);     mma_bf16(s[ntp + 1], aH, bh + 2);
                mma_bf16(s[ntp], aH, bl);     mma_bf16(s[ntp + 1], aH, bl + 2);
                mma_bf16(s[ntp], aL, bh);     mma_bf16(s[ntp + 1], aL, bh + 2);
            }
        }

        // softmax (slice-local online)
        float mx0 = -1e30f, mx8 = -1e30f;
#pragma unroll
        for (int nt = 0; nt < 4; nt++) {
#pragma unroll
            for (int j = 0; j < 4; j++) s[nt][j] *= 0.125f;
            mx0 = fmaxf(mx0, fmaxf(s[nt][0], s[nt][1]));
            mx8 = fmaxf(mx8, fmaxf(s[nt][2], s[nt][3]));
        }
        mx0 = fmaxf(mx0, __shfl_xor_sync(0xffffffffu, mx0, 1));
        mx0 = fmaxf(mx0, __shfl_xor_sync(0xffffffffu, mx0, 2));
        mx8 = fmaxf(mx8, __shfl_xor_sync(0xffffffffu, mx8, 1));
        mx8 = fmaxf(mx8, __shfl_xor_sync(0xffffffffu, mx8, 2));
        float mn0 = fmaxf(m0, mx0), mn8 = fmaxf(m8, mx8);
        float c0 = __expf(m0 - mn0), c8 = __expf(m8 - mn8);
        float ls0 = 0.f, ls8 = 0.f;
#pragma unroll
        for (int nt = 0; nt < 4; nt++) {
            s[nt][0] = __expf(s[nt][0] - mn0); ls0 += s[nt][0];
            s[nt][1] = __expf(s[nt][1] - mn0); ls0 += s[nt][1];
            s[nt][2] = __expf(s[nt][2] - mn8); ls8 += s[nt][2];
            s[nt][3] = __expf(s[nt][3] - mn8); ls8 += s[nt][3];
        }
        ls0 += __shfl_xor_sync(0xffffffffu, ls0, 1);
        ls0 += __shfl_xor_sync(0xffffffffu, ls0, 2);
        ls8 += __shfl_xor_sync(0xffffffffu, ls8, 1);
        ls8 += __shfl_xor_sync(0xffffffffu, ls8, 2);
        l0 = l0 * c0 + ls0; l8 = l8 * c8 + ls8;
        m0 = mn0; m8 = mn8;
#pragma unroll
        for (int nd = 0; nd < 8; nd++) {
            o[nd][0] *= c0; o[nd][1] *= c0;
            o[nd][2] *= c8; o[nd][3] *= c8;
        }

        // PV 3-pass
#pragma unroll
        for (int tt = 0; tt < 2; tt++) {
            uint32_t aH[4], aL[4];
            pack2(s[2 * tt][0], s[2 * tt][1], aH[0], aL[0]);
            pack2(s[2 * tt][2], s[2 * tt][3], aH[1], aL[1]);
            pack2(s[2 * tt + 1][0], s[2 * tt + 1][1], aH[2], aL[2]);
            pack2(s[2 * tt + 1][2], s[2 * tt + 1][3], aH[3], aL[3]);
            int j0 = kcol0 + tt * 16;
#pragma unroll
            for (int nd = 0; nd < 4; nd++) {
                int d0 = nd * 16;
                uint32_t bh[4], bl[4];
                {
                    int g = lane >> 3, rr = lane & 7;
                    uint32_t boff = (uint32_t)(((j0 + (g & 1) * 8 + rr) * 72 + d0 + (g >> 1) * 8) * 2);
                    ldmat_x4_t(bh, sbase + (uint32_t)(RVH * 4) + boff);
                    ldmat_x4_t(bl, sbase + (uint32_t)(RVL * 4) + boff);
                }
                mma_bf16(o[2 * nd], aH, bh);     mma_bf16(o[2 * nd + 1], aH, bh + 2);
                mma_bf16(o[2 * nd], aH, bl);     mma_bf16(o[2 * nd + 1], aH, bl + 2);
                mma_bf16(o[2 * nd], aL, bh);     mma_bf16(o[2 * nd + 1], aL, bh + 2);
            }
        }
        __syncthreads();
    }

    // merge the two k-slices
    float* smf = (float*)su;
    int r = mrow0 + (lane >> 2);
    if (kh2 == 1) {
        if ((lane & 3) == 0) {
            smf[RKH + r] = m0;       smf[RKH + 64 + r] = l0;
            smf[RKH + r + 8] = m8;   smf[RKH + 64 + r + 8] = l8;
        }
#pragma unroll
        for (int nd = 0; nd < 8; nd++) {
            int col = nd * 8 + (lane & 3) * 2;
            *(float2*)(smf + RVH + r * 66 + col) = make_float2(o[nd][0], o[nd][1]);
            *(float2*)(smf + RVH + (r + 8) * 66 + col) = make_float2(o[nd][2], o[nd][3]);
        }
    }
    __syncthreads();
    if (kh2 == 0) {
        float m1r = smf[RKH + r],     l1r = smf[RKH + 64 + r];
        float m1r8 = smf[RKH + r + 8], l1r8 = smf[RKH + 64 + r + 8];
        float M0 = fmaxf(m0, m1r), w00 = __expf(m0 - M0), w01 = __expf(m1r - M0);
        float L0 = l0 * w00 + l1r * w01;
        float M8 = fmaxf(m8, m1r8), w80 = __expf(m8 - M8), w81 = __expf(m1r8 - M8);
        float L8 = l8 * w80 + l1r8 * w81;
        if (!EDGE) {
            float i0 = 1.f / L0, i8 = 1.f / L8;
            size_t orow0 = (size_t)(b * NTOK + m * BS + r) * KH_DD + (h * DHEAD) / 2;
            size_t orow8 = (size_t)(b * NTOK + m * BS + r + 8) * KH_DD + (h * DHEAD) / 2;
#pragma unroll
            for (int nd = 0; nd < 8; nd++) {
                int col = nd * 8 + (lane & 3) * 2;
                float2 Oa = *(float2*)(smf + RVH + r * 66 + col);
                float2 Ob = *(float2*)(smf + RVH + (r + 8) * 66 + col);
                float f0 = (o[nd][0] * w00 + Oa.x * w01) * i0;
                float f1 = (o[nd][1] * w00 + Oa.y * w01) * i0;
                float f2 = (o[nd][2] * w80 + Ob.x * w81) * i8;
                float f3 = (o[nd][3] * w80 + Ob.y * w81) * i8;
                pack2(f0, f1, pch[orow0 + col / 2], pcl[orow0 + col / 2]);
                pack2(f2, f3, pch[orow8 + col / 2], pcl[orow8 + col / 2]);
            }
        } else {
            size_t pbase = ((((size_t)e * NH + h) * BB + b) * 8 + s0);
#pragma unroll
            for (int nd = 0; nd < 8; nd++) {
                int col = nd * 8 + (lane & 3) * 2;
                float2 Oa = *(float2*)(smf + RVH + r * 66 + col);
                float2 Ob = *(float2*)(smf + RVH + (r + 8) * 66 + col);
                float f0 = o[nd][0] * w00 + Oa.x * w01;
                float f1 = o[nd][1] * w00 + Oa.y * w01;
                float f2 = o[nd][2] * w80 + Ob.x * w81;
                float f3 = o[nd][3] * w80 + Ob.y * w81;
                *(float2*)(eo + pbase * 4096 + r * 64 + col) = make_float2(f0, f1);
                *(float2*)(eo + pbase * 4096 + (r + 8) * 64 + col) = make_float2(f2, f3);
            }
            if ((lane & 3) == 0) {
                em[pbase * 64 + r] = M0;     el[pbase * 64 + r] = L0;
                em[pbase * 64 + r + 8] = M8; el[pbase * 64 + r + 8] = L8;
            }
        }
    }
}

__global__ __launch_bounds__(256) void attn_edge_combine_kernel(
    const float* __restrict__ eo, const float* __restrict__ em,
    const float* __restrict__ el,
    uint32_t* __restrict__ pch, uint32_t* __restrict__ pcl)
{
    int e = blockIdx.x, h = blockIdx.y, b = blockIdx.z;
    int m = e ? (NBLK - 1) : 0;
    int t = threadIdx.x;
    int row = t >> 2, c0 = (t & 3) << 4;
    size_t base0 = ((((size_t)e * NH + h) * BB + b) * 8);

    float M = -3e38f;
#pragma unroll
    for (int s = 0; s < 8; s++) M = fmaxf(M, em[(base0 + s) * 64 + row]);
    float L = 0.f;
    float w[8];
#pragma unroll
    for (int s = 0; s < 8; s++) {
        w[s] = __expf(em[(base0 + s) * 64 + row] - M);
        L += w[s] * el[(base0 + s) * 64 + row];
    }
    float acc[16];
#pragma unroll
    for (int j = 0; j < 16; j++) acc[j] = 0.f;
#pragma unroll
    for (int s = 0; s < 8; s++) {
        const float* op = eo + (base0 + s) * 4096 + row * 64 + c0;
#pragma unroll
        for (int j = 0; j < 16; j++) acc[j] += w[s] * op[j];
    }
    float inv = 1.f / L;
    size_t orow = (size_t)(b * NTOK + m * BS + row) * KH_DD + ((h * DHEAD + c0) >> 1);
#pragma unroll
    for (int j = 0; j < 8; j++)
        pack2(acc[2 * j] * inv, acc[2 * j + 1] * inv, pch[orow + j], pcl[orow + j]);
}

// ---------------- final pooled head ----------------
__global__ __launch_bounds__(256) void final_part_kernel(
    const float* __restrict__ x, const float* __restrict__ fcw,
    float* __restrict__ part)
{
    int c = blockIdx.x, b = blockIdx.y;
    float acc = 0.f;
#pragma unroll
    for (int i = 0; i < 3; i++) {
        int d = threadIdx.x + i * 256;
        float s = 0.f;
        int n0 = c * 128;
        for (int n = n0; n < n0 + 128; n++)
            s += x[((size_t)b * NTOK + n) * DM + d];
        acc += s * fcw[d];
    }
    float dummy = 0.f;
    block_reduce2(acc, dummy);
    if (threadIdx.x == 0) part[b * 32 + c] = acc;
}

__global__ void final_sum_kernel(const float* __restrict__ part,
                                 const float* __restrict__ fcb,
                                 float* __restrict__ out)
{
    int t = threadIdx.x;
    int b = t >> 5, lane = t & 31;
    float v = part[b * 32 + lane];
#pragma unroll
    for (int off = 16; off > 0; off >>= 1)
        v += __shfl_down_sync(0xffffffffu, v, off);
    if (lane == 0) out[b] = v * (1.f / NTOK) + fcb[0];
}

// ---------------- driver ----------------
extern "C" void kernel_launch(void* const* d_in, const int* in_sizes, int n_in,
                              void* d_out, int out_size)
{
    const float* inputs = (const float*)d_in[0];
    const int*   rb_all = (const int*)d_in[1];
    const float* pos = (const float*)d_in[2];
    const float* tt  = (const float*)d_in[3];
    const float* eg  = (const float*)d_in[4];
    const float* eb  = (const float*)d_in[5];
    const float* Wq  = (const float*)d_in[6];  const float* bq = (const float*)d_in[7];
    const float* Wk  = (const float*)d_in[8];  const float* bk = (const float*)d_in[9];
    const float* Wv  = (const float*)d_in[10]; const float* bv = (const float*)d_in[11];
    const float* Wo  = (const float*)d_in[12]; const float* bo = (const float*)d_in[13];
    const float* l1g = (const float*)d_in[14]; const float* l1b = (const float*)d_in[15];
    const float* Wi  = (const float*)d_in[16]; const float* bi = (const float*)d_in[17];
    const float* Wd  = (const float*)d_in[18]; const float* bd = (const float*)d_in[19];
    const float* l2g = (const float*)d_in[20]; const float* l2b = (const float*)d_in[21];
    const float* fcw = (const float*)d_in[22]; const float* fcb = (const float*)d_in[23];
    float* out = (float*)d_out;

    float *x, *qkv, *tb, *a, *part, *eo, *em, *el, *bqkv;
    uint32_t *pxh, *pxl, *pch, *pcl, *phh, *phl, *wh, *wl;
    cudaGetSymbolAddress((void**)&x,    g_x);
    cudaGetSymbolAddress((void**)&qkv,  g_qkv);
    cudaGetSymbolAddress((void**)&tb,   g_t);
    cudaGetSymbolAddress((void**)&a,    g_a);
    cudaGetSymbolAddress((void**)&part, g_part);
    cudaGetSymbolAddress((void**)&eo,   g_eo);
    cudaGetSymbolAddress((void**)&em,   g_em);
    cudaGetSymbolAddress((void**)&el,   g_el);
    cudaGetSymbolAddress((void**)&bqkv, g_bqkv);
    cudaGetSymbolAddress((void**)&pxh,  g_pxh);
    cudaGetSymbolAddress((void**)&pxl,  g_pxl);
    cudaGetSymbolAddress((void**)&pch,  g_pch);
    cudaGetSymbolAddress((void**)&pcl,  g_pcl);
    cudaGetSymbolAddress((void**)&phh,  g_phh);
    cudaGetSymbolAddress((void**)&phl,  g_phl);
    cudaGetSymbolAddress((void**)&wh,   g_wh);
    cudaGetSymbolAddress((void**)&wl,   g_wl);

    const int ATTN_SMEM = 12800 * 4;             // 51200 bytes
    const int GEMM_SMEM = 2 * 32768;             // 65536 bytes
    cudaFuncSetAttribute((const void*)attn_mma_kernel<0>, cudaFuncAttributeMaxDynamicSharedMemorySize, ATTN_SMEM);
    cudaFuncSetAttribute((const void*)attn_mma_kernel<1>, cudaFuncAttributeMaxDynamicSharedMemorySize, ATTN_SMEM);
    cudaFuncSetAttribute((const void*)mgemm_kernel<0, 0>, cudaFuncAttributeMaxDynamicSharedMemorySize, GEMM_SMEM);
    cudaFuncSetAttribute((const void*)mgemm_kernel<1, 1>, cudaFuncAttributeMaxDynamicSharedMemorySize, GEMM_SMEM);

    const int MROWS = BB * NTOK;                 // 8192
    dim3 gemm_qkv(GS / 128, MROWS / 128);        // (18, 64)
    dim3 gemm_dd(DM / 128, MROWS / 128);         // (6, 64)
    dim3 gemm_ff(FFD / 128, MROWS / 128);        // (24, 64)

    embed_ln_kernel<<<MROWS, 256>>>(inputs, pos, tt, eg, eb, x, pxh, pxl);

    for (int l = 0; l < NL; l++) {
        size_t wdd = (size_t)l * DM * DM;
        size_t wff = (size_t)l * DM * FFD;

        pack_w_kernel<<<dim3(DM / 32, DM / 64), 256>>>(Wq + wdd, wh, wl, DM, DM);
        pack_w_kernel<<<dim3(DM / 32, DM / 64), 256>>>(Wk + wdd, wh + (size_t)DM * KH_DD,
                                                       wl + (size_t)DM * KH_DD, DM, DM);
        pack_w_kernel<<<dim3(DM / 32, DM / 64), 256>>>(Wv + wdd, wh + (size_t)2 * DM * KH_DD,
                                                       wl + (size_t)2 * DM * KH_DD, DM, DM);
        concat_bias_kernel<<<9, 256>>>(bq + l * DM, bk + l * DM, bv + l * DM, bqkv);
        mgemm_kernel<0, 0><<<gemm_qkv, 256, GEMM_SMEM>>>(pxh, pxl, wh, wl, bqkv,
                                                         qkv, nullptr, nullptr, KH_DD, GS);

        attn_mma_kernel<0><<<dim3(NBLK - 2, NH, BB), 256, ATTN_SMEM>>>(
            qkv, rb_all + l * NH * NBLK * RR, pch, pcl, nullptr, nullptr, nullptr);
        attn_mma_kernel<1><<<dim3(8, NH, BB * 2), 256, ATTN_SMEM>>>(
            qkv, nullptr, nullptr, nullptr, eo, em, el);
        attn_edge_combine_kernel<<<dim3(2, NH, BB), 256>>>(eo, em, el, pch, pcl);

        pack_w_kernel<<<dim3(DM / 32, DM / 64), 256>>>(Wo + wdd, wh, wl, DM, DM);
        mgemm_kernel<0, 0><<<gemm_dd, 256, GEMM_SMEM>>>(pch, pcl, wh, wl, bo + l * DM,
                                                        tb, nullptr, nullptr, KH_DD, DM);
        ln_add_kernel<<<MROWS, 256>>>(x, tb, l1g + l * DM, l1b + l * DM, a, pxh, pxl);

        pack_w_kernel<<<dim3(FFD / 32, DM / 64), 256>>>(Wi + wff, wh, wl, DM, FFD);
        mgemm_kernel<1, 1><<<gemm_ff, 256, GEMM_SMEM>>>(pxh, pxl, wh, wl, bi + l * FFD,
                                                        nullptr, phh, phl, KH_DD, FFD);

        pack_w_kernel<<<dim3(DM / 32, FFD / 64), 256>>>(Wd + wff, wh, wl, FFD, DM);
        mgemm_kernel<0, 0><<<gemm_dd, 256, GEMM_SMEM>>>(phh, phl, wh, wl, bd + l * DM,
                                                        tb, nullptr, nullptr, KH_FF, DM);
        ln_add_kernel<<<MROWS, 256>>>(a, tb, l2g + l * DM, l2b + l * DM, x, pxh, pxl);
    }

    final_part_kernel<<<dim3(32, BB), 256>>>(x, fcw, part);
    final_sum_kernel<<<1, 64>>>(part, fcb, out);
}

// round 8
// speedup vs baseline: 4.7471x; 1.0184x over previous
#include <cuda_runtime.h>
#include <math.h>
#include <stdint.h>

#define BB 2
#define NTOK 4096
#define DM 768
#define NH 12
#define DHEAD 64
#define NBLK 64
#define BS 64
#define FFD 3072
#define NL 2
#define RR 3
#define KH_DD (DM / 2)    // 384
#define KH_FF (FFD / 2)   // 1536
#define GS 2304           // fused qkv width
#define PQS (GS / 2)      // 1152 packed row stride

// packed weight layout per layer (uint32 words)
#define QKV_WORDS (GS * KH_DD)          // 884736
#define WO_OFF    QKV_WORDS             // 884736
#define WI_OFF    (WO_OFF + DM * KH_DD) // 1179648
#define WD_OFF    (WI_OFF + FFD * KH_DD)// 2359296
#define LOFF      (WD_OFF + DM * KH_FF) // 3538944

// ---------------- scratch ----------------
__device__ float g_x[BB * NTOK * DM];
__device__ float g_t[BB * NTOK * DM];
__device__ float g_a[BB * NTOK * DM];
__device__ float g_part[BB * 32];
__device__ float g_bqkv[2 * GS];
__device__ uint32_t g_pqh[BB * NTOK * PQS];     // packed qkv hi
__device__ uint32_t g_pql[BB * NTOK * PQS];     // packed qkv lo
__device__ uint32_t g_pxh[BB * NTOK * KH_DD];
__device__ uint32_t g_pxl[BB * NTOK * KH_DD];
__device__ uint32_t g_pch[BB * NTOK * KH_DD];
__device__ uint32_t g_pcl[BB * NTOK * KH_DD];
__device__ uint32_t g_phh[BB * NTOK * KH_FF];
__device__ uint32_t g_phl[BB * NTOK * KH_FF];
__device__ uint32_t g_wh[2 * LOFF];
__device__ uint32_t g_wl[2 * LOFF];
__device__ float g_eo[2 * NH * BB * 8 * 64 * 64];
__device__ float g_em[2 * NH * BB * 8 * 64];
__device__ float g_el[2 * NH * BB * 8 * 64];

// ---------------- helpers ----------------
__device__ __forceinline__ uint32_t f2bf(float x) {
    uint32_t u = __float_as_uint(x);
    return (u + 0x7FFFu + ((u >> 16) & 1u)) >> 16;
}
__device__ __forceinline__ float bf2f(uint32_t h) { return __uint_as_float(h << 16); }
__device__ __forceinline__ void pack2(float a, float b, uint32_t& hi, uint32_t& lo) {
    uint32_t h0 = f2bf(a), h1 = f2bf(b);
    hi = h0 | (h1 << 16);
    lo = f2bf(a - bf2f(h0)) | (f2bf(b - bf2f(h1)) << 16);
}
__device__ __forceinline__ uint32_t smem_u32(const void* p) {
    uint32_t a;
    asm("{ .reg .u64 t; cvta.to.shared.u64 t, %1; cvt.u32.u64 %0, t; }" : "=r"(a) : "l"(p));
    return a;
}
__device__ __forceinline__ void cp16(uint32_t saddr, const void* g) {
    asm volatile("cp.async.ca.shared.global [%0], [%1], 16;" :: "r"(saddr), "l"(g));
}
#define CP_COMMIT() asm volatile("cp.async.commit_group;" ::: "memory")
#define CP_WAIT1()  asm volatile("cp.async.wait_group 1;" ::: "memory")
#define CP_WAIT0()  asm volatile("cp.async.wait_group 0;" ::: "memory")

__device__ __forceinline__ void ldmat_x4(uint32_t* r, uint32_t saddr) {
    asm volatile("ldmatrix.sync.aligned.m8n8.x4.shared.b16 {%0,%1,%2,%3}, [%4];"
                 : "=r"(r[0]), "=r"(r[1]), "=r"(r[2]), "=r"(r[3]) : "r"(saddr));
}
__device__ __forceinline__ void ldmat_x4_t(uint32_t* r, uint32_t saddr) {
    asm volatile("ldmatrix.sync.aligned.m8n8.x4.trans.shared.b16 {%0,%1,%2,%3}, [%4];"
                 : "=r"(r[0]), "=r"(r[1]), "=r"(r[2]), "=r"(r[3]) : "r"(saddr));
}
__device__ __forceinline__ void mma_bf16(float* c, const uint32_t* a, const uint32_t* b) {
    asm volatile(
        "mma.sync.aligned.m16n8k16.row.col.f32.bf16.bf16.f32 "
        "{%0,%1,%2,%3}, {%4,%5,%6,%7}, {%8,%9}, {%0,%1,%2,%3};"
        : "+f"(c[0]), "+f"(c[1]), "+f"(c[2]), "+f"(c[3])
        : "r"(a[0]), "r"(a[1]), "r"(a[2]), "r"(a[3]), "r"(b[0]), "r"(b[1]));
}

// ---------------- batched weight packs ----------------
// core: transpose-pack a 64(K)x32(N) tile of W[K][N] into dst[N][Kh]
__device__ __forceinline__ void pack_tile(
    const float* __restrict__ W, uint32_t* __restrict__ hi, uint32_t* __restrict__ lo,
    int K, int N, int Kh, int k0, int n0, size_t dbase)
{
    __shared__ float tile[64][33];
    int t = threadIdx.x;
    for (int i = t; i < 64 * 32; i += 256) {
        int r = i >> 5, c = i & 31;
        tile[r][c] = W[(size_t)(k0 + r) * N + n0 + c];
    }
    __syncthreads();
    for (int i = t; i < 32 * 32; i += 256) {
        int n = i >> 5, kp = i & 31;
        size_t o = dbase + (size_t)(n0 + n) * Kh + (k0 >> 1) + kp;
        pack2(tile[kp * 2][n], tile[kp * 2 + 1][n], hi[o], lo[o]);
    }
}

// class A: Wq/Wk/Wv/Wo (K=DM, N=DM), z = layer*4 + which
__global__ __launch_bounds__(256) void pack_wA_kernel(
    const float* __restrict__ Wq, const float* __restrict__ Wk,
    const float* __restrict__ Wv, const float* __restrict__ Wo,
    uint32_t* __restrict__ hi, uint32_t* __restrict__ lo)
{
    int z = blockIdx.z, layer = z >> 2, which = z & 3;
    const float* W = (which == 0 ? Wq : which == 1 ? Wk : which == 2 ? Wv : Wo)
                     + (size_t)layer * DM * DM;
    size_t dbase = (size_t)layer * LOFF +
                   (which < 3 ? (size_t)which * DM * KH_DD : (size_t)WO_OFF);
    pack_tile(W, hi, lo, DM, DM, KH_DD, blockIdx.y * 64, blockIdx.x * 32, dbase);
}

// class B: Wi (K=DM, N=FFD), z = layer
__global__ __launch_bounds__(256) void pack_wB_kernel(
    const float* __restrict__ Wi, uint32_t* __restrict__ hi, uint32_t* __restrict__ lo)
{
    int layer = blockIdx.z;
    pack_tile(Wi + (size_t)layer * DM * FFD, hi, lo, DM, FFD, KH_DD,
              blockIdx.y * 64, blockIdx.x * 32, (size_t)layer * LOFF + WI_OFF);
}

// class C: Wd (K=FFD, N=DM), z = layer
__global__ __launch_bounds__(256) void pack_wC_kernel(
    const float* __restrict__ Wd, uint32_t* __restrict__ hi, uint32_t* __restrict__ lo)
{
    int layer = blockIdx.z;
    pack_tile(Wd + (size_t)layer * FFD * DM, hi, lo, FFD, DM, KH_FF,
              blockIdx.y * 64, blockIdx.x * 32, (size_t)layer * LOFF + WD_OFF);
}

__global__ void concat_bias_kernel(const float* __restrict__ a, const float* __restrict__ b,
                                   const float* __restrict__ c, float* __restrict__ o)
{
    int t = blockIdx.x * 256 + threadIdx.x;
    if (t >= 2 * GS) return;
    int l = t / GS, j = t - l * GS;
    float v;
    if (j < DM) v = a[l * DM + j];
    else if (j < 2 * DM) v = b[l * DM + j - DM];
    else v = c[l * DM + j - 2 * DM];
    o[t] = v;
}

// ---------------- block reduce ----------------
__device__ __forceinline__ void block_reduce2(float& s, float& s2) {
#pragma unroll
    for (int off = 16; off > 0; off >>= 1) {
        s  += __shfl_down_sync(0xffffffffu, s, off);
        s2 += __shfl_down_sync(0xffffffffu, s2, off);
    }
    __shared__ float sh[16];
    int w = threadIdx.x >> 5, lane = threadIdx.x & 31;
    if (lane == 0) { sh[w] = s; sh[8 + w] = s2; }
    __syncthreads();
    if (threadIdx.x == 0) {
        float a = 0.f, b = 0.f;
#pragma unroll
        for (int i = 0; i < 8; i++) { a += sh[i]; b += sh[8 + i]; }
        sh[0] = a; sh[8] = b;
    }
    __syncthreads();
    s = sh[0]; s2 = sh[8];
}

// ---------------- LN kernels ----------------
__device__ __forceinline__ void ln_core(
    float2 v0, float2 v1, int t, const float* g, const float* bta,
    float* out, uint32_t* ph, uint32_t* pl, size_t rowp)
{
    float s = v0.x + v0.y, s2 = v0.x * v0.x + v0.y * v0.y;
    if (t < 128) { s += v1.x + v1.y; s2 += v1.x * v1.x + v1.y * v1.y; }
    block_reduce2(s, s2);
    float mean = s * (1.f / DM);
    float var = s2 * (1.f / DM) - mean * mean;
    float rstd = rsqrtf(var + 1e-12f);
    {
        float2 gg = *(const float2*)(g + 2 * t);
        float2 bb = *(const float2*)(bta + 2 * t);
        float a = (v0.x - mean) * rstd * gg.x + bb.x;
        float b = (v0.y - mean) * rstd * gg.y + bb.y;
        ((float2*)out)[rowp + t] = make_float2(a, b);
        pack2(a, b, ph[rowp + t], pl[rowp + t]);
    }
    if (t < 128) {
        float2 gg = *(const float2*)(g + 512 + 2 * t);
        float2 bb = *(const float2*)(bta + 512 + 2 * t);
        float a = (v1.x - mean) * rstd * gg.x + bb.x;
        float b = (v1.y - mean) * rstd * gg.y + bb.y;
        ((float2*)out)[rowp + 256 + t] = make_float2(a, b);
        pack2(a, b, ph[rowp + 256 + t], pl[rowp + 256 + t]);
    }
}

__global__ __launch_bounds__(256) void embed_ln_kernel(
    const float* __restrict__ e, const float* __restrict__ pos,
    const float* __restrict__ tt, const float* __restrict__ g,
    const float* __restrict__ bta, float* __restrict__ out,
    uint32_t* __restrict__ ph, uint32_t* __restrict__ pl)
{
    int row = blockIdx.x, t = threadIdx.x;
    int n = row & (NTOK - 1);
    size_t rowp = (size_t)row * 384;
    size_t posp = (size_t)n * 384;
    float2 v0, v1 = make_float2(0.f, 0.f);
    {
        float2 a = ((const float2*)e)[rowp + t];
        float2 p = ((const float2*)pos)[posp + t];
        float2 tt2 = ((const float2*)tt)[t];
        v0 = make_float2(a.x + p.x + tt2.x, a.y + p.y + tt2.y);
    }
    if (t < 128) {
        float2 a = ((const float2*)e)[rowp + 256 + t];
        float2 p = ((const float2*)pos)[posp + 256 + t];
        float2 tt2 = ((const float2*)tt)[256 + t];
        v1 = make_float2(a.x + p.x + tt2.x, a.y + p.y + tt2.y);
    }
    ln_core(v0, v1, t, g, bta, out, ph, pl, rowp);
}

__global__ __launch_bounds__(256) void ln_add_kernel(
    const float* __restrict__ r, const float* __restrict__ y,
    const float* __restrict__ g, const float* __restrict__ bta,
    float* __restrict__ out, uint32_t* __restrict__ ph, uint32_t* __restrict__ pl)
{
    int row = blockIdx.x, t = threadIdx.x;
    size_t rowp = (size_t)row * 384;
    float2 v0, v1 = make_float2(0.f, 0.f);
    {
        float2 a = ((const float2*)r)[rowp + t];
        float2 b = ((const float2*)y)[rowp + t];
        v0 = make_float2(a.x + b.x, a.y + b.y);
    }
    if (t < 128) {
        float2 a = ((const float2*)r)[rowp + 256 + t];
        float2 b = ((const float2*)y)[rowp + 256 + t];
        v1 = make_float2(a.x + b.x, a.y + b.y);
    }
    ln_core(v0, v1, t, g, bta, out, ph, pl, rowp);
}

// ---------------- packed bf16 3-pass GEMM ----------------
template<int GELU, int PACK>
__global__ __launch_bounds__(256, 2) void mgemm_kernel(
    const uint32_t* __restrict__ Ah, const uint32_t* __restrict__ Al,
    const uint32_t* __restrict__ Bh, const uint32_t* __restrict__ Bl,
    const float* __restrict__ bias, float* __restrict__ C,
    uint32_t* __restrict__ Oh, uint32_t* __restrict__ Ol,
    int Kh, int Nn)
{
    extern __shared__ uint32_t sm[];
    uint32_t smem_addr = smem_u32(sm);
    const int RAH = 0, RAL = 2048, RBH = 4096, RBL = 6144;
    const uint32_t BUF_BYTES = 32768;

    const int t = threadIdx.x;
    const int wid = t >> 5, lane = t & 31;
    const int wr0 = (wid >> 1) * 32;
    const int wc0 = (wid & 1) * 64;
    const int lr = lane >> 2, lc = lane & 3;
    const int aRow0 = blockIdx.y * 128;
    const int bRow0 = blockIdx.x * 128;

    float acc[2][8][4];
#pragma unroll
    for (int i = 0; i < 2; i++)
#pragma unroll
        for (int j = 0; j < 8; j++)
#pragma unroll
            for (int q = 0; q < 4; q++) acc[i][j][q] = 0.f;

    auto ISSUE = [&](int c) {
        uint32_t sb = smem_addr + (uint32_t)(c & 1) * BUF_BYTES;
        int kp0 = c * 16;
#pragma unroll
        for (int i = 0; i < 8; i++) {
            int reg = i >> 1;
            int f = t + (i & 1) * 256;
            int row = f >> 2, w4 = f & 3;
            int sw = (w4 ^ ((row >> 1) & 3)) << 2;
            const uint32_t* g;
            int ro;
            if (reg == 0)      { g = Ah + (size_t)(aRow0 + row) * Kh + kp0 + w4 * 4; ro = RAH; }
            else if (reg == 1) { g = Al + (size_t)(aRow0 + row) * Kh + kp0 + w4 * 4; ro = RAL; }
            else if (reg == 2) { g = Bh + (size_t)(bRow0 + row) * Kh + kp0 + w4 * 4; ro = RBH; }
            else               { g = Bl + (size_t)(bRow0 + row) * Kh + kp0 + w4 * 4; ro = RBL; }
            cp16(sb + (uint32_t)(ro + row * 16 + sw) * 4u, g);
        }
        CP_COMMIT();
    };

    uint32_t ah_[2][4], al_[2][4], bf[8][2];
    auto LDA = [&](uint32_t (&dst)[2][4], uint32_t sb, int regOff, int s) {
#pragma unroll
        for (int mt = 0; mt < 2; mt++) {
            int row = wr0 + mt * 16 + (lane & 15);
            int c4 = (2 * s + (lane >> 4)) ^ ((row >> 1) & 3);
            ldmat_x4(dst[mt], sb + (uint32_t)((regOff + row * 16 + (c4 << 2)) * 4));
        }
    };
    auto LDB = [&](uint32_t sb, int regOff, int s) {
#pragma unroll
        for (int nt0 = 0; nt0 < 8; nt0 += 2) {
            int row = wc0 + nt0 * 8 + ((lane & 16) >> 1) + (lane & 7);
            int c4 = (2 * s + ((lane & 8) >> 3)) ^ ((row >> 1) & 3);
            uint32_t regs[4];
            ldmat_x4(regs, sb + (uint32_t)((regOff + row * 16 + (c4 << 2)) * 4));
            bf[nt0][0] = regs[0]; bf[nt0][1] = regs[1];
            bf[nt0 + 1][0] = regs[2]; bf[nt0 + 1][1] = regs[3];
        }
    };
    auto MMAS = [&](uint32_t (&a)[2][4]) {
#pragma unroll
        for (int mt = 0; mt < 2; mt++)
#pragma unroll
            for (int nt = 0; nt < 8; nt++) mma_bf16(acc[mt][nt], a[mt], bf[nt]);
    };
    auto COMP = [&](int buf) {
        uint32_t sb = smem_addr + (uint32_t)buf * BUF_BYTES;
#pragma unroll
        for (int s = 0; s < 2; s++) {
            LDA(ah_, sb, RAH, s);
            LDA(al_, sb, RAL, s);
            LDB(sb, RBH, s);
            MMAS(ah_);            // hh
            MMAS(al_);            // lh
            LDB(sb, RBL, s);
            MMAS(ah_);            // hl
        }
    };

    const int nch = Kh / 16;
    ISSUE(0);
    if (nch > 1) ISSUE(1);
    for (int c = 0; c < nch; c++) {
        if (c + 1 < nch) { CP_WAIT1(); } else { CP_WAIT0(); }
        __syncthreads();
        COMP(c & 1);
        __syncthreads();
        if (c + 2 < nch) ISSUE(c + 2);
    }

    const int Khn = Nn >> 1;
#pragma unroll
    for (int mt = 0; mt < 2; mt++) {
        int r = blockIdx.y * 128 + wr0 + mt * 16 + lr;
#pragma unroll
        for (int nt = 0; nt < 8; nt++) {
            int cc = blockIdx.x * 128 + wc0 + nt * 8 + lc * 2;
            float b0 = bias[cc], b1 = bias[cc + 1];
            float v[4];
            v[0] = acc[mt][nt][0] + b0; v[1] = acc[mt][nt][1] + b1;
            v[2] = acc[mt][nt][2] + b0; v[3] = acc[mt][nt][3] + b1;
            if (GELU) {
#pragma unroll
                for (int q = 0; q < 4; q++) {
                    float z = 0.7978845608028654f * (v[q] + 0.044715f * v[q] * v[q] * v[q]);
                    float e = __expf(2.f * z);
                    v[q] = 0.5f * v[q] * (2.f - 2.f / (e + 1.f));
                }
            }
            if (PACK) {
                int kp = cc >> 1;
                pack2(v[0], v[1], Oh[(size_t)r * Khn + kp], Ol[(size_t)r * Khn + kp]);
                pack2(v[2], v[3], Oh[(size_t)(r + 8) * Khn + kp], Ol[(size_t)(r + 8) * Khn + kp]);
            } else {
                *(float2*)(C + (size_t)r * Nn + cc) = make_float2(v[0], v[1]);
                *(float2*)(C + (size_t)(r + 8) * Nn + cc) = make_float2(v[2], v[3]);
            }
        }
    }
}

// ---------------- attention: mma flash kernel on packed qkv ----------------
template<int EDGE>
__global__ __launch_bounds__(256) void attn_mma_kernel(
    const uint32_t* __restrict__ pqh, const uint32_t* __restrict__ pql,
    const int* __restrict__ rb,
    uint32_t* __restrict__ pch, uint32_t* __restrict__ pcl,
    float* __restrict__ eo, float* __restrict__ em, float* __restrict__ el)
{
    extern __shared__ uint32_t su[];
    uint32_t sbase = smem_u32(su);
    const int RQH = 0, RQL = 2048, RKH = 4096, RKL = 6144, RVH = 8192, RVL = 10496;
    int t = threadIdx.x, wid = t >> 5, lane = t & 31;
    int mrow0 = (wid & 3) * 16;
    int kh2 = wid >> 2;
    int kcol0 = kh2 * 32;

    int h = blockIdx.y;
    int b, m, s0 = 0, e = 0;
    if (EDGE) { s0 = blockIdx.x; b = blockIdx.z >> 1; e = blockIdx.z & 1; m = e ? (NBLK - 1) : 0; }
    else { m = blockIdx.x + 1; b = blockIdx.z; }

    const uint32_t* qh = pqh + (size_t)(b * NTOK + m * BS) * PQS + h * 32;
    const uint32_t* ql = pql + (size_t)(b * NTOK + m * BS) * PQS + h * 32;
    const uint32_t* kbh = pqh + (size_t)b * NTOK * PQS + KH_DD + h * 32;
    const uint32_t* kbl = pql + (size_t)b * NTOK * PQS + KH_DD + h * 32;
    const uint32_t* vbh = pqh + (size_t)b * NTOK * PQS + 2 * KH_DD + h * 32;
    const uint32_t* vbl = pql + (size_t)b * NTOK * PQS + 2 * KH_DD + h * 32;

    // Q fill via cp.async (once)
    for (int u = t; u < 512; u += 256) {
        int r = u >> 3, c4 = u & 7;
        uint32_t doff = (uint32_t)((r * 32 + ((c4 ^ (r & 7)) << 2)) * 4);
        cp16(sbase + (uint32_t)(RQH * 4) + doff, qh + (size_t)r * PQS + c4 * 4);
        cp16(sbase + (uint32_t)(RQL * 4) + doff, ql + (size_t)r * PQS + c4 * 4);
    }
    CP_COMMIT();

    int list[8];
    if (!EDGE) {
        const int* r3 = rb + (h * NBLK + m) * RR;
        list[0] = 0; list[1] = NBLK - 1;
        list[2] = m - 1; list[3] = m; list[4] = m + 1;
        list[5] = r3[0]; list[6] = r3[1]; list[7] = r3[2];
    }

    float o[8][4];
#pragma unroll
    for (int i = 0; i < 8; i++)
#pragma unroll
        for (int j = 0; j < 4; j++) o[i][j] = 0.f;
    float m0 = -1e30f, m8 = -1e30f, l0 = 0.f, l8 = 0.f;

    for (int step = 0; step < 8; step++) {
        int blk = EDGE ? (s0 * 8 + step) : list[step];
        const uint32_t* kh = kbh + (size_t)(blk * BS) * PQS;
        const uint32_t* kl = kbl + (size_t)(blk * BS) * PQS;
        const uint32_t* vh = vbh + (size_t)(blk * BS) * PQS;
        const uint32_t* vl = vbl + (size_t)(blk * BS) * PQS;
        for (int u = t; u < 512; u += 256) {
            int r = u >> 3, c4 = u & 7;
            uint32_t doff = (uint32_t)((r * 32 + ((c4 ^ (r & 7)) << 2)) * 4);
            cp16(sbase + (uint32_t)(RKH * 4) + doff, kh + (size_t)r * PQS + c4 * 4);
            cp16(sbase + (uint32_t)(RKL * 4) + doff, kl + (size_t)r * PQS + c4 * 4);
        }
        for (int u = t; u < 512; u += 256) {
            int j = u >> 3, w4 = u & 7;
            uint32_t doff = (uint32_t)((j * 36 + w4 * 4) * 4);
            cp16(sbase + (uint32_t)(RVH * 4) + doff, vh + (size_t)j * PQS + w4 * 4);
            cp16(sbase + (uint32_t)(RVL * 4) + doff, vl + (size_t)j * PQS + w4 * 4);
        }
        CP_COMMIT();
        CP_WAIT0();
        __syncthreads();

        // QK^T 3-pass
        float s[4][4];
#pragma unroll
        for (int i = 0; i < 4; i++)
#pragma unroll
            for (int j = 0; j < 4; j++) s[i][j] = 0.f;
#pragma unroll
        for (int ks = 0; ks < 4; ks++) {
            uint32_t aH[4], aL[4];
            {
                int r = mrow0 + (lane & 15);
                int c4 = (2 * ks + (lane >> 4)) ^ (r & 7);
                ldmat_x4(aH, sbase + (uint32_t)((RQH + r * 32 + (c4 << 2)) * 4));
                ldmat_x4(aL, sbase + (uint32_t)((RQL + r * 32 + (c4 << 2)) * 4));
            }
#pragma unroll
            for (int ntp = 0; ntp < 4; ntp += 2) {
                uint32_t bh[4], bl[4];
                {
                    int r = kcol0 + ntp * 8 + ((lane & 16) >> 1) + (lane & 7);
                    int c4 = (2 * ks + ((lane & 8) >> 3)) ^ (r & 7);
                    ldmat_x4(bh, sbase + (uint32_t)((RKH + r * 32 + (c4 << 2)) * 4));
                    ldmat_x4(bl, sbase + (uint32_t)((RKL + r * 32 + (c4 << 2)) * 4));
                }
                mma_bf16(s[ntp], aH, bh);     mma_bf16(s[ntp + 1], aH, bh + 2);
                mma_bf16(s[ntp], aH, bl);     mma_bf16(s[ntp + 1], aH, bl + 2);
                mma_bf16(s[ntp], aL, bh);     mma_bf16(s[ntp + 1], aL, bh + 2);
            }
        }

        // softmax (slice-local online)
        float mx0 = -1e30f, mx8 = -1e30f;
#pragma unroll
        for (int nt = 0; nt < 4; nt++) {
#pragma unroll
            for (int j = 0; j < 4; j++) s[nt][j] *= 0.125f;
            mx0 = fmaxf(mx0, fmaxf(s[nt][0], s[nt][1]));
            mx8 = fmaxf(mx8, fmaxf(s[nt][2], s[nt][3]));
        }
        mx0 = fmaxf(mx0, __shfl_xor_sync(0xffffffffu, mx0, 1));
        mx0 = fmaxf(mx0, __shfl_xor_sync(0xffffffffu, mx0, 2));
        mx8 = fmaxf(mx8, __shfl_xor_sync(0xffffffffu, mx8, 1));
        mx8 = fmaxf(mx8, __shfl_xor_sync(0xffffffffu, mx8, 2));
        float mn0 = fmaxf(m0, mx0), mn8 = fmaxf(m8, mx8);
        float c0 = __expf(m0 - mn0), c8 = __expf(m8 - mn8);
        float ls0 = 0.f, ls8 = 0.f;
#pragma unroll
        for (int nt = 0; nt < 4; nt++) {
            s[nt][0] = __expf(s[nt][0] - mn0); ls0 += s[nt][0];
            s[nt][1] = __expf(s[nt][1] - mn0); ls0 += s[nt][1];
            s[nt][2] = __expf(s[nt][2] - mn8); ls8 += s[nt][2];
            s[nt][3] = __expf(s[nt][3] - mn8); ls8 += s[nt][3];
        }
        ls0 += __shfl_xor_sync(0xffffffffu, ls0, 1);
        ls0 += __shfl_xor_sync(0xffffffffu, ls0, 2);
        ls8 += __shfl_xor_sync(0xffffffffu, ls8, 1);
        ls8 += __shfl_xor_sync(0xffffffffu, ls8, 2);
        l0 = l0 * c0 + ls0; l8 = l8 * c8 + ls8;
        m0 = mn0; m8 = mn8;
#pragma unroll
        for (int nd = 0; nd < 8; nd++) {
            o[nd][0] *= c0; o[nd][1] *= c0;
            o[nd][2] *= c8; o[nd][3] *= c8;
        }

        // PV 3-pass
#pragma unroll
        for (int tt = 0; tt < 2; tt++) {
            uint32_t aH[4], aL[4];
            pack2(s[2 * tt][0], s[2 * tt][1], aH[0], aL[0]);
            pack2(s[2 * tt][2], s[2 * tt][3], aH[1], aL[1]);
            pack2(s[2 * tt + 1][0], s[2 * tt + 1][1], aH[2], aL[2]);
            pack2(s[2 * tt + 1][2], s[2 * tt + 1][3], aH[3], aL[3]);
            int j0 = kcol0 + tt * 16;
#pragma unroll
            for (int nd = 0; nd < 4; nd++) {
                int d0 = nd * 16;
                uint32_t bh[4], bl[4];
                {
                    int g = lane >> 3, rr = lane & 7;
                    uint32_t boff = (uint32_t)(((j0 + (g & 1) * 8 + rr) * 72 + d0 + (g >> 1) * 8) * 2);
                    ldmat_x4_t(bh, sbase + (uint32_t)(RVH * 4) + boff);
                    ldmat_x4_t(bl, sbase + (uint32_t)(RVL * 4) + boff);
                }
                mma_bf16(o[2 * nd], aH, bh);     mma_bf16(o[2 * nd + 1], aH, bh + 2);
                mma_bf16(o[2 * nd], aH, bl);     mma_bf16(o[2 * nd + 1], aH, bl + 2);
                mma_bf16(o[2 * nd], aL, bh);     mma_bf16(o[2 * nd + 1], aL, bh + 2);
            }
        }
        __syncthreads();
    }

    // merge the two k-slices
    float* smf = (float*)su;
    int r = mrow0 + (lane >> 2);
    if (kh2 == 1) {
        if ((lane & 3) == 0) {
            smf[RKH + r] = m0;       smf[RKH + 64 + r] = l0;
            smf[RKH + r + 8] = m8;   smf[RKH + 64 + r + 8] = l8;
        }
#pragma unroll
        for (int nd = 0; nd < 8; nd++) {
            int col = nd * 8 + (lane & 3) * 2;
            *(float2*)(smf + RVH + r * 66 + col) = make_float2(o[nd][0], o[nd][1]);
            *(float2*)(smf + RVH + (r + 8) * 66 + col) = make_float2(o[nd][2], o[nd][3]);
        }
    }
    __syncthreads();
    if (kh2 == 0) {
        float m1r = smf[RKH + r],     l1r = smf[RKH + 64 + r];
        float m1r8 = smf[RKH + r + 8], l1r8 = smf[RKH + 64 + r + 8];
        float M0 = fmaxf(m0, m1r), w00 = __expf(m0 - M0), w01 = __expf(m1r - M0);
        float L0 = l0 * w00 + l1r * w01;
        float M8 = fmaxf(m8, m1r8), w80 = __expf(m8 - M8), w81 = __expf(m1r8 - M8);
        float L8 = l8 * w80 + l1r8 * w81;
        if (!EDGE) {
            float i0 = 1.f / L0, i8 = 1.f / L8;
            size_t orow0 = (size_t)(b * NTOK + m * BS + r) * KH_DD + (h * DHEAD) / 2;
            size_t orow8 = (size_t)(b * NTOK + m * BS + r + 8) * KH_DD + (h * DHEAD) / 2;
#pragma unroll
            for (int nd = 0; nd < 8; nd++) {
                int col = nd * 8 + (lane & 3) * 2;
                float2 Oa = *(float2*)(smf + RVH + r * 66 + col);
                float2 Ob = *(float2*)(smf + RVH + (r + 8) * 66 + col);
                float f0 = (o[nd][0] * w00 + Oa.x * w01) * i0;
                float f1 = (o[nd][1] * w00 + Oa.y * w01) * i0;
                float f2 = (o[nd][2] * w80 + Ob.x * w81) * i8;
                float f3 = (o[nd][3] * w80 + Ob.y * w81) * i8;
                pack2(f0, f1, pch[orow0 + col / 2], pcl[orow0 + col / 2]);
                pack2(f2, f3, pch[orow8 + col / 2], pcl[orow8 + col / 2]);
            }
        } else {
            size_t pbase = ((((size_t)e * NH + h) * BB + b) * 8 + s0);
#pragma unroll
            for (int nd = 0; nd < 8; nd++) {
                int col = nd * 8 + (lane & 3) * 2;
                float2 Oa = *(float2*)(smf + RVH + r * 66 + col);
                float2 Ob = *(float2*)(smf + RVH + (r + 8) * 66 + col);
                float f0 = o[nd][0] * w00 + Oa.x * w01;
                float f1 = o[nd][1] * w00 + Oa.y * w01;
                float f2 = o[nd][2] * w80 + Ob.x * w81;
                float f3 = o[nd][3] * w80 + Ob.y * w81;
                *(float2*)(eo + pbase * 4096 + r * 64 + col) = make_float2(f0, f1);
                *(float2*)(eo + pbase * 4096 + (r + 8) * 64 + col) = make_float2(f2, f3);
            }
            if ((lane & 3) == 0) {
                em[pbase * 64 + r] = M0;     el[pbase * 64 + r] = L0;
                em[pbase * 64 + r + 8] = M8; el[pbase * 64 + r + 8] = L8;
            }
        }
    }
}

__global__ __launch_bounds__(256) void attn_edge_combine_kernel(
    const float* __restrict__ eo, const float* __restrict__ em,
    const float* __restrict__ el,
    uint32_t* __restrict__ pch, uint32_t* __restrict__ pcl)
{
    int e = blockIdx.x, h = blockIdx.y, b = blockIdx.z;
    int m = e ? (NBLK - 1) : 0;
    int t = threadIdx.x;
    int row = t >> 2, c0 = (t & 3) << 4;
    size_t base0 = ((((size_t)e * NH + h) * BB + b) * 8);

    float M = -3e38f;
#pragma unroll
    for (int s = 0; s < 8; s++) M = fmaxf(M, em[(base0 + s) * 64 + row]);
    float L = 0.f;
    float w[8];
#pragma unroll
    for (int s = 0; s < 8; s++) {
        w[s] = __expf(em[(base0 + s) * 64 + row] - M);
        L += w[s] * el[(base0 + s) * 64 + row];
    }
    float acc[16];
#pragma unroll
    for (int j = 0; j < 16; j++) acc[j] = 0.f;
#pragma unroll
    for (int s = 0; s < 8; s++) {
        const float* op = eo + (base0 + s) * 4096 + row * 64 + c0;
#pragma unroll
        for (int j = 0; j < 16; j++) acc[j] += w[s] * op[j];
    }
    float inv = 1.f / L;
    size_t orow = (size_t)(b * NTOK + m * BS + row) * KH_DD + ((h * DHEAD + c0) >> 1);
#pragma unroll
    for (int j = 0; j < 8; j++)
        pack2(acc[2 * j] * inv, acc[2 * j + 1] * inv, pch[orow + j], pcl[orow + j]);
}

// ---------------- final pooled head ----------------
__global__ __launch_bounds__(256) void final_part_kernel(
    const float* __restrict__ x, const float* __restrict__ fcw,
    float* __restrict__ part)
{
    int c = blockIdx.x, b = blockIdx.y;
    float acc = 0.f;
#pragma unroll
    for (int i = 0; i < 3; i++) {
        int d = threadIdx.x + i * 256;
        float s = 0.f;
        int n0 = c * 128;
        for (int n = n0; n < n0 + 128; n++)
            s += x[((size_t)b * NTOK + n) * DM + d];
        acc += s * fcw[d];
    }
    float dummy = 0.f;
    block_reduce2(acc, dummy);
    if (threadIdx.x == 0) part[b * 32 + c] = acc;
}

__global__ void final_sum_kernel(const float* __restrict__ part,
                                 const float* __restrict__ fcb,
                                 float* __restrict__ out)
{
    int t = threadIdx.x;
    int b = t >> 5, lane = t & 31;
    float v = part[b * 32 + lane];
#pragma unroll
    for (int off = 16; off > 0; off >>= 1)
        v += __shfl_down_sync(0xffffffffu, v, off);
    if (lane == 0) out[b] = v * (1.f / NTOK) + fcb[0];
}

// ---------------- driver ----------------
extern "C" void kernel_launch(void* const* d_in, const int* in_sizes, int n_in,
                              void* d_out, int out_size)
{
    const float* inputs = (const float*)d_in[0];
    const int*   rb_all = (const int*)d_in[1];
    const float* pos = (const float*)d_in[2];
    const float* tt  = (const float*)d_in[3];
    const float* eg  = (const float*)d_in[4];
    const float* eb  = (const float*)d_in[5];
    const float* Wq  = (const float*)d_in[6];  const float* bq = (const float*)d_in[7];
    const float* Wk  = (const float*)d_in[8];  const float* bk = (const float*)d_in[9];
    const float* Wv  = (const float*)d_in[10]; const float* bv = (const float*)d_in[11];
    const float* Wo  = (const float*)d_in[12]; const float* bo = (const float*)d_in[13];
    const float* l1g = (const float*)d_in[14]; const float* l1b = (const float*)d_in[15];
    const float* Wi  = (const float*)d_in[16]; const float* bi = (const float*)d_in[17];
    const float* Wd  = (const float*)d_in[18]; const float* bd = (const float*)d_in[19];
    const float* l2g = (const float*)d_in[20]; const float* l2b = (const float*)d_in[21];
    const float* fcw = (const float*)d_in[22]; const float* fcb = (const float*)d_in[23];
    float* out = (float*)d_out;

    float *x, *tb, *a, *part, *eo, *em, *el, *bqkv;
    uint32_t *pqh, *pql, *pxh, *pxl, *pch, *pcl, *phh, *phl, *wh, *wl;
    cudaGetSymbolAddress((void**)&x,    g_x);
    cudaGetSymbolAddress((void**)&tb,   g_t);
    cudaGetSymbolAddress((void**)&a,    g_a);
    cudaGetSymbolAddress((void**)&part, g_part);
    cudaGetSymbolAddress((void**)&eo,   g_eo);
    cudaGetSymbolAddress((void**)&em,   g_em);
    cudaGetSymbolAddress((void**)&el,   g_el);
    cudaGetSymbolAddress((void**)&bqkv, g_bqkv);
    cudaGetSymbolAddress((void**)&pqh,  g_pqh);
    cudaGetSymbolAddress((void**)&pql,  g_pql);
    cudaGetSymbolAddress((void**)&pxh,  g_pxh);
    cudaGetSymbolAddress((void**)&pxl,  g_pxl);
    cudaGetSymbolAddress((void**)&pch,  g_pch);
    cudaGetSymbolAddress((void**)&pcl,  g_pcl);
    cudaGetSymbolAddress((void**)&phh,  g_phh);
    cudaGetSymbolAddress((void**)&phl,  g_phl);
    cudaGetSymbolAddress((void**)&wh,   g_wh);
    cudaGetSymbolAddress((void**)&wl,   g_wl);

    const int ATTN_SMEM = 12800 * 4;             // 51200 bytes
    const int GEMM_SMEM = 2 * 32768;             // 65536 bytes
    cudaFuncSetAttribute((const void*)attn_mma_kernel<0>, cudaFuncAttributeMaxDynamicSharedMemorySize, ATTN_SMEM);
    cudaFuncSetAttribute((const void*)attn_mma_kernel<1>, cudaFuncAttributeMaxDynamicSharedMemorySize, ATTN_SMEM);
    cudaFuncSetAttribute((const void*)mgemm_kernel<0, 0>, cudaFuncAttributeMaxDynamicSharedMemorySize, GEMM_SMEM);
    cudaFuncSetAttribute((const void*)mgemm_kernel<0, 1>, cudaFuncAttributeMaxDynamicSharedMemorySize, GEMM_SMEM);
    cudaFuncSetAttribute((const void*)mgemm_kernel<1, 1>, cudaFuncAttributeMaxDynamicSharedMemorySize, GEMM_SMEM);

    const int MROWS = BB * NTOK;                 // 8192
    dim3 gemm_qkv(GS / 128, MROWS / 128);        // (18, 64)
    dim3 gemm_dd(DM / 128, MROWS / 128);         // (6, 64)
    dim3 gemm_ff(FFD / 128, MROWS / 128);        // (24, 64)

    // upfront: embed LN + all weight packs + biases
    embed_ln_kernel<<<MROWS, 256>>>(inputs, pos, tt, eg, eb, x, pxh, pxl);
    pack_wA_kernel<<<dim3(DM / 32, DM / 64, 8), 256>>>(Wq, Wk, Wv, Wo, wh, wl);
    pack_wB_kernel<<<dim3(FFD / 32, DM / 64, 2), 256>>>(Wi, wh, wl);
    pack_wC_kernel<<<dim3(DM / 32, FFD / 64, 2), 256>>>(Wd, wh, wl);
    concat_bias_kernel<<<18, 256>>>(bq, bk, bv, bqkv);

    for (int l = 0; l < NL; l++) {
        const uint32_t* whl = wh + (size_t)l * LOFF;
        const uint32_t* wll = wl + (size_t)l * LOFF;

        // fused QKV GEMM -> packed output
        mgemm_kernel<0, 1><<<gemm_qkv, 256, GEMM_SMEM>>>(
            pxh, pxl, whl, wll, bqkv + l * GS, nullptr, pqh, pql, KH_DD, GS);

        attn_mma_kernel<0><<<dim3(NBLK - 2, NH, BB), 256, ATTN_SMEM>>>(
            pqh, pql, rb_all + l * NH * NBLK * RR, pch, pcl, nullptr, nullptr, nullptr);
        attn_mma_kernel<1><<<dim3(8, NH, BB * 2), 256, ATTN_SMEM>>>(
            pqh, pql, nullptr, nullptr, nullptr, eo, em, el);
        attn_edge_combine_kernel<<<dim3(2, NH, BB), 256>>>(eo, em, el, pch, pcl);

        mgemm_kernel<0, 0><<<gemm_dd, 256, GEMM_SMEM>>>(
            pch, pcl, whl + WO_OFF, wll + WO_OFF, bo + l * DM,
            tb, nullptr, nullptr, KH_DD, DM);
        ln_add_kernel<<<MROWS, 256>>>(x, tb, l1g + l * DM, l1b + l * DM, a, pxh, pxl);

        mgemm_kernel<1, 1><<<gemm_ff, 256, GEMM_SMEM>>>(
            pxh, pxl, whl + WI_OFF, wll + WI_OFF, bi + l * FFD,
            nullptr, phh, phl, KH_DD, FFD);

        mgemm_kernel<0, 0><<<gemm_dd, 256, GEMM_SMEM>>>(
            phh, phl, whl + WD_OFF, wll + WD_OFF, bd + l * DM,
            tb, nullptr, nullptr, KH_FF, DM);
        ln_add_kernel<<<MROWS, 256>>>(a, tb, l2g + l * DM, l2b + l * DM, x, pxh, pxl);
    }

    final_part_kernel<<<dim3(32, BB), 256>>>(x, fcw, part);
    final_sum_kernel<<<1, 64>>>(part, fcb, out);
}